// round 1
// baseline (speedup 1.0000x reference)
#include <cuda_runtime.h>
#include <cuda_bf16.h>

#define NN 50000
#define NE 640000
#define RK 128
#define NG 50
#define ORDER 3
#define LN_EPS 1e-5f

// ---------------- device scratch (no allocation allowed) ----------------
__device__ float g_h[NN * RK];     // XW * inv_sqrt_out
__device__ float g_bufA[NN * RK];  // layer activations ping
__device__ float g_bufB[NN * RK];  // layer activations pong
__device__ int   g_deg_out[NN];
__device__ int   g_deg_in[NN];
__device__ float g_inv_out[NN];
__device__ float g_inv_in[NN];
__device__ int   g_rowptr[NN + 1];
__device__ int   g_cursor[NN];
__device__ int   g_col[NE];

// ---------------- setup kernels ----------------
__global__ void zero_deg_kernel() {
    int i = blockIdx.x * blockDim.x + threadIdx.x;
    if (i < NN) { g_deg_out[i] = 0; g_deg_in[i] = 0; }
}

__global__ void deg_kernel(const int* __restrict__ src, const int* __restrict__ dst) {
    int e = blockIdx.x * blockDim.x + threadIdx.x;
    if (e < NE) {
        atomicAdd(&g_deg_out[src[e]], 1);
        atomicAdd(&g_deg_in[dst[e]], 1);
    }
}

__global__ void inv_kernel() {
    int i = blockIdx.x * blockDim.x + threadIdx.x;
    if (i < NN) {
        g_inv_out[i] = rsqrtf(fmaxf((float)g_deg_out[i], 1.0f));
        g_inv_in[i]  = rsqrtf(fmaxf((float)g_deg_in[i],  1.0f));
    }
}

// single-block exclusive scan of deg_in -> rowptr (+ cursor copy)
__global__ void scan_kernel() {
    __shared__ int part[1024];
    const int tid = threadIdx.x;
    const int CH = (NN + 1023) / 1024;  // 49
    int base = tid * CH;
    int s = 0;
    for (int i = 0; i < CH; i++) {
        int idx = base + i;
        if (idx < NN) s += g_deg_in[idx];
    }
    part[tid] = s;
    __syncthreads();
    for (int off = 1; off < 1024; off <<= 1) {
        int v = (tid >= off) ? part[tid - off] : 0;
        __syncthreads();
        part[tid] += v;
        __syncthreads();
    }
    int run = (tid == 0) ? 0 : part[tid - 1];
    for (int i = 0; i < CH; i++) {
        int idx = base + i;
        if (idx < NN) {
            g_rowptr[idx] = run;
            g_cursor[idx] = run;
            run += g_deg_in[idx];
        }
    }
    if (tid == 1023) g_rowptr[NN] = part[1023];
}

__global__ void scatter_kernel(const int* __restrict__ src, const int* __restrict__ dst) {
    int e = blockIdx.x * blockDim.x + threadIdx.x;
    if (e < NE) {
        int d = dst[e];
        int p = atomicAdd(&g_cursor[d], 1);
        g_col[p] = src[e];
    }
}

// ---------------- GEMM: H[n][c] = inv_out[n] * sum_k X[n][k]*W[k][c] ----------------
// Block: 256 threads, 64 rows. Two column-tiles of 64. 4x4 register blocking.
#define GB_ROWS 64
#define XS_PITCH 129
#define GEMM_SMEM (GB_ROWS * XS_PITCH * 4 + RK * 64 * 4)

__global__ void __launch_bounds__(256) gemm_kernel(
    const float* __restrict__ X, const float* __restrict__ W,
    float* __restrict__ H)
{
    extern __shared__ float sm[];
    float* xs = sm;                        // [64][129]
    float* ws = sm + GB_ROWS * XS_PITCH;   // [128][64] per tile
    float4* ws4 = (float4*)ws;

    const int tid = threadIdx.x;
    const int row0 = blockIdx.x * GB_ROWS;
    const float4* X4 = (const float4*)X;

    // load 64 rows of X into padded smem (zero-fill OOB)
    for (int i = tid; i < GB_ROWS * 32; i += 256) {
        int r = i >> 5, c4 = i & 31;
        float4 v = make_float4(0.f, 0.f, 0.f, 0.f);
        if (row0 + r < NN) v = X4[(row0 + r) * 32 + c4];
        float* p = &xs[r * XS_PITCH + c4 * 4];
        p[0] = v.x; p[1] = v.y; p[2] = v.z; p[3] = v.w;
    }

    const int c4 = tid & 15;        // which float4 of 64-col tile
    const int rq = tid >> 4;        // row quad 0..15
    const int r0 = rq * 4;
    const float4* W4 = (const float4*)W;

    for (int t = 0; t < 2; t++) {
        __syncthreads();
        // load W column tile [128][64]
        for (int i = tid; i < RK * 16; i += 256) {
            int k = i >> 4, cc = i & 15;
            ws4[i] = W4[k * 32 + t * 16 + cc];
        }
        __syncthreads();

        float4 a0 = make_float4(0.f,0.f,0.f,0.f);
        float4 a1 = a0, a2 = a0, a3 = a0;
        #pragma unroll 4
        for (int k = 0; k < RK; k++) {
            float4 w = ws4[k * 16 + c4];
            float x0 = xs[(r0 + 0) * XS_PITCH + k];
            float x1 = xs[(r0 + 1) * XS_PITCH + k];
            float x2 = xs[(r0 + 2) * XS_PITCH + k];
            float x3 = xs[(r0 + 3) * XS_PITCH + k];
            a0.x += x0 * w.x; a0.y += x0 * w.y; a0.z += x0 * w.z; a0.w += x0 * w.w;
            a1.x += x1 * w.x; a1.y += x1 * w.y; a1.z += x1 * w.z; a1.w += x1 * w.w;
            a2.x += x2 * w.x; a2.y += x2 * w.y; a2.z += x2 * w.z; a2.w += x2 * w.w;
            a3.x += x3 * w.x; a3.y += x3 * w.y; a3.z += x3 * w.z; a3.w += x3 * w.w;
        }

        float4* H4 = (float4*)H;
        float4 accs[4] = {a0, a1, a2, a3};
        #pragma unroll
        for (int j = 0; j < 4; j++) {
            int gr = row0 + r0 + j;
            if (gr < NN) {
                float s = g_inv_out[gr];
                float4 o = accs[j];
                o.x *= s; o.y *= s; o.z *= s; o.w *= s;
                H4[gr * 32 + t * 16 + c4] = o;
            }
        }
    }
}

// ---------------- SpMM + inv_in + bias + LayerNorm + ReLU ----------------
// one warp per dst node; lane covers 4 consecutive channels
__global__ void __launch_bounds__(256) spmm_ln_kernel(
    const float* __restrict__ H,
    const float* __restrict__ b, const float* __restrict__ gamma,
    const float* __restrict__ beta, float* __restrict__ out)
{
    int warp = (blockIdx.x * blockDim.x + threadIdx.x) >> 5;
    int lane = threadIdx.x & 31;
    if (warp >= NN) return;

    int beg = g_rowptr[warp];
    int end = g_rowptr[warp + 1];
    const float4* H4 = (const float4*)H;

    float4 acc = make_float4(0.f, 0.f, 0.f, 0.f);
    int e = beg;
    // unroll-by-4 for memory-level parallelism (L2-resident gathers)
    for (; e + 3 < end; e += 4) {
        int s0 = g_col[e], s1 = g_col[e+1], s2 = g_col[e+2], s3 = g_col[e+3];
        float4 v0 = H4[s0 * 32 + lane];
        float4 v1 = H4[s1 * 32 + lane];
        float4 v2 = H4[s2 * 32 + lane];
        float4 v3 = H4[s3 * 32 + lane];
        acc.x += v0.x + v1.x + v2.x + v3.x;
        acc.y += v0.y + v1.y + v2.y + v3.y;
        acc.z += v0.z + v1.z + v2.z + v3.z;
        acc.w += v0.w + v1.w + v2.w + v3.w;
    }
    for (; e < end; e++) {
        int s0 = g_col[e];
        float4 v0 = H4[s0 * 32 + lane];
        acc.x += v0.x; acc.y += v0.y; acc.z += v0.z; acc.w += v0.w;
    }

    float sc = g_inv_in[warp];
    float4 bb = ((const float4*)b)[lane];
    float x0 = acc.x * sc + bb.x;
    float x1 = acc.y * sc + bb.y;
    float x2 = acc.z * sc + bb.z;
    float x3 = acc.w * sc + bb.w;

    // mean
    float s = x0 + x1 + x2 + x3;
    #pragma unroll
    for (int o = 16; o > 0; o >>= 1) s += __shfl_xor_sync(0xFFFFFFFFu, s, o);
    float mu = s * (1.0f / RK);

    float d0 = x0 - mu, d1 = x1 - mu, d2 = x2 - mu, d3 = x3 - mu;
    float v = d0*d0 + d1*d1 + d2*d2 + d3*d3;
    #pragma unroll
    for (int o = 16; o > 0; o >>= 1) v += __shfl_xor_sync(0xFFFFFFFFu, v, o);
    float rstd = rsqrtf(v * (1.0f / RK) + LN_EPS);

    float4 gg = ((const float4*)gamma)[lane];
    float4 be = ((const float4*)beta)[lane];
    float y0 = fmaxf(d0 * rstd * gg.x + be.x, 0.f);
    float y1 = fmaxf(d1 * rstd * gg.y + be.y, 0.f);
    float y2 = fmaxf(d2 * rstd * gg.z + be.z, 0.f);
    float y3 = fmaxf(d3 * rstd * gg.w + be.w, 0.f);

    ((float4*)out)[warp * 32 + lane] = make_float4(y0, y1, y2, y3);
}

// ---------------- final gather of first node of each graph ----------------
__global__ void gather_out_kernel(const float* __restrict__ feats,
                                  const int* __restrict__ bnn,
                                  float* __restrict__ out)
{
    __shared__ int sidx;
    int g = blockIdx.x;
    if (threadIdx.x == 0) {
        int p = 0;
        for (int i = 0; i < g; i++) p += bnn[i];
        sidx = p;
    }
    __syncthreads();
    out[g * RK + threadIdx.x] = feats[sidx * RK + threadIdx.x];
}

// ---------------- launch ----------------
extern "C" void kernel_launch(void* const* d_in, const int* in_sizes, int n_in,
                              void* d_out, int out_size)
{
    const float* features = (const float*)d_in[0];
    const int*   src      = (const int*)d_in[1];
    const int*   dst      = (const int*)d_in[2];
    const int*   bnn      = (const int*)d_in[3];
    const float* Ws       = (const float*)d_in[4];   // [3][128][128]
    const float* bs       = (const float*)d_in[5];   // [3][128]
    const float* gammas   = (const float*)d_in[6];
    const float* betas    = (const float*)d_in[7];
    float* out = (float*)d_out;

    cudaFuncSetAttribute(gemm_kernel, cudaFuncAttributeMaxDynamicSharedMemorySize, GEMM_SMEM);

    float *hbuf, *bufA, *bufB;
    cudaGetSymbolAddress((void**)&hbuf, g_h);
    cudaGetSymbolAddress((void**)&bufA, g_bufA);
    cudaGetSymbolAddress((void**)&bufB, g_bufB);

    // graph structure setup (per launch; deterministic up to fp sum order)
    zero_deg_kernel<<<(NN + 255) / 256, 256>>>();
    deg_kernel<<<(NE + 255) / 256, 256>>>(src, dst);
    inv_kernel<<<(NN + 255) / 256, 256>>>();
    scan_kernel<<<1, 1024>>>();
    scatter_kernel<<<(NE + 255) / 256, 256>>>(src, dst);

    const int gemm_grid = (NN + GB_ROWS - 1) / GB_ROWS;
    const int spmm_grid = (NN * 32 + 255) / 256;  // one warp per node

    const float* in_ptr = features;
    float* outs[ORDER] = {bufA, bufB, bufA};
    for (int i = 0; i < ORDER; i++) {
        gemm_kernel<<<gemm_grid, 256, GEMM_SMEM>>>(in_ptr, Ws + i * RK * RK, hbuf);
        spmm_ln_kernel<<<spmm_grid, 256>>>(hbuf, bs + i * RK, gammas + i * RK,
                                           betas + i * RK, outs[i]);
        in_ptr = outs[i];
    }

    gather_out_kernel<<<NG, RK>>>(outs[ORDER - 1], bnn, out);
}

// round 2
// speedup vs baseline: 1.2561x; 1.2561x over previous
#include <cuda_runtime.h>
#include <cuda_bf16.h>

#define NN 50000
#define NE 640000
#define RK 128
#define NG 50
#define ORDER 3
#define LN_EPS 1e-5f

#define SCAN_CH 1024
#define SCAN_NB ((NN + SCAN_CH - 1) / SCAN_CH)   // 49

// ---------------- device scratch (no allocation allowed) ----------------
__device__ float g_h[NN * RK];     // XW * inv_sqrt_out
__device__ float g_bufA[NN * RK];  // layer activations ping
__device__ float g_bufB[NN * RK];  // layer activations pong
__device__ int   g_deg_out[NN];
__device__ int   g_deg_in[NN + SCAN_CH];   // padded so int4 loads never OOB
__device__ float g_inv_out[NN];
__device__ float g_inv_in[NN];
__device__ int   g_rowptr[NN + 1];
__device__ int   g_cursor[NN];
__device__ int   g_col[NE];
__device__ int   g_part[SCAN_NB];

// ---------------- setup kernels ----------------
__global__ void deg_kernel(const int* __restrict__ src, const int* __restrict__ dst) {
    int e = blockIdx.x * blockDim.x + threadIdx.x;
    if (e < NE) {
        atomicAdd(&g_deg_out[src[e]], 1);
        atomicAdd(&g_deg_in[dst[e]], 1);
    }
}

// phase 1: per-1024-chunk sums of deg_in
__global__ void __launch_bounds__(256) block_reduce_kernel() {
    const int b = blockIdx.x;
    const int tid = threadIdx.x;
    const int4* di4 = (const int4*)g_deg_in;   // padded, safe
    int4 v = di4[b * 256 + tid];
    int s = v.x + v.y + v.z + v.w;
    #pragma unroll
    for (int o = 16; o > 0; o >>= 1) s += __shfl_xor_sync(0xFFFFFFFFu, s, o);
    __shared__ int ws[8];
    if ((tid & 31) == 0) ws[tid >> 5] = s;
    __syncthreads();
    if (tid < 8) {
        int t = ws[tid];
        #pragma unroll
        for (int o = 4; o > 0; o >>= 1) t += __shfl_xor_sync(0xFFu, t, o);
        if (tid == 0) g_part[b] = t;
    }
}

// phase 2: exclusive scan of 49 partials (one warp + serial tail — tiny)
__global__ void scan_parts_kernel() {
    if (threadIdx.x == 0) {
        int run = 0;
        #pragma unroll
        for (int i = 0; i < SCAN_NB; i++) {
            int v = g_part[i];
            g_part[i] = run;
            run += v;
        }
        g_rowptr[NN] = run;
    }
}

// phase 3: per-chunk exclusive scan; write rowptr/cursor; fuse inv computation
__global__ void __launch_bounds__(256) block_scan_kernel() {
    const int b = blockIdx.x;
    const int tid = threadIdx.x;
    const int base = b * SCAN_CH + tid * 4;

    const int4* di4 = (const int4*)g_deg_in;
    int4 v = di4[b * 256 + tid];
    int tsum = v.x + v.y + v.z + v.w;

    // block exclusive scan of per-thread sums (Hillis-Steele over 256)
    __shared__ int sc[256];
    sc[tid] = tsum;
    __syncthreads();
    #pragma unroll
    for (int o = 1; o < 256; o <<= 1) {
        int t = (tid >= o) ? sc[tid - o] : 0;
        __syncthreads();
        sc[tid] += t;
        __syncthreads();
    }
    int run = g_part[b] + ((tid == 0) ? 0 : sc[tid - 1]);

    int r0 = run;
    int r1 = r0 + v.x;
    int r2 = r1 + v.y;
    int r3 = r2 + v.z;

    if (base + 0 < NN) { g_rowptr[base+0] = r0; g_cursor[base+0] = r0; }
    if (base + 1 < NN) { g_rowptr[base+1] = r1; g_cursor[base+1] = r1; }
    if (base + 2 < NN) { g_rowptr[base+2] = r2; g_cursor[base+2] = r2; }
    if (base + 3 < NN) { g_rowptr[base+3] = r3; g_cursor[base+3] = r3; }

    // fused inv computation
    #pragma unroll
    for (int j = 0; j < 4; j++) {
        int idx = base + j;
        if (idx < NN) {
            int din = (j == 0) ? v.x : (j == 1) ? v.y : (j == 2) ? v.z : v.w;
            g_inv_in[idx]  = rsqrtf(fmaxf((float)din, 1.0f));
            g_inv_out[idx] = rsqrtf(fmaxf((float)g_deg_out[idx], 1.0f));
        }
    }
}

__global__ void scatter_kernel(const int* __restrict__ src, const int* __restrict__ dst) {
    int e = blockIdx.x * blockDim.x + threadIdx.x;
    if (e < NE) {
        int d = dst[e];
        int p = atomicAdd(&g_cursor[d], 1);
        g_col[p] = src[e];
    }
}

// ---------------- GEMM: H[n][c] = inv_out[n] * sum_k X[n][k]*W[k][c] ----------------
#define GB_ROWS 64
#define XS_PITCH 129
#define GEMM_SMEM (GB_ROWS * XS_PITCH * 4 + RK * 64 * 4)

__global__ void __launch_bounds__(256) gemm_kernel(
    const float* __restrict__ X, const float* __restrict__ W,
    float* __restrict__ H)
{
    extern __shared__ float sm[];
    float* xs = sm;                        // [64][129]
    float* ws = sm + GB_ROWS * XS_PITCH;   // [128][64] per tile
    float4* ws4 = (float4*)ws;

    const int tid = threadIdx.x;
    const int row0 = blockIdx.x * GB_ROWS;
    const float4* X4 = (const float4*)X;

    for (int i = tid; i < GB_ROWS * 32; i += 256) {
        int r = i >> 5, c4 = i & 31;
        float4 v = make_float4(0.f, 0.f, 0.f, 0.f);
        if (row0 + r < NN) v = X4[(row0 + r) * 32 + c4];
        float* p = &xs[r * XS_PITCH + c4 * 4];
        p[0] = v.x; p[1] = v.y; p[2] = v.z; p[3] = v.w;
    }

    const int c4 = tid & 15;
    const int rq = tid >> 4;
    const int r0 = rq * 4;
    const float4* W4 = (const float4*)W;

    for (int t = 0; t < 2; t++) {
        __syncthreads();
        for (int i = tid; i < RK * 16; i += 256) {
            int k = i >> 4, cc = i & 15;
            ws4[i] = W4[k * 32 + t * 16 + cc];
        }
        __syncthreads();

        float4 a0 = make_float4(0.f,0.f,0.f,0.f);
        float4 a1 = a0, a2 = a0, a3 = a0;
        #pragma unroll 4
        for (int k = 0; k < RK; k++) {
            float4 w = ws4[k * 16 + c4];
            float x0 = xs[(r0 + 0) * XS_PITCH + k];
            float x1 = xs[(r0 + 1) * XS_PITCH + k];
            float x2 = xs[(r0 + 2) * XS_PITCH + k];
            float x3 = xs[(r0 + 3) * XS_PITCH + k];
            a0.x += x0 * w.x; a0.y += x0 * w.y; a0.z += x0 * w.z; a0.w += x0 * w.w;
            a1.x += x1 * w.x; a1.y += x1 * w.y; a1.z += x1 * w.z; a1.w += x1 * w.w;
            a2.x += x2 * w.x; a2.y += x2 * w.y; a2.z += x2 * w.z; a2.w += x2 * w.w;
            a3.x += x3 * w.x; a3.y += x3 * w.y; a3.z += x3 * w.z; a3.w += x3 * w.w;
        }

        float4* H4 = (float4*)H;
        float4 accs[4] = {a0, a1, a2, a3};
        #pragma unroll
        for (int j = 0; j < 4; j++) {
            int gr = row0 + r0 + j;
            if (gr < NN) {
                float s = g_inv_out[gr];
                float4 o = accs[j];
                o.x *= s; o.y *= s; o.z *= s; o.w *= s;
                H4[gr * 32 + t * 16 + c4] = o;
            }
        }
    }
}

// ---------------- SpMM + inv_in + bias + LayerNorm + ReLU ----------------
__global__ void __launch_bounds__(256) spmm_ln_kernel(
    const float* __restrict__ H,
    const float* __restrict__ b, const float* __restrict__ gamma,
    const float* __restrict__ beta, float* __restrict__ out)
{
    int warp = (blockIdx.x * blockDim.x + threadIdx.x) >> 5;
    int lane = threadIdx.x & 31;
    if (warp >= NN) return;

    int beg = g_rowptr[warp];
    int end = g_rowptr[warp + 1];
    const float4* H4 = (const float4*)H;

    float4 acc = make_float4(0.f, 0.f, 0.f, 0.f);
    int e = beg;
    for (; e + 3 < end; e += 4) {
        int s0 = g_col[e], s1 = g_col[e+1], s2 = g_col[e+2], s3 = g_col[e+3];
        float4 v0 = H4[s0 * 32 + lane];
        float4 v1 = H4[s1 * 32 + lane];
        float4 v2 = H4[s2 * 32 + lane];
        float4 v3 = H4[s3 * 32 + lane];
        acc.x += v0.x + v1.x + v2.x + v3.x;
        acc.y += v0.y + v1.y + v2.y + v3.y;
        acc.z += v0.z + v1.z + v2.z + v3.z;
        acc.w += v0.w + v1.w + v2.w + v3.w;
    }
    for (; e < end; e++) {
        int s0 = g_col[e];
        float4 v0 = H4[s0 * 32 + lane];
        acc.x += v0.x; acc.y += v0.y; acc.z += v0.z; acc.w += v0.w;
    }

    float sc = g_inv_in[warp];
    float4 bb = ((const float4*)b)[lane];
    float x0 = acc.x * sc + bb.x;
    float x1 = acc.y * sc + bb.y;
    float x2 = acc.z * sc + bb.z;
    float x3 = acc.w * sc + bb.w;

    float s = x0 + x1 + x2 + x3;
    #pragma unroll
    for (int o = 16; o > 0; o >>= 1) s += __shfl_xor_sync(0xFFFFFFFFu, s, o);
    float mu = s * (1.0f / RK);

    float d0 = x0 - mu, d1 = x1 - mu, d2 = x2 - mu, d3 = x3 - mu;
    float v = d0*d0 + d1*d1 + d2*d2 + d3*d3;
    #pragma unroll
    for (int o = 16; o > 0; o >>= 1) v += __shfl_xor_sync(0xFFFFFFFFu, v, o);
    float rstd = rsqrtf(v * (1.0f / RK) + LN_EPS);

    float4 gg = ((const float4*)gamma)[lane];
    float4 be = ((const float4*)beta)[lane];
    float y0 = fmaxf(d0 * rstd * gg.x + be.x, 0.f);
    float y1 = fmaxf(d1 * rstd * gg.y + be.y, 0.f);
    float y2 = fmaxf(d2 * rstd * gg.z + be.z, 0.f);
    float y3 = fmaxf(d3 * rstd * gg.w + be.w, 0.f);

    ((float4*)out)[warp * 32 + lane] = make_float4(y0, y1, y2, y3);
}

// ---------------- final gather of first node of each graph ----------------
__global__ void gather_out_kernel(const float* __restrict__ feats,
                                  const int* __restrict__ bnn,
                                  float* __restrict__ out)
{
    __shared__ int sidx;
    int g = blockIdx.x;
    if (threadIdx.x == 0) {
        int p = 0;
        for (int i = 0; i < g; i++) p += bnn[i];
        sidx = p;
    }
    __syncthreads();
    out[g * RK + threadIdx.x] = feats[sidx * RK + threadIdx.x];
}

// ---------------- launch ----------------
extern "C" void kernel_launch(void* const* d_in, const int* in_sizes, int n_in,
                              void* d_out, int out_size)
{
    const float* features = (const float*)d_in[0];
    const int*   src      = (const int*)d_in[1];
    const int*   dst      = (const int*)d_in[2];
    const int*   bnn      = (const int*)d_in[3];
    const float* Ws       = (const float*)d_in[4];
    const float* bs       = (const float*)d_in[5];
    const float* gammas   = (const float*)d_in[6];
    const float* betas    = (const float*)d_in[7];
    float* out = (float*)d_out;

    cudaFuncSetAttribute(gemm_kernel, cudaFuncAttributeMaxDynamicSharedMemorySize, GEMM_SMEM);

    float *hbuf, *bufA, *bufB;
    cudaGetSymbolAddress((void**)&hbuf, g_h);
    cudaGetSymbolAddress((void**)&bufA, g_bufA);
    cudaGetSymbolAddress((void**)&bufB, g_bufB);
    int *dout_p, *din_p;
    cudaGetSymbolAddress((void**)&dout_p, g_deg_out);
    cudaGetSymbolAddress((void**)&din_p, g_deg_in);

    // zero degree arrays (incl. deg_in padding)
    cudaMemsetAsync(dout_p, 0, NN * sizeof(int));
    cudaMemsetAsync(din_p, 0, (NN + SCAN_CH) * sizeof(int));

    // graph structure setup
    deg_kernel<<<(NE + 255) / 256, 256>>>(src, dst);
    block_reduce_kernel<<<SCAN_NB, 256>>>();
    scan_parts_kernel<<<1, 32>>>();
    block_scan_kernel<<<SCAN_NB, 256>>>();
    scatter_kernel<<<(NE + 255) / 256, 256>>>(src, dst);

    const int gemm_grid = (NN + GB_ROWS - 1) / GB_ROWS;
    const int spmm_grid = (NN * 32 + 255) / 256;

    const float* in_ptr = features;
    float* outs[ORDER] = {bufA, bufB, bufA};
    for (int i = 0; i < ORDER; i++) {
        gemm_kernel<<<gemm_grid, 256, GEMM_SMEM>>>(in_ptr, Ws + i * RK * RK, hbuf);
        spmm_ln_kernel<<<spmm_grid, 256>>>(hbuf, bs + i * RK, gammas + i * RK,
                                           betas + i * RK, outs[i]);
        in_ptr = outs[i];
    }

    gather_out_kernel<<<NG, RK>>>(outs[ORDER - 1], bnn, out);
}

// round 5
// speedup vs baseline: 1.6133x; 1.2843x over previous
#include <cuda_runtime.h>
#include <cuda_bf16.h>
#include <cstdint>

#define NN 50000
#define NE 640000
#define RK 128
#define NG 50
#define ORDER 3
#define LN_EPS 1e-5f

#define SCAN_CH 1024
#define SCAN_NB ((NN + SCAN_CH - 1) / SCAN_CH)   // 49

// tcgen05 is an arch-accelerated feature: legal only in the compute_103a /
// sm_103a compilation pass. nvcc also emits portable compute_103 PTX, which
// must not see the tcgen05 asm. Guard on the feature macro.
#if defined(__CUDA_ARCH__) && (defined(__CUDA_ARCH_FEAT_SM103_ALL) || \
    (defined(__CUDA_ARCH_SPECIFIC__) && (__CUDA_ARCH_SPECIFIC__ == 1030)))
#define HAS_TCGEN05 1
#else
#define HAS_TCGEN05 0
#endif

// ---------------- device scratch (no allocation allowed) ----------------
__device__ float g_h[NN * RK];
__device__ float g_bufA[NN * RK];
__device__ float g_bufB[NN * RK];
__device__ int   g_deg_out[NN];
__device__ int   g_deg_in[NN + SCAN_CH];
__device__ float g_inv_out[NN];
__device__ float g_inv_in[NN];
__device__ int   g_rowptr[NN + 1];
__device__ int   g_cursor[NN];
__device__ int   g_col[NE];
__device__ int   g_part[SCAN_NB];
// pre-transposed / pre-split / pre-swizzled W (B[n][k] = W[k][n]) per layer
__device__ float g_Bhi[ORDER][RK * RK];
__device__ float g_Blo[ORDER][RK * RK];

// ---------------- portable helpers ----------------
__device__ __forceinline__ uint32_t smem_u32(const void* p) {
    uint32_t a;
    asm("{ .reg .u64 t; cvta.to.shared.u64 t, %1; cvt.u32.u64 %0, t; }" : "=r"(a) : "l"(p));
    return a;
}

__device__ __forceinline__ void split_tf32(float x, uint32_t& hi, uint32_t& lo) {
    uint32_t h;
    asm("cvt.rna.tf32.f32 %0, %1;" : "=r"(h) : "f"(x));
    float l = x - __uint_as_float(h);
    uint32_t lb;
    asm("cvt.rna.tf32.f32 %0, %1;" : "=r"(lb) : "f"(l));
    hi = h; lo = lb;
}

// blocked SW128 atom layout for a [128 rows x 128 float cols] tile:
// atom = 8 rows x 32 floats (128B); atom_offset = atom_row + atom_col*16
__device__ __forceinline__ uint32_t tile_off_sw(int row, int col) {
    uint32_t boff = (uint32_t)((row >> 3) + (col >> 5) * 16) * 1024u
                  + (uint32_t)(row & 7) * 128u + (uint32_t)(col & 31) * 4u;
    return boff ^ ((boff >> 3) & 0x70);
}

// ---------------- sm_103a-only PTX wrappers ----------------
#if HAS_TCGEN05

#define TC_ALLOC(saddr, n) \
    asm volatile("tcgen05.alloc.cta_group::1.sync.aligned.shared::cta.b32 [%0], %1;" \
                 :: "r"((uint32_t)(saddr)), "r"((uint32_t)(n)) : "memory")
#define TC_DEALLOC(t, n) \
    asm volatile("tcgen05.dealloc.cta_group::1.sync.aligned.b32 %0, %1;" :: "r"(t), "r"((uint32_t)(n)))
#define TC_RELINQ() \
    asm volatile("tcgen05.relinquish_alloc_permit.cta_group::1.sync.aligned;")
#define TC_COMMIT(mbar) \
    asm volatile("tcgen05.commit.cta_group::1.mbarrier::arrive::one.shared::cluster.b64 [%0];" \
                 :: "r"((uint32_t)(mbar)) : "memory")
#define TC_FENCE_AFTER()  asm volatile("tcgen05.fence::after_thread_sync;" ::: "memory")
#define TC_FENCE_BEFORE() asm volatile("tcgen05.fence::before_thread_sync;" ::: "memory")
#define TC_WAIT_LD()      asm volatile("tcgen05.wait::ld.sync.aligned;" ::: "memory")

#define MBAR_INIT(mbar, cnt) \
    asm volatile("mbarrier.init.shared.b64 [%0], %1;" :: "r"((uint32_t)(mbar)), "r"((uint32_t)(cnt)) : "memory")
#define MBAR_WAIT(mbar, ph) do { \
    uint32_t _m = (uint32_t)(mbar); uint32_t _p = (uint32_t)(ph); uint32_t _d; \
    asm volatile("{\n\t.reg .pred p;\n\t" \
        "mbarrier.try_wait.parity.acquire.cta.shared::cta.b64 p, [%1], %2;\n\t" \
        "selp.b32 %0, 1, 0, p;\n\t}" : "=r"(_d) : "r"(_m), "r"(_p) : "memory"); \
    if (!_d) { \
        asm volatile("{\n\t.reg .pred P1;\n\t" \
            "WL_%=:\n\t" \
            "mbarrier.try_wait.parity.acquire.cta.shared::cta.b64 P1, [%0], %1, 0x989680;\n\t" \
            "@P1 bra.uni WD_%=;\n\t" \
            "bra.uni WL_%=;\n\t" \
            "WD_%=:\n\t}" :: "r"(_m), "r"(_p) : "memory"); \
    } \
} while (0)

#define LDTM_X32(r, t) \
    asm volatile("tcgen05.ld.sync.aligned.32x32b.x32.b32 " \
        "{%0, %1, %2, %3, %4, %5, %6, %7, %8, %9, %10, %11, %12, %13, %14, %15, " \
        " %16, %17, %18, %19, %20, %21, %22, %23, %24, %25, %26, %27, %28, %29, %30, %31}, [%32];" \
        : "=r"((r)[0]),  "=r"((r)[1]),  "=r"((r)[2]),  "=r"((r)[3]), \
          "=r"((r)[4]),  "=r"((r)[5]),  "=r"((r)[6]),  "=r"((r)[7]), \
          "=r"((r)[8]),  "=r"((r)[9]),  "=r"((r)[10]), "=r"((r)[11]), \
          "=r"((r)[12]), "=r"((r)[13]), "=r"((r)[14]), "=r"((r)[15]), \
          "=r"((r)[16]), "=r"((r)[17]), "=r"((r)[18]), "=r"((r)[19]), \
          "=r"((r)[20]), "=r"((r)[21]), "=r"((r)[22]), "=r"((r)[23]), \
          "=r"((r)[24]), "=r"((r)[25]), "=r"((r)[26]), "=r"((r)[27]), \
          "=r"((r)[28]), "=r"((r)[29]), "=r"((r)[30]), "=r"((r)[31]) \
        : "r"(t))

static constexpr uint64_t DESC_BASE_SW128 =
    (uint64_t(2) << 61) | (uint64_t(1) << 46) | (uint64_t(64) << 32) | (uint64_t(1) << 16);
__device__ __forceinline__ uint64_t make_desc(uint32_t addr) {
    return DESC_BASE_SW128 | ((uint64_t)(addr >> 4) & 0x3FFF);
}

// idesc: dtype=F32(1<<4), atype=TF32(2<<7), btype=TF32(2<<10), N/8=16<<17, M/16=8<<24
static constexpr uint32_t IDESC_TF32 =
    (1u << 4) | (2u << 7) | (2u << 10) | (16u << 17) | (8u << 24);

__device__ __forceinline__ void mma_tf32_ss(uint32_t d, uint64_t a, uint64_t b,
                                            bool acc) {
    uint32_t en = acc ? 1u : 0u;
    asm volatile(
        "{\n\t.reg .pred p;\n\tsetp.ne.u32 p, %5, 0;\n\t"
        "tcgen05.mma.cta_group::1.kind::tf32 [%0], %1, %2, %3, {%4, %4, %4, %4}, p;\n\t}"
        :: "r"(d), "l"(a), "l"(b), "r"(IDESC_TF32), "r"(0u), "r"(en) : "memory");
}

#endif // HAS_TCGEN05

// ---------------- setup kernels ----------------
__global__ void deg_kernel(const int* __restrict__ src, const int* __restrict__ dst) {
    int e = blockIdx.x * blockDim.x + threadIdx.x;
    if (e < NE) {
        atomicAdd(&g_deg_out[src[e]], 1);
        atomicAdd(&g_deg_in[dst[e]], 1);
    }
}

__global__ void __launch_bounds__(256) block_reduce_kernel() {
    const int b = blockIdx.x;
    const int tid = threadIdx.x;
    const int4* di4 = (const int4*)g_deg_in;
    int4 v = di4[b * 256 + tid];
    int s = v.x + v.y + v.z + v.w;
    #pragma unroll
    for (int o = 16; o > 0; o >>= 1) s += __shfl_xor_sync(0xFFFFFFFFu, s, o);
    __shared__ int ws[8];
    if ((tid & 31) == 0) ws[tid >> 5] = s;
    __syncthreads();
    if (tid < 8) {
        int t = ws[tid];
        #pragma unroll
        for (int o = 4; o > 0; o >>= 1) t += __shfl_xor_sync(0xFFu, t, o);
        if (tid == 0) g_part[b] = t;
    }
}

__global__ void scan_parts_kernel() {
    if (threadIdx.x == 0) {
        int run = 0;
        #pragma unroll
        for (int i = 0; i < SCAN_NB; i++) {
            int v = g_part[i];
            g_part[i] = run;
            run += v;
        }
        g_rowptr[NN] = run;
    }
}

__global__ void __launch_bounds__(256) block_scan_kernel() {
    const int b = blockIdx.x;
    const int tid = threadIdx.x;
    const int base = b * SCAN_CH + tid * 4;

    const int4* di4 = (const int4*)g_deg_in;
    int4 v = di4[b * 256 + tid];
    int tsum = v.x + v.y + v.z + v.w;

    __shared__ int sc[256];
    sc[tid] = tsum;
    __syncthreads();
    #pragma unroll
    for (int o = 1; o < 256; o <<= 1) {
        int t = (tid >= o) ? sc[tid - o] : 0;
        __syncthreads();
        sc[tid] += t;
        __syncthreads();
    }
    int run = g_part[b] + ((tid == 0) ? 0 : sc[tid - 1]);

    int r0 = run;
    int r1 = r0 + v.x;
    int r2 = r1 + v.y;
    int r3 = r2 + v.z;

    if (base + 0 < NN) { g_rowptr[base+0] = r0; g_cursor[base+0] = r0; }
    if (base + 1 < NN) { g_rowptr[base+1] = r1; g_cursor[base+1] = r1; }
    if (base + 2 < NN) { g_rowptr[base+2] = r2; g_cursor[base+2] = r2; }
    if (base + 3 < NN) { g_rowptr[base+3] = r3; g_cursor[base+3] = r3; }

    #pragma unroll
    for (int j = 0; j < 4; j++) {
        int idx = base + j;
        if (idx < NN) {
            int din = (j == 0) ? v.x : (j == 1) ? v.y : (j == 2) ? v.z : v.w;
            g_inv_in[idx]  = rsqrtf(fmaxf((float)din, 1.0f));
            g_inv_out[idx] = rsqrtf(fmaxf((float)g_deg_out[idx], 1.0f));
        }
    }
}

__global__ void scatter_kernel(const int* __restrict__ src, const int* __restrict__ dst) {
    int e = blockIdx.x * blockDim.x + threadIdx.x;
    if (e < NE) {
        int d = dst[e];
        int p = atomicAdd(&g_cursor[d], 1);
        g_col[p] = src[e];
    }
}

// ---------------- W prep: transpose + tf32 hi/lo split + swizzle ----------------
__global__ void __launch_bounds__(256) prep_w_kernel(const float* __restrict__ Ws) {
    int idx = blockIdx.x * 256 + threadIdx.x;     // 3*16384 total
    int layer = idx >> 14;
    int rem = idx & 16383;
    int k = rem >> 7;        // 0..127
    int n = rem & 127;       // 0..127 (consecutive threads -> coalesced read)
    float w = Ws[layer * RK * RK + k * RK + n];
    uint32_t hi, lo;
    split_tf32(w, hi, lo);
    uint32_t off4 = tile_off_sw(n, k) >> 2;       // B[n][k]
    g_Bhi[layer][off4] = __uint_as_float(hi);
    g_Blo[layer][off4] = __uint_as_float(lo);
}

// ---------------- tcgen05 GEMM: H[n][c] = inv_out[n] * (X W)[n][c] ----------------
// 3xTF32: D = Xhi*Bhi + Xlo*Bhi + Xhi*Blo
#define SM_META 0
#define SM_MBAR 8
#define SM_XHI  1024
#define SM_XLO  (SM_XHI + 65536)
#define SM_BHI  (SM_XLO + 65536)
#define SM_BLO  (SM_BHI + 32768)
#define SM_TOTAL (SM_BLO + 32768)
#define TMEM_COLS 128
#define GRID_M ((NN + 127) / 128)

__global__ void __launch_bounds__(128, 1) gemm_tc_kernel(
    const float* __restrict__ X,
    const float* __restrict__ Bhi, const float* __restrict__ Blo,
    float* __restrict__ H)
{
#if HAS_TCGEN05
    extern __shared__ char smem[];
    const uint32_t sbase = smem_u32(smem);
    const int tid = threadIdx.x;
    const int wid = tid >> 5;
    const int lane = tid & 31;
    const int row0 = blockIdx.x * 128;

    if (wid == 0) TC_ALLOC(sbase + SM_META, TMEM_COLS);
    if (tid == 0) MBAR_INIT(sbase + SM_MBAR, 1);

    // load + split X tile [128 x 128] into swizzled blocked layout
    const float4* X4 = (const float4*)X;
    #pragma unroll
    for (int i = 0; i < 32; i++) {
        int idx = tid + i * 128;            // 4096 float4
        int r = idx >> 5, c4 = idx & 31;
        float4 v = make_float4(0.f, 0.f, 0.f, 0.f);
        if (row0 + r < NN) v = X4[(row0 + r) * 32 + c4];
        uint32_t h0, l0, h1, l1, h2, l2, h3, l3;
        split_tf32(v.x, h0, l0); split_tf32(v.y, h1, l1);
        split_tf32(v.z, h2, l2); split_tf32(v.w, h3, l3);
        uint32_t off = tile_off_sw(r, c4 * 4);
        *(uint4*)(smem + SM_XHI + off) = make_uint4(h0, h1, h2, h3);
        *(uint4*)(smem + SM_XLO + off) = make_uint4(l0, l1, l2, l3);
    }

    __syncthreads();
    uint32_t tmem;
    asm volatile("ld.shared.b32 %0, [%1];" : "=r"(tmem) : "r"(sbase + SM_META));

    const uint64_t a_hi = make_desc(sbase + SM_XHI);
    const uint64_t a_lo = make_desc(sbase + SM_XLO);
    const uint64_t b_hi = make_desc(sbase + SM_BHI);
    const uint64_t b_lo = make_desc(sbase + SM_BLO);

    for (int half = 0; half < 2; half++) {
        // copy this half's pre-swizzled B (2 atom-cols = 8192 floats each buf)
        const float4* sh = (const float4*)(Bhi + half * 8192);
        const float4* sl = (const float4*)(Blo + half * 8192);
        float4* dh = (float4*)(smem + SM_BHI);
        float4* dl = (float4*)(smem + SM_BLO);
        #pragma unroll
        for (int i = 0; i < 16; i++) {
            dh[tid + i * 128] = sh[tid + i * 128];
            dl[tid + i * 128] = sl[tid + i * 128];
        }
        __syncthreads();

        if (tid == 0) {
            TC_FENCE_AFTER();
            #pragma unroll
            for (int p = 0; p < 3; p++) {
                uint64_t ab = (p == 1) ? a_lo : a_hi;
                uint64_t bb = (p == 2) ? b_lo : b_hi;
                #pragma unroll
                for (int s = 0; s < 8; s++) {
                    int g = half * 8 + s;
                    uint64_t a = ab + (uint64_t)((g >> 2) * 1024 + (g & 3) * 2);
                    uint64_t b = bb + (uint64_t)((s >> 2) * 1024 + (s & 3) * 2);
                    mma_tf32_ss(tmem, a, b, !(half == 0 && p == 0 && s == 0));
                }
            }
            TC_COMMIT(sbase + SM_MBAR);
        }
        MBAR_WAIT(sbase + SM_MBAR, half);
        if (half == 0) __syncthreads();  // everyone past wait before B overwrite
    }

    TC_FENCE_AFTER();

    // epilogue: each warp reads its 32-lane subpartition, scales, stores
    int row = row0 + wid * 32 + lane;
    float s = (row < NN) ? g_inv_out[row] : 0.f;
    float4* H4 = (float4*)H;
    #pragma unroll
    for (int base = 0; base < 128; base += 32) {
        uint32_t r[32];
        LDTM_X32(r, tmem + base);
        TC_WAIT_LD();
        if (row < NN) {
            #pragma unroll
            for (int j = 0; j < 8; j++) {
                float4 o;
                o.x = __uint_as_float(r[j*4+0]) * s;
                o.y = __uint_as_float(r[j*4+1]) * s;
                o.z = __uint_as_float(r[j*4+2]) * s;
                o.w = __uint_as_float(r[j*4+3]) * s;
                H4[row * 32 + (base >> 2) + j] = o;
            }
        }
    }

    TC_FENCE_BEFORE();
    __syncthreads();
    if (wid == 0) {
        TC_RELINQ();
        TC_DEALLOC(tmem, TMEM_COLS);
    }
#else
    // Portable-PTX fallback target (compute_103): never executed on GB300 —
    // the harness runs the sm_103a cubin. Intentionally empty.
    (void)X; (void)Bhi; (void)Blo; (void)H;
#endif
}

// ---------------- SpMM + inv_in + bias + LayerNorm + ReLU ----------------
__global__ void __launch_bounds__(256) spmm_ln_kernel(
    const float* __restrict__ H,
    const float* __restrict__ b, const float* __restrict__ gamma,
    const float* __restrict__ beta, float* __restrict__ out)
{
    int warp = (blockIdx.x * blockDim.x + threadIdx.x) >> 5;
    int lane = threadIdx.x & 31;
    if (warp >= NN) return;

    int beg = g_rowptr[warp];
    int end = g_rowptr[warp + 1];
    const float4* H4 = (const float4*)H;

    float4 acc = make_float4(0.f, 0.f, 0.f, 0.f);
    int e = beg;
    for (; e + 3 < end; e += 4) {
        int s0 = g_col[e], s1 = g_col[e+1], s2 = g_col[e+2], s3 = g_col[e+3];
        float4 v0 = H4[s0 * 32 + lane];
        float4 v1 = H4[s1 * 32 + lane];
        float4 v2 = H4[s2 * 32 + lane];
        float4 v3 = H4[s3 * 32 + lane];
        acc.x += v0.x + v1.x + v2.x + v3.x;
        acc.y += v0.y + v1.y + v2.y + v3.y;
        acc.z += v0.z + v1.z + v2.z + v3.z;
        acc.w += v0.w + v1.w + v2.w + v3.w;
    }
    for (; e < end; e++) {
        int s0 = g_col[e];
        float4 v0 = H4[s0 * 32 + lane];
        acc.x += v0.x; acc.y += v0.y; acc.z += v0.z; acc.w += v0.w;
    }

    float sc = g_inv_in[warp];
    float4 bb = ((const float4*)b)[lane];
    float x0 = acc.x * sc + bb.x;
    float x1 = acc.y * sc + bb.y;
    float x2 = acc.z * sc + bb.z;
    float x3 = acc.w * sc + bb.w;

    float s = x0 + x1 + x2 + x3;
    #pragma unroll
    for (int o = 16; o > 0; o >>= 1) s += __shfl_xor_sync(0xFFFFFFFFu, s, o);
    float mu = s * (1.0f / RK);

    float d0 = x0 - mu, d1 = x1 - mu, d2 = x2 - mu, d3 = x3 - mu;
    float v = d0*d0 + d1*d1 + d2*d2 + d3*d3;
    #pragma unroll
    for (int o = 16; o > 0; o >>= 1) v += __shfl_xor_sync(0xFFFFFFFFu, v, o);
    float rstd = rsqrtf(v * (1.0f / RK) + LN_EPS);

    float4 gg = ((const float4*)gamma)[lane];
    float4 be = ((const float4*)beta)[lane];
    float y0 = fmaxf(d0 * rstd * gg.x + be.x, 0.f);
    float y1 = fmaxf(d1 * rstd * gg.y + be.y, 0.f);
    float y2 = fmaxf(d2 * rstd * gg.z + be.z, 0.f);
    float y3 = fmaxf(d3 * rstd * gg.w + be.w, 0.f);

    ((float4*)out)[warp * 32 + lane] = make_float4(y0, y1, y2, y3);
}

// ---------------- final gather ----------------
__global__ void gather_out_kernel(const float* __restrict__ feats,
                                  const int* __restrict__ bnn,
                                  float* __restrict__ out)
{
    __shared__ int sidx;
    int g = blockIdx.x;
    if (threadIdx.x == 0) {
        int p = 0;
        for (int i = 0; i < g; i++) p += bnn[i];
        sidx = p;
    }
    __syncthreads();
    out[g * RK + threadIdx.x] = feats[sidx * RK + threadIdx.x];
}

// ---------------- launch ----------------
extern "C" void kernel_launch(void* const* d_in, const int* in_sizes, int n_in,
                              void* d_out, int out_size)
{
    const float* features = (const float*)d_in[0];
    const int*   src      = (const int*)d_in[1];
    const int*   dst      = (const int*)d_in[2];
    const int*   bnn      = (const int*)d_in[3];
    const float* Ws       = (const float*)d_in[4];
    const float* bs       = (const float*)d_in[5];
    const float* gammas   = (const float*)d_in[6];
    const float* betas    = (const float*)d_in[7];
    float* out = (float*)d_out;

    static int smem_set = 0;
    if (!smem_set) {
        cudaFuncSetAttribute(gemm_tc_kernel,
                             cudaFuncAttributeMaxDynamicSharedMemorySize, SM_TOTAL);
        smem_set = 1;
    }

    float *hbuf, *bufA, *bufB, *bhi, *blo;
    cudaGetSymbolAddress((void**)&hbuf, g_h);
    cudaGetSymbolAddress((void**)&bufA, g_bufA);
    cudaGetSymbolAddress((void**)&bufB, g_bufB);
    cudaGetSymbolAddress((void**)&bhi, g_Bhi);
    cudaGetSymbolAddress((void**)&blo, g_Blo);
    int *dout_p, *din_p;
    cudaGetSymbolAddress((void**)&dout_p, g_deg_out);
    cudaGetSymbolAddress((void**)&din_p, g_deg_in);

    cudaMemsetAsync(dout_p, 0, NN * sizeof(int));
    cudaMemsetAsync(din_p, 0, (NN + SCAN_CH) * sizeof(int));

    // graph structure + weight prep
    deg_kernel<<<(NE + 255) / 256, 256>>>(src, dst);
    prep_w_kernel<<<(ORDER * RK * RK) / 256, 256>>>(Ws);
    block_reduce_kernel<<<SCAN_NB, 256>>>();
    scan_parts_kernel<<<1, 32>>>();
    block_scan_kernel<<<SCAN_NB, 256>>>();
    scatter_kernel<<<(NE + 255) / 256, 256>>>(src, dst);

    const int spmm_grid = (NN * 32 + 255) / 256;

    const float* in_ptr = features;
    float* outs[ORDER] = {bufA, bufB, bufA};
    for (int i = 0; i < ORDER; i++) {
        gemm_tc_kernel<<<GRID_M, 128, SM_TOTAL>>>(in_ptr,
                                                  bhi + i * RK * RK,
                                                  blo + i * RK * RK, hbuf);
        spmm_ln_kernel<<<spmm_grid, 256>>>(hbuf, bs + i * RK, gammas + i * RK,
                                           betas + i * RK, outs[i]);
        in_ptr = outs[i];
    }

    gather_out_kernel<<<NG, RK>>>(outs[ORDER - 1], bnn, out);
}

// round 7
// speedup vs baseline: 1.8399x; 1.1404x over previous
#include <cuda_runtime.h>
#include <cuda_bf16.h>
#include <cuda_fp16.h>
#include <cstdint>

#define NN 50000
#define NE 640000
#define RK 128
#define NG 50
#define ORDER 3
#define LN_EPS 1e-5f

#define SCAN_CH 1024
#define SCAN_NB ((NN + SCAN_CH - 1) / SCAN_CH)   // 49

// tcgen05 is arch-accelerated: legal only in the compute_103a / sm_103a pass.
#if defined(__CUDA_ARCH__) && (defined(__CUDA_ARCH_FEAT_SM103_ALL) || \
    (defined(__CUDA_ARCH_SPECIFIC__) && (__CUDA_ARCH_SPECIFIC__ == 1030)))
#define HAS_TCGEN05 1
#else
#define HAS_TCGEN05 0
#endif

// ---------------- device scratch (no allocation allowed) ----------------
__device__ uint2 g_h16[NN * 32];   // H in fp16: 32 uint2 (=128 half) per row
__device__ float g_bufA[NN * RK];
__device__ float g_bufB[NN * RK];
__device__ int   g_deg_out[NN];
__device__ int   g_deg_in[NN + SCAN_CH];
__device__ float g_inv_out[NN];
__device__ float g_inv_in[NN];
__device__ int   g_rowptr[NN + 1];
__device__ int   g_cursor[NN];
__device__ int   g_col[NE];
__device__ __align__(16) int g_part[52];   // 49 used + 3 zero pad (int4 loads)
// pre-transposed / pre-split / pre-swizzled W (B[n][k] = W[k][n]) per layer
__device__ float g_Bhi[ORDER][RK * RK];
__device__ float g_Blo[ORDER][RK * RK];

// ---------------- portable helpers ----------------
__device__ __forceinline__ uint32_t smem_u32(const void* p) {
    uint32_t a;
    asm("{ .reg .u64 t; cvta.to.shared.u64 t, %1; cvt.u32.u64 %0, t; }" : "=r"(a) : "l"(p));
    return a;
}

__device__ __forceinline__ void split_tf32(float x, uint32_t& hi, uint32_t& lo) {
    uint32_t h;
    asm("cvt.rna.tf32.f32 %0, %1;" : "=r"(h) : "f"(x));
    float l = x - __uint_as_float(h);
    uint32_t lb;
    asm("cvt.rna.tf32.f32 %0, %1;" : "=r"(lb) : "f"(l));
    hi = h; lo = lb;
}

// blocked SW128 atom layout for a [128 rows x 128 float cols] tile
__device__ __forceinline__ uint32_t tile_off_sw(int row, int col) {
    uint32_t boff = (uint32_t)((row >> 3) + (col >> 5) * 16) * 1024u
                  + (uint32_t)(row & 7) * 128u + (uint32_t)(col & 31) * 4u;
    return boff ^ ((boff >> 3) & 0x70);
}

// ---------------- sm_103a-only PTX wrappers ----------------
#if HAS_TCGEN05

#define TC_ALLOC(saddr, n) \
    asm volatile("tcgen05.alloc.cta_group::1.sync.aligned.shared::cta.b32 [%0], %1;" \
                 :: "r"((uint32_t)(saddr)), "r"((uint32_t)(n)) : "memory")
#define TC_DEALLOC(t, n) \
    asm volatile("tcgen05.dealloc.cta_group::1.sync.aligned.b32 %0, %1;" :: "r"(t), "r"((uint32_t)(n)))
#define TC_RELINQ() \
    asm volatile("tcgen05.relinquish_alloc_permit.cta_group::1.sync.aligned;")
#define TC_COMMIT(mbar) \
    asm volatile("tcgen05.commit.cta_group::1.mbarrier::arrive::one.shared::cluster.b64 [%0];" \
                 :: "r"((uint32_t)(mbar)) : "memory")
#define TC_FENCE_AFTER()  asm volatile("tcgen05.fence::after_thread_sync;" ::: "memory")
#define TC_FENCE_BEFORE() asm volatile("tcgen05.fence::before_thread_sync;" ::: "memory")
#define TC_WAIT_LD()      asm volatile("tcgen05.wait::ld.sync.aligned;" ::: "memory")

#define MBAR_INIT(mbar, cnt) \
    asm volatile("mbarrier.init.shared.b64 [%0], %1;" :: "r"((uint32_t)(mbar)), "r"((uint32_t)(cnt)) : "memory")
#define MBAR_WAIT(mbar, ph) do { \
    uint32_t _m = (uint32_t)(mbar); uint32_t _p = (uint32_t)(ph); uint32_t _d; \
    asm volatile("{\n\t.reg .pred p;\n\t" \
        "mbarrier.try_wait.parity.acquire.cta.shared::cta.b64 p, [%1], %2;\n\t" \
        "selp.b32 %0, 1, 0, p;\n\t}" : "=r"(_d) : "r"(_m), "r"(_p) : "memory"); \
    if (!_d) { \
        asm volatile("{\n\t.reg .pred P1;\n\t" \
            "WL_%=:\n\t" \
            "mbarrier.try_wait.parity.acquire.cta.shared::cta.b64 P1, [%0], %1, 0x989680;\n\t" \
            "@P1 bra.uni WD_%=;\n\t" \
            "bra.uni WL_%=;\n\t" \
            "WD_%=:\n\t}" :: "r"(_m), "r"(_p) : "memory"); \
    } \
} while (0)

#define LDTM_X32(r, t) \
    asm volatile("tcgen05.ld.sync.aligned.32x32b.x32.b32 " \
        "{%0, %1, %2, %3, %4, %5, %6, %7, %8, %9, %10, %11, %12, %13, %14, %15, " \
        " %16, %17, %18, %19, %20, %21, %22, %23, %24, %25, %26, %27, %28, %29, %30, %31}, [%32];" \
        : "=r"((r)[0]),  "=r"((r)[1]),  "=r"((r)[2]),  "=r"((r)[3]), \
          "=r"((r)[4]),  "=r"((r)[5]),  "=r"((r)[6]),  "=r"((r)[7]), \
          "=r"((r)[8]),  "=r"((r)[9]),  "=r"((r)[10]), "=r"((r)[11]), \
          "=r"((r)[12]), "=r"((r)[13]), "=r"((r)[14]), "=r"((r)[15]), \
          "=r"((r)[16]), "=r"((r)[17]), "=r"((r)[18]), "=r"((r)[19]), \
          "=r"((r)[20]), "=r"((r)[21]), "=r"((r)[22]), "=r"((r)[23]), \
          "=r"((r)[24]), "=r"((r)[25]), "=r"((r)[26]), "=r"((r)[27]), \
          "=r"((r)[28]), "=r"((r)[29]), "=r"((r)[30]), "=r"((r)[31]) \
        : "r"(t))

static constexpr uint64_t DESC_BASE_SW128 =
    (uint64_t(2) << 61) | (uint64_t(1) << 46) | (uint64_t(64) << 32) | (uint64_t(1) << 16);
__device__ __forceinline__ uint64_t make_desc(uint32_t addr) {
    return DESC_BASE_SW128 | ((uint64_t)(addr >> 4) & 0x3FFF);
}

// idesc: dtype=F32, atype=btype=TF32, N=128, M=128
static constexpr uint32_t IDESC_TF32 =
    (1u << 4) | (2u << 7) | (2u << 10) | (16u << 17) | (8u << 24);

__device__ __forceinline__ void mma_tf32_ss(uint32_t d, uint64_t a, uint64_t b,
                                            bool acc) {
    uint32_t en = acc ? 1u : 0u;
    asm volatile(
        "{\n\t.reg .pred p;\n\tsetp.ne.u32 p, %5, 0;\n\t"
        "tcgen05.mma.cta_group::1.kind::tf32 [%0], %1, %2, %3, {%4, %4, %4, %4}, p;\n\t}"
        :: "r"(d), "l"(a), "l"(b), "r"(IDESC_TF32), "r"(0u), "r"(en) : "memory");
}

#endif // HAS_TCGEN05

// ---------------- setup: degrees + W prep fused ----------------
__global__ void __launch_bounds__(256) setup_kernel(
    const int* __restrict__ src, const int* __restrict__ dst,
    const float* __restrict__ Ws)
{
    int i = blockIdx.x * 256 + threadIdx.x;
    if (i < NE) {
        atomicAdd(&g_deg_out[src[i]], 1);
        atomicAdd(&g_deg_in[dst[i]], 1);
    }
    if (i < ORDER * RK * RK) {
        int layer = i >> 14;
        int rem = i & 16383;
        int k = rem >> 7;
        int n = rem & 127;
        float w = Ws[layer * RK * RK + k * RK + n];
        uint32_t hi, lo;
        split_tf32(w, hi, lo);
        uint32_t off4 = tile_off_sw(n, k) >> 2;
        g_Bhi[layer][off4] = __uint_as_float(hi);
        g_Blo[layer][off4] = __uint_as_float(lo);
    }
    if (i < 3) g_part[49 + i] = 0;   // pad for int4 scan loads
}

// phase 1: per-1024-chunk sums of deg_in
__global__ void __launch_bounds__(256) block_reduce_kernel() {
    const int b = blockIdx.x;
    const int tid = threadIdx.x;
    const int4* di4 = (const int4*)g_deg_in;
    int4 v = di4[b * 256 + tid];
    int s = v.x + v.y + v.z + v.w;
    #pragma unroll
    for (int o = 16; o > 0; o >>= 1) s += __shfl_xor_sync(0xFFFFFFFFu, s, o);
    __shared__ int ws[8];
    if ((tid & 31) == 0) ws[tid >> 5] = s;
    __syncthreads();
    if (tid < 8) {
        int t = ws[tid];
        #pragma unroll
        for (int o = 4; o > 0; o >>= 1) t += __shfl_xor_sync(0xFFu, t, o);
        if (tid == 0) g_part[b] = t;
    }
}

// phase 2 (fused): chunk offset from g_part via warp scan; per-chunk scan;
// rowptr/cursor/inv writes
__global__ void __launch_bounds__(256) block_scan_kernel() {
    const int b = blockIdx.x;
    const int tid = threadIdx.x;
    const int base = b * SCAN_CH + tid * 4;

    __shared__ int s_off;
    if (tid < 32) {
        int4 p = (tid < 13) ? ((const int4*)g_part)[tid] : make_int4(0, 0, 0, 0);
        int i0 = tid * 4;
        int off = ((i0 + 0) < b ? p.x : 0) + ((i0 + 1) < b ? p.y : 0)
                + ((i0 + 2) < b ? p.z : 0) + ((i0 + 3) < b ? p.w : 0);
        int tot = p.x + p.y + p.z + p.w;
        #pragma unroll
        for (int o = 16; o > 0; o >>= 1) {
            off += __shfl_xor_sync(0xFFFFFFFFu, off, o);
            tot += __shfl_xor_sync(0xFFFFFFFFu, tot, o);
        }
        if (tid == 0) {
            s_off = off;
            if (b == 0) g_rowptr[NN] = tot;
        }
    }

    const int4* di4 = (const int4*)g_deg_in;
    int4 v = di4[b * 256 + tid];
    int tsum = v.x + v.y + v.z + v.w;

    __shared__ int sc[256];
    sc[tid] = tsum;
    __syncthreads();
    #pragma unroll
    for (int o = 1; o < 256; o <<= 1) {
        int t = (tid >= o) ? sc[tid - o] : 0;
        __syncthreads();
        sc[tid] += t;
        __syncthreads();
    }
    int run = s_off + ((tid == 0) ? 0 : sc[tid - 1]);

    int r0 = run;
    int r1 = r0 + v.x;
    int r2 = r1 + v.y;
    int r3 = r2 + v.z;

    if (base + 0 < NN) { g_rowptr[base+0] = r0; g_cursor[base+0] = r0; }
    if (base + 1 < NN) { g_rowptr[base+1] = r1; g_cursor[base+1] = r1; }
    if (base + 2 < NN) { g_rowptr[base+2] = r2; g_cursor[base+2] = r2; }
    if (base + 3 < NN) { g_rowptr[base+3] = r3; g_cursor[base+3] = r3; }

    #pragma unroll
    for (int j = 0; j < 4; j++) {
        int idx = base + j;
        if (idx < NN) {
            int din = (j == 0) ? v.x : (j == 1) ? v.y : (j == 2) ? v.z : v.w;
            g_inv_in[idx]  = rsqrtf(fmaxf((float)din, 1.0f));
            g_inv_out[idx] = rsqrtf(fmaxf((float)g_deg_out[idx], 1.0f));
        }
    }
}

__global__ void scatter_kernel(const int* __restrict__ src, const int* __restrict__ dst) {
    int e = blockIdx.x * blockDim.x + threadIdx.x;
    if (e < NE) {
        int d = dst[e];
        int p = atomicAdd(&g_cursor[d], 1);
        g_col[p] = src[e];
    }
}

// ---------------- tcgen05 GEMM: H16[n][c] = fp16(inv_out[n] * (X W)[n][c]) ----------------
#define SM_META 0
#define SM_MBAR 8
#define SM_XHI  1024
#define SM_XLO  (SM_XHI + 65536)
#define SM_BHI  (SM_XLO + 65536)
#define SM_BLO  (SM_BHI + 32768)
#define SM_TOTAL (SM_BLO + 32768)
#define TMEM_COLS 128
#define GRID_M ((NN + 127) / 128)

__global__ void __launch_bounds__(128, 1) gemm_tc_kernel(
    const float* __restrict__ X,
    const float* __restrict__ Bhi, const float* __restrict__ Blo,
    uint2* __restrict__ H)
{
#if HAS_TCGEN05
    extern __shared__ char smem[];
    const uint32_t sbase = smem_u32(smem);
    const int tid = threadIdx.x;
    const int wid = tid >> 5;
    const int lane = tid & 31;
    const int row0 = blockIdx.x * 128;

    if (wid == 0) TC_ALLOC(sbase + SM_META, TMEM_COLS);
    if (tid == 0) MBAR_INIT(sbase + SM_MBAR, 1);

    // load + split X tile [128 x 128] into swizzled blocked layout
    const float4* X4 = (const float4*)X;
    #pragma unroll
    for (int i = 0; i < 32; i++) {
        int idx = tid + i * 128;
        int r = idx >> 5, c4 = idx & 31;
        float4 v = make_float4(0.f, 0.f, 0.f, 0.f);
        if (row0 + r < NN) v = X4[(row0 + r) * 32 + c4];
        uint32_t h0, l0, h1, l1, h2, l2, h3, l3;
        split_tf32(v.x, h0, l0); split_tf32(v.y, h1, l1);
        split_tf32(v.z, h2, l2); split_tf32(v.w, h3, l3);
        uint32_t off = tile_off_sw(r, c4 * 4);
        *(uint4*)(smem + SM_XHI + off) = make_uint4(h0, h1, h2, h3);
        *(uint4*)(smem + SM_XLO + off) = make_uint4(l0, l1, l2, l3);
    }

    __syncthreads();
    uint32_t tmem;
    asm volatile("ld.shared.b32 %0, [%1];" : "=r"(tmem) : "r"(sbase + SM_META));

    const uint64_t a_hi = make_desc(sbase + SM_XHI);
    const uint64_t a_lo = make_desc(sbase + SM_XLO);
    const uint64_t b_hi = make_desc(sbase + SM_BHI);
    const uint64_t b_lo = make_desc(sbase + SM_BLO);

    for (int half = 0; half < 2; half++) {
        const float4* sh = (const float4*)(Bhi + half * 8192);
        const float4* sl = (const float4*)(Blo + half * 8192);
        float4* dh = (float4*)(smem + SM_BHI);
        float4* dl = (float4*)(smem + SM_BLO);
        #pragma unroll
        for (int i = 0; i < 16; i++) {
            dh[tid + i * 128] = sh[tid + i * 128];
            dl[tid + i * 128] = sl[tid + i * 128];
        }
        __syncthreads();

        if (tid == 0) {
            TC_FENCE_AFTER();
            #pragma unroll
            for (int p = 0; p < 3; p++) {
                uint64_t ab = (p == 1) ? a_lo : a_hi;
                uint64_t bb = (p == 2) ? b_lo : b_hi;
                #pragma unroll
                for (int s = 0; s < 8; s++) {
                    int g = half * 8 + s;
                    uint64_t a = ab + (uint64_t)((g >> 2) * 1024 + (g & 3) * 2);
                    uint64_t b = bb + (uint64_t)((s >> 2) * 1024 + (s & 3) * 2);
                    mma_tf32_ss(tmem, a, b, !(half == 0 && p == 0 && s == 0));
                }
            }
            TC_COMMIT(sbase + SM_MBAR);
        }
        MBAR_WAIT(sbase + SM_MBAR, half);
        if (half == 0) __syncthreads();
    }

    TC_FENCE_AFTER();

    // epilogue: scale by inv_out, convert fp16, store (32 uint2 per row)
    int row = row0 + wid * 32 + lane;
    float s = (row < NN) ? g_inv_out[row] : 0.f;
    #pragma unroll
    for (int base = 0; base < 128; base += 32) {
        uint32_t r[32];
        LDTM_X32(r, tmem + base);
        TC_WAIT_LD();
        if (row < NN) {
            #pragma unroll
            for (int j = 0; j < 8; j++) {
                float2 p0 = make_float2(__uint_as_float(r[j*4+0]) * s,
                                        __uint_as_float(r[j*4+1]) * s);
                float2 p1 = make_float2(__uint_as_float(r[j*4+2]) * s,
                                        __uint_as_float(r[j*4+3]) * s);
                __half2 h0 = __float22half2_rn(p0);
                __half2 h1 = __float22half2_rn(p1);
                uint2 u;
                u.x = *reinterpret_cast<uint32_t*>(&h0);
                u.y = *reinterpret_cast<uint32_t*>(&h1);
                H[row * 32 + (base >> 2) + j] = u;
            }
        }
    }

    TC_FENCE_BEFORE();
    __syncthreads();
    if (wid == 0) {
        TC_RELINQ();
        TC_DEALLOC(tmem, TMEM_COLS);
    }
#else
    // Portable-PTX fallback target (compute_103): never executed on GB300.
    (void)X; (void)Bhi; (void)Blo; (void)H;
#endif
}

// ---------------- SpMM(fp16 in, fp32 accum) + inv_in + bias + LN + ReLU ----------------
__global__ void __launch_bounds__(256) spmm_ln_kernel(
    const uint2* __restrict__ H,
    const float* __restrict__ b, const float* __restrict__ gamma,
    const float* __restrict__ beta, float* __restrict__ out)
{
    int warp = (blockIdx.x * blockDim.x + threadIdx.x) >> 5;
    int lane = threadIdx.x & 31;
    if (warp >= NN) return;

    int beg = g_rowptr[warp];
    int end = g_rowptr[warp + 1];

    float4 acc = make_float4(0.f, 0.f, 0.f, 0.f);
    int e = beg;
    for (; e + 3 < end; e += 4) {
        int s0 = g_col[e], s1 = g_col[e+1], s2 = g_col[e+2], s3 = g_col[e+3];
        uint2 v0 = H[s0 * 32 + lane];
        uint2 v1 = H[s1 * 32 + lane];
        uint2 v2 = H[s2 * 32 + lane];
        uint2 v3 = H[s3 * 32 + lane];
        #pragma unroll
        for (int q = 0; q < 4; q++) {
            uint2 v = (q == 0) ? v0 : (q == 1) ? v1 : (q == 2) ? v2 : v3;
            float2 a0 = __half22float2(*reinterpret_cast<__half2*>(&v.x));
            float2 a1 = __half22float2(*reinterpret_cast<__half2*>(&v.y));
            acc.x += a0.x; acc.y += a0.y; acc.z += a1.x; acc.w += a1.y;
        }
    }
    for (; e < end; e++) {
        uint2 v = H[g_col[e] * 32 + lane];
        float2 a0 = __half22float2(*reinterpret_cast<__half2*>(&v.x));
        float2 a1 = __half22float2(*reinterpret_cast<__half2*>(&v.y));
        acc.x += a0.x; acc.y += a0.y; acc.z += a1.x; acc.w += a1.y;
    }

    float sc = g_inv_in[warp];
    float4 bb = ((const float4*)b)[lane];
    float x0 = acc.x * sc + bb.x;
    float x1 = acc.y * sc + bb.y;
    float x2 = acc.z * sc + bb.z;
    float x3 = acc.w * sc + bb.w;

    float s = x0 + x1 + x2 + x3;
    #pragma unroll
    for (int o = 16; o > 0; o >>= 1) s += __shfl_xor_sync(0xFFFFFFFFu, s, o);
    float mu = s * (1.0f / RK);

    float d0 = x0 - mu, d1 = x1 - mu, d2 = x2 - mu, d3 = x3 - mu;
    float v = d0*d0 + d1*d1 + d2*d2 + d3*d3;
    #pragma unroll
    for (int o = 16; o > 0; o >>= 1) v += __shfl_xor_sync(0xFFFFFFFFu, v, o);
    float rstd = rsqrtf(v * (1.0f / RK) + LN_EPS);

    float4 gg = ((const float4*)gamma)[lane];
    float4 be = ((const float4*)beta)[lane];
    float y0 = fmaxf(d0 * rstd * gg.x + be.x, 0.f);
    float y1 = fmaxf(d1 * rstd * gg.y + be.y, 0.f);
    float y2 = fmaxf(d2 * rstd * gg.z + be.z, 0.f);
    float y3 = fmaxf(d3 * rstd * gg.w + be.w, 0.f);

    ((float4*)out)[warp * 32 + lane] = make_float4(y0, y1, y2, y3);
}

// ---------------- final gather ----------------
__global__ void gather_out_kernel(const float* __restrict__ feats,
                                  const int* __restrict__ bnn,
                                  float* __restrict__ out)
{
    __shared__ int sidx;
    int g = blockIdx.x;
    if (threadIdx.x == 0) {
        int p = 0;
        for (int i = 0; i < g; i++) p += bnn[i];
        sidx = p;
    }
    __syncthreads();
    out[g * RK + threadIdx.x] = feats[sidx * RK + threadIdx.x];
}

// ---------------- launch ----------------
extern "C" void kernel_launch(void* const* d_in, const int* in_sizes, int n_in,
                              void* d_out, int out_size)
{
    const float* features = (const float*)d_in[0];
    const int*   src      = (const int*)d_in[1];
    const int*   dst      = (const int*)d_in[2];
    const int*   bnn      = (const int*)d_in[3];
    const float* Ws       = (const float*)d_in[4];
    const float* bs       = (const float*)d_in[5];
    const float* gammas   = (const float*)d_in[6];
    const float* betas    = (const float*)d_in[7];
    float* out = (float*)d_out;

    static int smem_set = 0;
    if (!smem_set) {
        cudaFuncSetAttribute(gemm_tc_kernel,
                             cudaFuncAttributeMaxDynamicSharedMemorySize, SM_TOTAL);
        smem_set = 1;
    }

    uint2* hbuf;
    float *bufA, *bufB, *bhi, *blo;
    cudaGetSymbolAddress((void**)&hbuf, g_h16);
    cudaGetSymbolAddress((void**)&bufA, g_bufA);
    cudaGetSymbolAddress((void**)&bufB, g_bufB);
    cudaGetSymbolAddress((void**)&bhi, g_Bhi);
    cudaGetSymbolAddress((void**)&blo, g_Blo);
    int *dout_p, *din_p;
    cudaGetSymbolAddress((void**)&dout_p, g_deg_out);
    cudaGetSymbolAddress((void**)&din_p, g_deg_in);

    cudaMemsetAsync(dout_p, 0, NN * sizeof(int));
    cudaMemsetAsync(din_p, 0, (NN + SCAN_CH) * sizeof(int));

    // graph structure + weight prep
    setup_kernel<<<(NE + 255) / 256, 256>>>(src, dst, Ws);
    block_reduce_kernel<<<SCAN_NB, 256>>>();
    block_scan_kernel<<<SCAN_NB, 256>>>();
    scatter_kernel<<<(NE + 255) / 256, 256>>>(src, dst);

    const int spmm_grid = (NN * 32 + 255) / 256;

    const float* in_ptr = features;
    float* outs[ORDER] = {bufA, bufB, bufA};
    for (int i = 0; i < ORDER; i++) {
        gemm_tc_kernel<<<GRID_M, 128, SM_TOTAL>>>(in_ptr,
                                                  bhi + i * RK * RK,
                                                  blo + i * RK * RK, hbuf);
        spmm_ln_kernel<<<spmm_grid, 256>>>(hbuf, bs + i * RK, gammas + i * RK,
                                           betas + i * RK, outs[i]);
        in_ptr = outs[i];
    }

    gather_out_kernel<<<NG, RK>>>(outs[ORDER - 1], bnn, out);
}

// round 9
// speedup vs baseline: 2.1786x; 1.1841x over previous
#include <cuda_runtime.h>
#include <cuda_bf16.h>
#include <cuda_fp16.h>
#include <cstdint>

#define NN 50000
#define NE 640000
#define RK 128
#define NG 50
#define ORDER 3
#define LN_EPS 1e-5f

#define SCAN_CH 1024
#define SCAN_NB ((NN + SCAN_CH - 1) / SCAN_CH)   // 49

// tcgen05 is arch-accelerated: legal only in the compute_103a / sm_103a pass.
#if defined(__CUDA_ARCH__) && (defined(__CUDA_ARCH_FEAT_SM103_ALL) || \
    (defined(__CUDA_ARCH_SPECIFIC__) && (__CUDA_ARCH_SPECIFIC__ == 1030)))
#define HAS_TCGEN05 1
#else
#define HAS_TCGEN05 0
#endif

// ---------------- device scratch (no allocation allowed) ----------------
__device__ uint2 g_h16[NN * 32];   // H in fp16: 32 uint2 (=128 half) per row
__device__ float g_bufA[NN * RK];
__device__ float g_bufB[NN * RK];
__device__ int   g_deg_out[NN];
__device__ int   g_deg_in[NN + SCAN_CH];
__device__ float g_inv_out[NN];
__device__ float g_inv_in[NN];
__device__ int   g_rowptr[NN + 1];
__device__ int   g_cursor[NN];
__device__ int   g_col[NE];
__device__ __align__(16) int g_part[52];   // 49 used + 3 zero pad (int4 loads)
// pre-transposed / fp16 hi-lo split / pre-swizzled W (B[n][k] = W[k][n])
__device__ __align__(16) __half g_Bhi[ORDER][RK * RK];
__device__ __align__(16) __half g_Blo[ORDER][RK * RK];

// ---------------- portable helpers ----------------
__device__ __forceinline__ uint32_t smem_u32(const void* p) {
    uint32_t a;
    asm("{ .reg .u64 t; cvta.to.shared.u64 t, %1; cvt.u32.u64 %0, t; }" : "=r"(a) : "l"(p));
    return a;
}

// blocked SW128 atom layout for a [128 rows x 128 half cols] tile:
// atom = 8 rows x 64 halves (128B); atom_offset = (row>>3) + (col>>6)*16
__device__ __forceinline__ uint32_t tile_off_f16(int row, int col) {
    uint32_t boff = (uint32_t)((row >> 3) + (col >> 6) * 16) * 1024u
                  + (uint32_t)(row & 7) * 128u + (uint32_t)(col & 63) * 2u;
    return boff ^ ((boff >> 3) & 0x70);
}

// ---------------- sm_103a-only PTX wrappers ----------------
#if HAS_TCGEN05

#define TC_ALLOC(saddr, n) \
    asm volatile("tcgen05.alloc.cta_group::1.sync.aligned.shared::cta.b32 [%0], %1;" \
                 :: "r"((uint32_t)(saddr)), "r"((uint32_t)(n)) : "memory")
#define TC_DEALLOC(t, n) \
    asm volatile("tcgen05.dealloc.cta_group::1.sync.aligned.b32 %0, %1;" :: "r"(t), "r"((uint32_t)(n)))
#define TC_RELINQ() \
    asm volatile("tcgen05.relinquish_alloc_permit.cta_group::1.sync.aligned;")
#define TC_COMMIT(mbar) \
    asm volatile("tcgen05.commit.cta_group::1.mbarrier::arrive::one.shared::cluster.b64 [%0];" \
                 :: "r"((uint32_t)(mbar)) : "memory")
#define TC_FENCE_AFTER()  asm volatile("tcgen05.fence::after_thread_sync;" ::: "memory")
#define TC_FENCE_BEFORE() asm volatile("tcgen05.fence::before_thread_sync;" ::: "memory")
#define TC_WAIT_LD()      asm volatile("tcgen05.wait::ld.sync.aligned;" ::: "memory")

#define MBAR_INIT(mbar, cnt) \
    asm volatile("mbarrier.init.shared.b64 [%0], %1;" :: "r"((uint32_t)(mbar)), "r"((uint32_t)(cnt)) : "memory")
#define MBAR_WAIT(mbar, ph) do { \
    uint32_t _m = (uint32_t)(mbar); uint32_t _p = (uint32_t)(ph); uint32_t _d; \
    asm volatile("{\n\t.reg .pred p;\n\t" \
        "mbarrier.try_wait.parity.acquire.cta.shared::cta.b64 p, [%1], %2;\n\t" \
        "selp.b32 %0, 1, 0, p;\n\t}" : "=r"(_d) : "r"(_m), "r"(_p) : "memory"); \
    if (!_d) { \
        asm volatile("{\n\t.reg .pred P1;\n\t" \
            "WL_%=:\n\t" \
            "mbarrier.try_wait.parity.acquire.cta.shared::cta.b64 P1, [%0], %1, 0x989680;\n\t" \
            "@P1 bra.uni WD_%=;\n\t" \
            "bra.uni WL_%=;\n\t" \
            "WD_%=:\n\t}" :: "r"(_m), "r"(_p) : "memory"); \
    } \
} while (0)

#define LDTM_X32(r, t) \
    asm volatile("tcgen05.ld.sync.aligned.32x32b.x32.b32 " \
        "{%0, %1, %2, %3, %4, %5, %6, %7, %8, %9, %10, %11, %12, %13, %14, %15, " \
        " %16, %17, %18, %19, %20, %21, %22, %23, %24, %25, %26, %27, %28, %29, %30, %31}, [%32];" \
        : "=r"((r)[0]),  "=r"((r)[1]),  "=r"((r)[2]),  "=r"((r)[3]), \
          "=r"((r)[4]),  "=r"((r)[5]),  "=r"((r)[6]),  "=r"((r)[7]), \
          "=r"((r)[8]),  "=r"((r)[9]),  "=r"((r)[10]), "=r"((r)[11]), \
          "=r"((r)[12]), "=r"((r)[13]), "=r"((r)[14]), "=r"((r)[15]), \
          "=r"((r)[16]), "=r"((r)[17]), "=r"((r)[18]), "=r"((r)[19]), \
          "=r"((r)[20]), "=r"((r)[21]), "=r"((r)[22]), "=r"((r)[23]), \
          "=r"((r)[24]), "=r"((r)[25]), "=r"((r)[26]), "=r"((r)[27]), \
          "=r"((r)[28]), "=r"((r)[29]), "=r"((r)[30]), "=r"((r)[31]) \
        : "r"(t))

static constexpr uint64_t DESC_BASE_SW128 =
    (uint64_t(2) << 61) | (uint64_t(1) << 46) | (uint64_t(64) << 32) | (uint64_t(1) << 16);
__device__ __forceinline__ uint64_t make_desc(uint32_t addr) {
    return DESC_BASE_SW128 | ((uint64_t)(addr >> 4) & 0x3FFF);
}

// idesc kind::f16: dtype=F32(1<<4), atype=F16(0), btype=F16(0), N=128, M=128
static constexpr uint32_t IDESC_F16 =
    (1u << 4) | (16u << 17) | (8u << 24);   // 0x8200010

__device__ __forceinline__ void mma_f16_ss(uint32_t d, uint64_t a, uint64_t b,
                                           bool acc) {
    uint32_t en = acc ? 1u : 0u;
    asm volatile(
        "{\n\t.reg .pred p;\n\tsetp.ne.u32 p, %5, 0;\n\t"
        "tcgen05.mma.cta_group::1.kind::f16 [%0], %1, %2, %3, {%4, %4, %4, %4}, p;\n\t}"
        :: "r"(d), "l"(a), "l"(b), "r"(IDESC_F16), "r"(0u), "r"(en) : "memory");
}

#endif // HAS_TCGEN05

// ---------------- setup: degrees (4 edges/thread) + W fp16-split prep ----------------
__global__ void __launch_bounds__(256) setup_kernel(
    const int* __restrict__ src, const int* __restrict__ dst,
    const float* __restrict__ Ws)
{
    int i = blockIdx.x * 256 + threadIdx.x;
    if (i < NE / 4) {
        int4 s4 = ((const int4*)src)[i];
        int4 d4 = ((const int4*)dst)[i];
        atomicAdd(&g_deg_out[s4.x], 1);
        atomicAdd(&g_deg_out[s4.y], 1);
        atomicAdd(&g_deg_out[s4.z], 1);
        atomicAdd(&g_deg_out[s4.w], 1);
        atomicAdd(&g_deg_in[d4.x], 1);
        atomicAdd(&g_deg_in[d4.y], 1);
        atomicAdd(&g_deg_in[d4.z], 1);
        atomicAdd(&g_deg_in[d4.w], 1);
    }
    if (i < ORDER * RK * RK) {
        int layer = i >> 14;
        int rem = i & 16383;
        int k = rem >> 7;
        int n = rem & 127;
        float w = Ws[layer * RK * RK + k * RK + n];
        __half whi = __float2half_rn(w);
        __half wlo = __float2half_rn(w - __half2float(whi));
        uint32_t off2 = tile_off_f16(n, k) >> 1;   // B[n][k]
        g_Bhi[layer][off2] = whi;
        g_Blo[layer][off2] = wlo;
    }
    if (i < 3) g_part[49 + i] = 0;   // pad for int4 scan loads
}

// phase 1: per-1024-chunk sums of deg_in
__global__ void __launch_bounds__(256) block_reduce_kernel() {
    const int b = blockIdx.x;
    const int tid = threadIdx.x;
    const int4* di4 = (const int4*)g_deg_in;
    int4 v = di4[b * 256 + tid];
    int s = v.x + v.y + v.z + v.w;
    #pragma unroll
    for (int o = 16; o > 0; o >>= 1) s += __shfl_xor_sync(0xFFFFFFFFu, s, o);
    __shared__ int ws[8];
    if ((tid & 31) == 0) ws[tid >> 5] = s;
    __syncthreads();
    if (tid < 8) {
        int t = ws[tid];
        #pragma unroll
        for (int o = 4; o > 0; o >>= 1) t += __shfl_xor_sync(0xFFu, t, o);
        if (tid == 0) g_part[b] = t;
    }
}

// phase 2 (fused): chunk offset from g_part via warp scan; per-chunk scan
__global__ void __launch_bounds__(256) block_scan_kernel() {
    const int b = blockIdx.x;
    const int tid = threadIdx.x;
    const int base = b * SCAN_CH + tid * 4;

    __shared__ int s_off;
    if (tid < 32) {
        int4 p = (tid < 13) ? ((const int4*)g_part)[tid] : make_int4(0, 0, 0, 0);
        int i0 = tid * 4;
        int off = ((i0 + 0) < b ? p.x : 0) + ((i0 + 1) < b ? p.y : 0)
                + ((i0 + 2) < b ? p.z : 0) + ((i0 + 3) < b ? p.w : 0);
        int tot = p.x + p.y + p.z + p.w;
        #pragma unroll
        for (int o = 16; o > 0; o >>= 1) {
            off += __shfl_xor_sync(0xFFFFFFFFu, off, o);
            tot += __shfl_xor_sync(0xFFFFFFFFu, tot, o);
        }
        if (tid == 0) {
            s_off = off;
            if (b == 0) g_rowptr[NN] = tot;
        }
    }

    const int4* di4 = (const int4*)g_deg_in;
    int4 v = di4[b * 256 + tid];
    int tsum = v.x + v.y + v.z + v.w;

    __shared__ int sc[256];
    sc[tid] = tsum;
    __syncthreads();
    #pragma unroll
    for (int o = 1; o < 256; o <<= 1) {
        int t = (tid >= o) ? sc[tid - o] : 0;
        __syncthreads();
        sc[tid] += t;
        __syncthreads();
    }
    int run = s_off + ((tid == 0) ? 0 : sc[tid - 1]);

    int r0 = run;
    int r1 = r0 + v.x;
    int r2 = r1 + v.y;
    int r3 = r2 + v.z;

    if (base + 0 < NN) { g_rowptr[base+0] = r0; g_cursor[base+0] = r0; }
    if (base + 1 < NN) { g_rowptr[base+1] = r1; g_cursor[base+1] = r1; }
    if (base + 2 < NN) { g_rowptr[base+2] = r2; g_cursor[base+2] = r2; }
    if (base + 3 < NN) { g_rowptr[base+3] = r3; g_cursor[base+3] = r3; }

    #pragma unroll
    for (int j = 0; j < 4; j++) {
        int idx = base + j;
        if (idx < NN) {
            int din = (j == 0) ? v.x : (j == 1) ? v.y : (j == 2) ? v.z : v.w;
            g_inv_in[idx]  = rsqrtf(fmaxf((float)din, 1.0f));
            g_inv_out[idx] = rsqrtf(fmaxf((float)g_deg_out[idx], 1.0f));
        }
    }
}

// 4 edges/thread CSR bucket scatter
__global__ void __launch_bounds__(256) scatter_kernel(
    const int* __restrict__ src, const int* __restrict__ dst)
{
    int i = blockIdx.x * 256 + threadIdx.x;
    if (i < NE / 4) {
        int4 s4 = ((const int4*)src)[i];
        int4 d4 = ((const int4*)dst)[i];
        int p0 = atomicAdd(&g_cursor[d4.x], 1);
        int p1 = atomicAdd(&g_cursor[d4.y], 1);
        int p2 = atomicAdd(&g_cursor[d4.z], 1);
        int p3 = atomicAdd(&g_cursor[d4.w], 1);
        g_col[p0] = s4.x;
        g_col[p1] = s4.y;
        g_col[p2] = s4.z;
        g_col[p3] = s4.w;
    }
}

// ---------------- tcgen05 GEMM (fp16 hi/lo 3-pass): H16 = fp16(inv_out * XW) ----------------
#define SM_META 0
#define SM_MBAR 8
#define SM_XHI  1024
#define SM_XLO  (SM_XHI + 32768)
#define SM_BHI  (SM_XLO + 32768)
#define SM_BLO  (SM_BHI + 32768)
#define SM_TOTAL (SM_BLO + 32768)   // 132 KB
#define TMEM_COLS 128
#define GRID_M ((NN + 127) / 128)

__global__ void __launch_bounds__(128, 1) gemm_tc_kernel(
    const float* __restrict__ X,
    const __half* __restrict__ Bhi, const __half* __restrict__ Blo,
    uint2* __restrict__ H)
{
#if HAS_TCGEN05
    extern __shared__ char smem[];
    const uint32_t sbase = smem_u32(smem);
    const int tid = threadIdx.x;
    const int wid = tid >> 5;
    const int lane = tid & 31;
    const int row0 = blockIdx.x * 128;

    if (wid == 0) TC_ALLOC(sbase + SM_META, TMEM_COLS);
    if (tid == 0) MBAR_INIT(sbase + SM_MBAR, 1);

    // copy pre-swizzled B (32KB each buf)
    {
        const uint4* bh = (const uint4*)Bhi;
        const uint4* bl = (const uint4*)Blo;
        uint4* dh = (uint4*)(smem + SM_BHI);
        uint4* dl = (uint4*)(smem + SM_BLO);
        #pragma unroll
        for (int i = 0; i < 16; i++) {
            dh[tid + i * 128] = bh[tid + i * 128];
            dl[tid + i * 128] = bl[tid + i * 128];
        }
    }

    // load + fp16-split X tile [128 x 128] into swizzled blocked layout
    const float4* X4 = (const float4*)X;
    #pragma unroll
    for (int i = 0; i < 32; i++) {
        int idx = tid + i * 128;
        int r = idx >> 5, c4 = idx & 31;
        float4 v = make_float4(0.f, 0.f, 0.f, 0.f);
        if (row0 + r < NN) v = X4[(row0 + r) * 32 + c4];
        __half2 h01 = __float22half2_rn(make_float2(v.x, v.y));
        __half2 h23 = __float22half2_rn(make_float2(v.z, v.w));
        float2 b01 = __half22float2(h01);
        float2 b23 = __half22float2(h23);
        __half2 l01 = __float22half2_rn(make_float2(v.x - b01.x, v.y - b01.y));
        __half2 l23 = __float22half2_rn(make_float2(v.z - b23.x, v.w - b23.y));
        uint2 uhi, ulo;
        uhi.x = *reinterpret_cast<uint32_t*>(&h01);
        uhi.y = *reinterpret_cast<uint32_t*>(&h23);
        ulo.x = *reinterpret_cast<uint32_t*>(&l01);
        ulo.y = *reinterpret_cast<uint32_t*>(&l23);
        uint32_t off = tile_off_f16(r, c4 * 4);
        *(uint2*)(smem + SM_XHI + off) = uhi;
        *(uint2*)(smem + SM_XLO + off) = ulo;
    }

    __syncthreads();
    uint32_t tmem;
    asm volatile("ld.shared.b32 %0, [%1];" : "=r"(tmem) : "r"(sbase + SM_META));

    if (tid == 0) {
        TC_FENCE_AFTER();
        const uint64_t a_hi = make_desc(sbase + SM_XHI);
        const uint64_t a_lo = make_desc(sbase + SM_XLO);
        const uint64_t b_hi = make_desc(sbase + SM_BHI);
        const uint64_t b_lo = make_desc(sbase + SM_BLO);
        // K-step offsets (16B units): 4 steps in atom-col 0, 4 in atom-col 1
        #pragma unroll
        for (int p = 0; p < 3; p++) {
            uint64_t ab = (p == 1) ? a_lo : a_hi;
            uint64_t bb = (p == 2) ? b_lo : b_hi;
            #pragma unroll
            for (int s = 0; s < 8; s++) {
                uint64_t off = (uint64_t)((s >> 2) * 1024 + (s & 3) * 2);
                mma_f16_ss(tmem, ab + off, bb + off, !(p == 0 && s == 0));
            }
        }
        TC_COMMIT(sbase + SM_MBAR);
    }
    MBAR_WAIT(sbase + SM_MBAR, 0);
    TC_FENCE_AFTER();

    // epilogue: scale by inv_out, convert fp16, store (32 uint2 per row)
    int row = row0 + wid * 32 + lane;
    float s = (row < NN) ? g_inv_out[row] : 0.f;
    #pragma unroll
    for (int base = 0; base < 128; base += 32) {
        uint32_t r[32];
        LDTM_X32(r, tmem + base);
        TC_WAIT_LD();
        if (row < NN) {
            #pragma unroll
            for (int j = 0; j < 8; j++) {
                float2 p0 = make_float2(__uint_as_float(r[j*4+0]) * s,
                                        __uint_as_float(r[j*4+1]) * s);
                float2 p1 = make_float2(__uint_as_float(r[j*4+2]) * s,
                                        __uint_as_float(r[j*4+3]) * s);
                __half2 h0 = __float22half2_rn(p0);
                __half2 h1 = __float22half2_rn(p1);
                uint2 u;
                u.x = *reinterpret_cast<uint32_t*>(&h0);
                u.y = *reinterpret_cast<uint32_t*>(&h1);
                H[row * 32 + (base >> 2) + j] = u;
            }
        }
    }

    TC_FENCE_BEFORE();
    __syncthreads();
    if (wid == 0) {
        TC_RELINQ();
        TC_DEALLOC(tmem, TMEM_COLS);
    }
#else
    // Portable-PTX fallback target (compute_103): never executed on GB300.
    (void)X; (void)Bhi; (void)Blo; (void)H;
#endif
}

// ---------------- SpMM(fp16 in, fp32 accum) + inv_in + bias + LN + ReLU ----------------
__global__ void __launch_bounds__(256) spmm_ln_kernel(
    const uint2* __restrict__ H,
    const float* __restrict__ b, const float* __restrict__ gamma,
    const float* __restrict__ beta, float* __restrict__ out)
{
    int warp = (blockIdx.x * blockDim.x + threadIdx.x) >> 5;
    int lane = threadIdx.x & 31;
    if (warp >= NN) return;

    int beg = g_rowptr[warp];
    int end = g_rowptr[warp + 1];

    float4 acc = make_float4(0.f, 0.f, 0.f, 0.f);
    int e = beg;
    for (; e + 3 < end; e += 4) {
        int s0 = g_col[e], s1 = g_col[e+1], s2 = g_col[e+2], s3 = g_col[e+3];
        uint2 v0 = H[s0 * 32 + lane];
        uint2 v1 = H[s1 * 32 + lane];
        uint2 v2 = H[s2 * 32 + lane];
        uint2 v3 = H[s3 * 32 + lane];
        #pragma unroll
        for (int q = 0; q < 4; q++) {
            uint2 v = (q == 0) ? v0 : (q == 1) ? v1 : (q == 2) ? v2 : v3;
            float2 a0 = __half22float2(*reinterpret_cast<__half2*>(&v.x));
            float2 a1 = __half22float2(*reinterpret_cast<__half2*>(&v.y));
            acc.x += a0.x; acc.y += a0.y; acc.z += a1.x; acc.w += a1.y;
        }
    }
    for (; e < end; e++) {
        uint2 v = H[g_col[e] * 32 + lane];
        float2 a0 = __half22float2(*reinterpret_cast<__half2*>(&v.x));
        float2 a1 = __half22float2(*reinterpret_cast<__half2*>(&v.y));
        acc.x += a0.x; acc.y += a0.y; acc.z += a1.x; acc.w += a1.y;
    }

    float sc = g_inv_in[warp];
    float4 bb = ((const float4*)b)[lane];
    float x0 = acc.x * sc + bb.x;
    float x1 = acc.y * sc + bb.y;
    float x2 = acc.z * sc + bb.z;
    float x3 = acc.w * sc + bb.w;

    float s = x0 + x1 + x2 + x3;
    #pragma unroll
    for (int o = 16; o > 0; o >>= 1) s += __shfl_xor_sync(0xFFFFFFFFu, s, o);
    float mu = s * (1.0f / RK);

    float d0 = x0 - mu, d1 = x1 - mu, d2 = x2 - mu, d3 = x3 - mu;
    float v = d0*d0 + d1*d1 + d2*d2 + d3*d3;
    #pragma unroll
    for (int o = 16; o > 0; o >>= 1) v += __shfl_xor_sync(0xFFFFFFFFu, v, o);
    float rstd = rsqrtf(v * (1.0f / RK) + LN_EPS);

    float4 gg = ((const float4*)gamma)[lane];
    float4 be = ((const float4*)beta)[lane];
    float y0 = fmaxf(d0 * rstd * gg.x + be.x, 0.f);
    float y1 = fmaxf(d1 * rstd * gg.y + be.y, 0.f);
    float y2 = fmaxf(d2 * rstd * gg.z + be.z, 0.f);
    float y3 = fmaxf(d3 * rstd * gg.w + be.w, 0.f);

    ((float4*)out)[warp * 32 + lane] = make_float4(y0, y1, y2, y3);
}

// ---------------- final gather ----------------
__global__ void gather_out_kernel(const float* __restrict__ feats,
                                  const int* __restrict__ bnn,
                                  float* __restrict__ out)
{
    __shared__ int sidx;
    int g = blockIdx.x;
    if (threadIdx.x == 0) {
        int p = 0;
        for (int i = 0; i < g; i++) p += bnn[i];
        sidx = p;
    }
    __syncthreads();
    out[g * RK + threadIdx.x] = feats[sidx * RK + threadIdx.x];
}

// ---------------- launch ----------------
extern "C" void kernel_launch(void* const* d_in, const int* in_sizes, int n_in,
                              void* d_out, int out_size)
{
    const float* features = (const float*)d_in[0];
    const int*   src      = (const int*)d_in[1];
    const int*   dst      = (const int*)d_in[2];
    const int*   bnn      = (const int*)d_in[3];
    const float* Ws       = (const float*)d_in[4];
    const float* bs       = (const float*)d_in[5];
    const float* gammas   = (const float*)d_in[6];
    const float* betas    = (const float*)d_in[7];
    float* out = (float*)d_out;

    cudaFuncSetAttribute(gemm_tc_kernel,
                         cudaFuncAttributeMaxDynamicSharedMemorySize, SM_TOTAL);

    uint2* hbuf;
    float *bufA, *bufB;
    __half *bhi, *blo;
    cudaGetSymbolAddress((void**)&hbuf, g_h16);
    cudaGetSymbolAddress((void**)&bufA, g_bufA);
    cudaGetSymbolAddress((void**)&bufB, g_bufB);
    cudaGetSymbolAddress((void**)&bhi, g_Bhi);
    cudaGetSymbolAddress((void**)&blo, g_Blo);
    int *dout_p, *din_p;
    cudaGetSymbolAddress((void**)&dout_p, g_deg_out);
    cudaGetSymbolAddress((void**)&din_p, g_deg_in);

    cudaMemsetAsync(dout_p, 0, NN * sizeof(int));
    cudaMemsetAsync(din_p, 0, (NN + SCAN_CH) * sizeof(int));

    const int e4_grid = (NE / 4 + 255) / 256;   // 625 (covers W prep: 49152 < 160000)
    setup_kernel<<<e4_grid, 256>>>(src, dst, Ws);
    block_reduce_kernel<<<SCAN_NB, 256>>>();
    block_scan_kernel<<<SCAN_NB, 256>>>();
    scatter_kernel<<<e4_grid, 256>>>(src, dst);

    const int spmm_grid = (NN * 32 + 255) / 256;

    const float* in_ptr = features;
    float* outs[ORDER] = {bufA, bufB, bufA};
    for (int i = 0; i < ORDER; i++) {
        gemm_tc_kernel<<<GRID_M, 128, SM_TOTAL>>>(in_ptr,
                                                  bhi + i * RK * RK,
                                                  blo + i * RK * RK, hbuf);
        spmm_ln_kernel<<<spmm_grid, 256>>>(hbuf, bs + i * RK, gammas + i * RK,
                                           betas + i * RK, outs[i]);
        in_ptr = outs[i];
    }

    gather_out_kernel<<<NG, RK>>>(outs[ORDER - 1], bnn, out);
}

// round 11
// speedup vs baseline: 3.3920x; 1.5570x over previous
#include <cuda_runtime.h>
#include <cuda_bf16.h>
#include <cuda_fp16.h>
#include <cstdint>

#define NN 50000
#define NE 640000
#define RK 128
#define NG 50
#define ORDER 3
#define LN_EPS 1e-5f

#define SCAN_CH 1024
#define SCAN_NB ((NN + SCAN_CH - 1) / SCAN_CH)   // 49

// tcgen05 is arch-accelerated: legal only in the compute_103a / sm_103a pass.
#if defined(__CUDA_ARCH__) && (defined(__CUDA_ARCH_FEAT_SM103_ALL) || \
    (defined(__CUDA_ARCH_SPECIFIC__) && (__CUDA_ARCH_SPECIFIC__ == 1030)))
#define HAS_TCGEN05 1
#else
#define HAS_TCGEN05 0
#endif

// ---------------- device scratch (no allocation allowed) ----------------
__device__ __align__(16) uint2 g_h16[NN * 32];   // H (fp16) for current layer
__device__ __align__(16) float g_bufA[NN * RK];  // X1 compact (F1 rows)
__device__ __align__(16) float g_bufB[NN * RK];  // X2 compact (F2 rows)
__device__ int   g_deg_out[NN];
__device__ int   g_deg_in[NN + SCAN_CH];
__device__ float g_inv_out[NN];
__device__ float g_inv_in[NN];
__device__ int   g_rowptr[NN + 1];
__device__ int   g_cursor[NN];
__device__ int   g_col[NE];
__device__ __align__(16) int g_part[52];
// frontier machinery
__device__ int   g_map1[NN];     // node -> compact row in F1 (or -1)
__device__ int   g_map2[NN];     // node -> compact row in F2 (or -1)
__device__ int   g_list1[NN];
__device__ int   g_list2[NN];
__device__ unsigned char g_need[NN];    // dst needs its in-edges in CSR
__device__ unsigned char g_flag3[NN];   // node is one of the 50 finals
__device__ int   g_first[NG];
__device__ int   g_cnt[2];       // [0]=|F1|, [1]=|F2|
// pre-transposed / fp16 hi-lo split / pre-swizzled W (B[n][k] = W[k][n])
__device__ __align__(16) __half g_Bhi[ORDER][RK * RK];
__device__ __align__(16) __half g_Blo[ORDER][RK * RK];

// ---------------- portable helpers ----------------
__device__ __forceinline__ uint32_t smem_u32(const void* p) {
    uint32_t a;
    asm("{ .reg .u64 t; cvta.to.shared.u64 t, %1; cvt.u32.u64 %0, t; }" : "=r"(a) : "l"(p));
    return a;
}

// blocked SW128 atom layout for a [128 rows x 128 half cols] tile
__device__ __forceinline__ uint32_t tile_off_f16(int row, int col) {
    uint32_t boff = (uint32_t)((row >> 3) + (col >> 6) * 16) * 1024u
                  + (uint32_t)(row & 7) * 128u + (uint32_t)(col & 63) * 2u;
    return boff ^ ((boff >> 3) & 0x70);
}

// ---------------- sm_103a-only PTX wrappers ----------------
#if HAS_TCGEN05

#define TC_ALLOC(saddr, n) \
    asm volatile("tcgen05.alloc.cta_group::1.sync.aligned.shared::cta.b32 [%0], %1;" \
                 :: "r"((uint32_t)(saddr)), "r"((uint32_t)(n)) : "memory")
#define TC_DEALLOC(t, n) \
    asm volatile("tcgen05.dealloc.cta_group::1.sync.aligned.b32 %0, %1;" :: "r"(t), "r"((uint32_t)(n)))
#define TC_RELINQ() \
    asm volatile("tcgen05.relinquish_alloc_permit.cta_group::1.sync.aligned;")
#define TC_COMMIT(mbar) \
    asm volatile("tcgen05.commit.cta_group::1.mbarrier::arrive::one.shared::cluster.b64 [%0];" \
                 :: "r"((uint32_t)(mbar)) : "memory")
#define TC_FENCE_AFTER()  asm volatile("tcgen05.fence::after_thread_sync;" ::: "memory")
#define TC_FENCE_BEFORE() asm volatile("tcgen05.fence::before_thread_sync;" ::: "memory")
#define TC_WAIT_LD()      asm volatile("tcgen05.wait::ld.sync.aligned;" ::: "memory")

#define MBAR_INIT(mbar, cnt) \
    asm volatile("mbarrier.init.shared.b64 [%0], %1;" :: "r"((uint32_t)(mbar)), "r"((uint32_t)(cnt)) : "memory")
#define MBAR_WAIT(mbar, ph) do { \
    uint32_t _m = (uint32_t)(mbar); uint32_t _p = (uint32_t)(ph); uint32_t _d; \
    asm volatile("{\n\t.reg .pred p;\n\t" \
        "mbarrier.try_wait.parity.acquire.cta.shared::cta.b64 p, [%1], %2;\n\t" \
        "selp.b32 %0, 1, 0, p;\n\t}" : "=r"(_d) : "r"(_m), "r"(_p) : "memory"); \
    if (!_d) { \
        asm volatile("{\n\t.reg .pred P1;\n\t" \
            "WL_%=:\n\t" \
            "mbarrier.try_wait.parity.acquire.cta.shared::cta.b64 P1, [%0], %1, 0x989680;\n\t" \
            "@P1 bra.uni WD_%=;\n\t" \
            "bra.uni WL_%=;\n\t" \
            "WD_%=:\n\t}" :: "r"(_m), "r"(_p) : "memory"); \
    } \
} while (0)

#define LDTM_X32(r, t) \
    asm volatile("tcgen05.ld.sync.aligned.32x32b.x32.b32 " \
        "{%0, %1, %2, %3, %4, %5, %6, %7, %8, %9, %10, %11, %12, %13, %14, %15, " \
        " %16, %17, %18, %19, %20, %21, %22, %23, %24, %25, %26, %27, %28, %29, %30, %31}, [%32];" \
        : "=r"((r)[0]),  "=r"((r)[1]),  "=r"((r)[2]),  "=r"((r)[3]), \
          "=r"((r)[4]),  "=r"((r)[5]),  "=r"((r)[6]),  "=r"((r)[7]), \
          "=r"((r)[8]),  "=r"((r)[9]),  "=r"((r)[10]), "=r"((r)[11]), \
          "=r"((r)[12]), "=r"((r)[13]), "=r"((r)[14]), "=r"((r)[15]), \
          "=r"((r)[16]), "=r"((r)[17]), "=r"((r)[18]), "=r"((r)[19]), \
          "=r"((r)[20]), "=r"((r)[21]), "=r"((r)[22]), "=r"((r)[23]), \
          "=r"((r)[24]), "=r"((r)[25]), "=r"((r)[26]), "=r"((r)[27]), \
          "=r"((r)[28]), "=r"((r)[29]), "=r"((r)[30]), "=r"((r)[31]) \
        : "r"(t))

static constexpr uint64_t DESC_BASE_SW128 =
    (uint64_t(2) << 61) | (uint64_t(1) << 46) | (uint64_t(64) << 32) | (uint64_t(1) << 16);
__device__ __forceinline__ uint64_t make_desc(uint32_t addr) {
    return DESC_BASE_SW128 | ((uint64_t)(addr >> 4) & 0x3FFF);
}

// idesc kind::f16: dtype=F32(1<<4), atype=F16(0), btype=F16(0), N=128, M=128
static constexpr uint32_t IDESC_F16 =
    (1u << 4) | (16u << 17) | (8u << 24);

__device__ __forceinline__ void mma_f16_ss(uint32_t d, uint64_t a, uint64_t b,
                                           bool acc) {
    uint32_t en = acc ? 1u : 0u;
    asm volatile(
        "{\n\t.reg .pred p;\n\tsetp.ne.u32 p, %5, 0;\n\t"
        "tcgen05.mma.cta_group::1.kind::f16 [%0], %1, %2, %3, {%4, %4, %4, %4}, p;\n\t}"
        :: "r"(d), "l"(a), "l"(b), "r"(IDESC_F16), "r"(0u), "r"(en) : "memory");
}

#endif // HAS_TCGEN05

// ---------------- setup: degrees + W fp16-split prep + F3 marking ----------------
__global__ void __launch_bounds__(256) setup_kernel(
    const int* __restrict__ src, const int* __restrict__ dst,
    const float* __restrict__ Ws, const int* __restrict__ bnn)
{
    int i = blockIdx.x * 256 + threadIdx.x;
    if (i < NE / 4) {
        int4 s4 = ((const int4*)src)[i];
        int4 d4 = ((const int4*)dst)[i];
        atomicAdd(&g_deg_out[s4.x], 1);
        atomicAdd(&g_deg_out[s4.y], 1);
        atomicAdd(&g_deg_out[s4.z], 1);
        atomicAdd(&g_deg_out[s4.w], 1);
        atomicAdd(&g_deg_in[d4.x], 1);
        atomicAdd(&g_deg_in[d4.y], 1);
        atomicAdd(&g_deg_in[d4.z], 1);
        atomicAdd(&g_deg_in[d4.w], 1);
    }
    if (i < ORDER * RK * RK) {
        int layer = i >> 14;
        int rem = i & 16383;
        int k = rem >> 7;
        int n = rem & 127;
        float w = Ws[layer * RK * RK + k * RK + n];
        __half whi = __float2half_rn(w);
        __half wlo = __float2half_rn(w - __half2float(whi));
        uint32_t off2 = tile_off_f16(n, k) >> 1;
        g_Bhi[layer][off2] = whi;
        g_Blo[layer][off2] = wlo;
    }
    if (i < 3) g_part[49 + i] = 0;
    if (blockIdx.x == 0 && threadIdx.x == 0) {
        int run = 0;
        #pragma unroll 1
        for (int g = 0; g < NG; g++) {
            g_first[g] = run;
            g_flag3[run] = 1;
            g_need[run] = 1;
            run += bnn[g];
        }
    }
}

// frontier pass: F2 = unique srcs of edges into F3 (the 50 finals)
__global__ void __launch_bounds__(256) pass_f2_kernel(
    const int* __restrict__ src, const int* __restrict__ dst)
{
    int i = blockIdx.x * 256 + threadIdx.x;
    if (i >= NE / 4) return;
    int4 s4 = ((const int4*)src)[i];
    int4 d4 = ((const int4*)dst)[i];
    #pragma unroll
    for (int q = 0; q < 4; q++) {
        int d = (q == 0) ? d4.x : (q == 1) ? d4.y : (q == 2) ? d4.z : d4.w;
        int s = (q == 0) ? s4.x : (q == 1) ? s4.y : (q == 2) ? s4.z : s4.w;
        if (g_flag3[d]) {
            if (atomicCAS(&g_map2[s], -1, -2) == -1) {
                int idx = atomicAdd(&g_cnt[1], 1);
                g_list2[idx] = s;
                g_map2[s] = idx;     // read only by later kernels
                g_need[s] = 1;
            }
        }
    }
}

// frontier pass: F1 = unique srcs of edges into F2
__global__ void __launch_bounds__(256) pass_f1_kernel(
    const int* __restrict__ src, const int* __restrict__ dst)
{
    int i = blockIdx.x * 256 + threadIdx.x;
    if (i >= NE / 4) return;
    int4 s4 = ((const int4*)src)[i];
    int4 d4 = ((const int4*)dst)[i];
    #pragma unroll
    for (int q = 0; q < 4; q++) {
        int d = (q == 0) ? d4.x : (q == 1) ? d4.y : (q == 2) ? d4.z : d4.w;
        int s = (q == 0) ? s4.x : (q == 1) ? s4.y : (q == 2) ? s4.z : s4.w;
        if (g_map2[d] != -1) {
            if (atomicCAS(&g_map1[s], -1, -2) == -1) {
                int idx = atomicAdd(&g_cnt[0], 1);
                g_list1[idx] = s;
                g_map1[s] = idx;
                g_need[s] = 1;
            }
        }
    }
}

// phase 1: per-1024-chunk sums of deg_in
__global__ void __launch_bounds__(256) block_reduce_kernel() {
    const int b = blockIdx.x;
    const int tid = threadIdx.x;
    const int4* di4 = (const int4*)g_deg_in;
    int4 v = di4[b * 256 + tid];
    int s = v.x + v.y + v.z + v.w;
    #pragma unroll
    for (int o = 16; o > 0; o >>= 1) s += __shfl_xor_sync(0xFFFFFFFFu, s, o);
    __shared__ int ws[8];
    if ((tid & 31) == 0) ws[tid >> 5] = s;
    __syncthreads();
    if (tid < 8) {
        int t = ws[tid];
        #pragma unroll
        for (int o = 4; o > 0; o >>= 1) t += __shfl_xor_sync(0xFFu, t, o);
        if (tid == 0) g_part[b] = t;
    }
}

// phase 2: fused partial-scan + per-chunk scan + rowptr/cursor/inv
__global__ void __launch_bounds__(256) block_scan_kernel() {
    const int b = blockIdx.x;
    const int tid = threadIdx.x;
    const int base = b * SCAN_CH + tid * 4;

    __shared__ int s_off;
    if (tid < 32) {
        int4 p = (tid < 13) ? ((const int4*)g_part)[tid] : make_int4(0, 0, 0, 0);
        int i0 = tid * 4;
        int off = ((i0 + 0) < b ? p.x : 0) + ((i0 + 1) < b ? p.y : 0)
                + ((i0 + 2) < b ? p.z : 0) + ((i0 + 3) < b ? p.w : 0);
        #pragma unroll
        for (int o = 16; o > 0; o >>= 1)
            off += __shfl_xor_sync(0xFFFFFFFFu, off, o);
        if (tid == 0) s_off = off;
    }

    const int4* di4 = (const int4*)g_deg_in;
    int4 v = di4[b * 256 + tid];
    int tsum = v.x + v.y + v.z + v.w;

    __shared__ int sc[256];
    sc[tid] = tsum;
    __syncthreads();
    #pragma unroll
    for (int o = 1; o < 256; o <<= 1) {
        int t = (tid >= o) ? sc[tid - o] : 0;
        __syncthreads();
        sc[tid] += t;
        __syncthreads();
    }
    int run = s_off + ((tid == 0) ? 0 : sc[tid - 1]);

    int r0 = run;
    int r1 = r0 + v.x;
    int r2 = r1 + v.y;
    int r3 = r2 + v.z;

    if (base + 0 < NN) { g_rowptr[base+0] = r0; g_cursor[base+0] = r0; }
    if (base + 1 < NN) { g_rowptr[base+1] = r1; g_cursor[base+1] = r1; }
    if (base + 2 < NN) { g_rowptr[base+2] = r2; g_cursor[base+2] = r2; }
    if (base + 3 < NN) { g_rowptr[base+3] = r3; g_cursor[base+3] = r3; }

    #pragma unroll
    for (int j = 0; j < 4; j++) {
        int idx = base + j;
        if (idx < NN) {
            int din = (j == 0) ? v.x : (j == 1) ? v.y : (j == 2) ? v.z : v.w;
            g_inv_in[idx]  = rsqrtf(fmaxf((float)din, 1.0f));
            g_inv_out[idx] = rsqrtf(fmaxf((float)g_deg_out[idx], 1.0f));
        }
    }
}

// filtered CSR scatter: only edges whose dst needs its in-edge list
__global__ void __launch_bounds__(256) scatter_kernel(
    const int* __restrict__ src, const int* __restrict__ dst)
{
    int i = blockIdx.x * 256 + threadIdx.x;
    if (i >= NE / 4) return;
    int4 s4 = ((const int4*)src)[i];
    int4 d4 = ((const int4*)dst)[i];
    #pragma unroll
    for (int q = 0; q < 4; q++) {
        int d = (q == 0) ? d4.x : (q == 1) ? d4.y : (q == 2) ? d4.z : d4.w;
        int s = (q == 0) ? s4.x : (q == 1) ? s4.y : (q == 2) ? s4.z : s4.w;
        if (g_need[d]) {
            int p = atomicAdd(&g_cursor[d], 1);
            g_col[p] = s;
        }
    }
}

// ---------------- tcgen05 GEMM (fp16 hi/lo 3-pass) ----------------
#define SM_META 0
#define SM_MBAR 8
#define SM_XHI  1024
#define SM_XLO  (SM_XHI + 32768)
#define SM_BHI  (SM_XLO + 32768)
#define SM_BLO  (SM_BHI + 32768)
#define SM_TOTAL (SM_BLO + 32768)   // 132 KB
#define TMEM_COLS 128
#define GRID_M ((NN + 127) / 128)

__global__ void __launch_bounds__(128, 1) gemm_tc_kernel(
    const float* __restrict__ X,
    const __half* __restrict__ Bhi, const __half* __restrict__ Blo,
    uint2* __restrict__ H,
    const int* __restrict__ nodelist, const int* __restrict__ cntp)
{
#if HAS_TCGEN05
    const int n = cntp ? *cntp : NN;
    const int row0 = blockIdx.x * 128;
    if (row0 >= n) return;

    extern __shared__ char smem[];
    const uint32_t sbase = smem_u32(smem);
    const int tid = threadIdx.x;
    const int wid = tid >> 5;
    const int lane = tid & 31;

    if (wid == 0) TC_ALLOC(sbase + SM_META, TMEM_COLS);
    if (tid == 0) MBAR_INIT(sbase + SM_MBAR, 1);

    {
        const uint4* bh = (const uint4*)Bhi;
        const uint4* bl = (const uint4*)Blo;
        uint4* dh = (uint4*)(smem + SM_BHI);
        uint4* dl = (uint4*)(smem + SM_BLO);
        #pragma unroll
        for (int i = 0; i < 16; i++) {
            dh[tid + i * 128] = bh[tid + i * 128];
            dl[tid + i * 128] = bl[tid + i * 128];
        }
    }

    const float4* X4 = (const float4*)X;
    #pragma unroll
    for (int i = 0; i < 32; i++) {
        int idx = tid + i * 128;
        int r = idx >> 5, c4 = idx & 31;
        float4 v = make_float4(0.f, 0.f, 0.f, 0.f);
        if (row0 + r < n) v = X4[(row0 + r) * 32 + c4];
        __half2 h01 = __float22half2_rn(make_float2(v.x, v.y));
        __half2 h23 = __float22half2_rn(make_float2(v.z, v.w));
        float2 b01 = __half22float2(h01);
        float2 b23 = __half22float2(h23);
        __half2 l01 = __float22half2_rn(make_float2(v.x - b01.x, v.y - b01.y));
        __half2 l23 = __float22half2_rn(make_float2(v.z - b23.x, v.w - b23.y));
        uint2 uhi, ulo;
        uhi.x = *reinterpret_cast<uint32_t*>(&h01);
        uhi.y = *reinterpret_cast<uint32_t*>(&h23);
        ulo.x = *reinterpret_cast<uint32_t*>(&l01);
        ulo.y = *reinterpret_cast<uint32_t*>(&l23);
        uint32_t off = tile_off_f16(r, c4 * 4);
        *(uint2*)(smem + SM_XHI + off) = uhi;
        *(uint2*)(smem + SM_XLO + off) = ulo;
    }

    __syncthreads();
    uint32_t tmem;
    asm volatile("ld.shared.b32 %0, [%1];" : "=r"(tmem) : "r"(sbase + SM_META));

    if (tid == 0) {
        TC_FENCE_AFTER();
        const uint64_t a_hi = make_desc(sbase + SM_XHI);
        const uint64_t a_lo = make_desc(sbase + SM_XLO);
        const uint64_t b_hi = make_desc(sbase + SM_BHI);
        const uint64_t b_lo = make_desc(sbase + SM_BLO);
        #pragma unroll
        for (int p = 0; p < 3; p++) {
            uint64_t ab = (p == 1) ? a_lo : a_hi;
            uint64_t bb = (p == 2) ? b_lo : b_hi;
            #pragma unroll
            for (int s = 0; s < 8; s++) {
                uint64_t off = (uint64_t)((s >> 2) * 1024 + (s & 3) * 2);
                mma_f16_ss(tmem, ab + off, bb + off, !(p == 0 && s == 0));
            }
        }
        TC_COMMIT(sbase + SM_MBAR);
    }
    MBAR_WAIT(sbase + SM_MBAR, 0);
    TC_FENCE_AFTER();

    int row = row0 + wid * 32 + lane;
    float s = 0.f;
    if (row < n) {
        int node = nodelist ? nodelist[row] : row;
        s = g_inv_out[node];
    }
    #pragma unroll
    for (int base = 0; base < 128; base += 32) {
        uint32_t r[32];
        LDTM_X32(r, tmem + base);
        TC_WAIT_LD();
        if (row < n) {
            #pragma unroll
            for (int j = 0; j < 8; j++) {
                float2 p0 = make_float2(__uint_as_float(r[j*4+0]) * s,
                                        __uint_as_float(r[j*4+1]) * s);
                float2 p1 = make_float2(__uint_as_float(r[j*4+2]) * s,
                                        __uint_as_float(r[j*4+3]) * s);
                __half2 h0 = __float22half2_rn(p0);
                __half2 h1 = __float22half2_rn(p1);
                uint2 u;
                u.x = *reinterpret_cast<uint32_t*>(&h0);
                u.y = *reinterpret_cast<uint32_t*>(&h1);
                H[row * 32 + (base >> 2) + j] = u;
            }
        }
    }

    TC_FENCE_BEFORE();
    __syncthreads();
    if (wid == 0) {
        TC_RELINQ();
        TC_DEALLOC(tmem, TMEM_COLS);
    }
#else
    (void)X; (void)Bhi; (void)Blo; (void)H; (void)nodelist; (void)cntp;
#endif
}

// ---------------- SpMM + inv_in + bias + LN + ReLU (3 modes) ----------------
// MODE 0: dst=list1[w], w<cnt[0], H indexed by raw src, out row w
// MODE 1: dst=list2[w], w<cnt[1], H indexed by map1[src], out row w
// MODE 2: dst=first[w], w<NG,     H indexed by map2[src], out row w (d_out)
template<int MODE>
__global__ void __launch_bounds__(256) spmm_ln_t(
    const uint2* __restrict__ H,
    const float* __restrict__ b, const float* __restrict__ gamma,
    const float* __restrict__ beta, float4* __restrict__ out)
{
    int w = (blockIdx.x * blockDim.x + threadIdx.x) >> 5;
    int lane = threadIdx.x & 31;

    int n_dst = (MODE == 0) ? g_cnt[0] : (MODE == 1) ? g_cnt[1] : NG;
    if (w >= n_dst) return;
    int dst = (MODE == 0) ? g_list1[w] : (MODE == 1) ? g_list2[w] : g_first[w];

    int beg = g_rowptr[dst];
    int end = g_rowptr[dst + 1];

    float4 acc = make_float4(0.f, 0.f, 0.f, 0.f);
    int e = beg;
    for (; e + 3 < end; e += 4) {
        int s0 = g_col[e], s1 = g_col[e+1], s2 = g_col[e+2], s3 = g_col[e+3];
        if (MODE == 1) { s0 = g_map1[s0]; s1 = g_map1[s1]; s2 = g_map1[s2]; s3 = g_map1[s3]; }
        if (MODE == 2) { s0 = g_map2[s0]; s1 = g_map2[s1]; s2 = g_map2[s2]; s3 = g_map2[s3]; }
        uint2 v0 = H[s0 * 32 + lane];
        uint2 v1 = H[s1 * 32 + lane];
        uint2 v2 = H[s2 * 32 + lane];
        uint2 v3 = H[s3 * 32 + lane];
        #pragma unroll
        for (int q = 0; q < 4; q++) {
            uint2 v = (q == 0) ? v0 : (q == 1) ? v1 : (q == 2) ? v2 : v3;
            float2 a0 = __half22float2(*reinterpret_cast<__half2*>(&v.x));
            float2 a1 = __half22float2(*reinterpret_cast<__half2*>(&v.y));
            acc.x += a0.x; acc.y += a0.y; acc.z += a1.x; acc.w += a1.y;
        }
    }
    for (; e < end; e++) {
        int s0 = g_col[e];
        if (MODE == 1) s0 = g_map1[s0];
        if (MODE == 2) s0 = g_map2[s0];
        uint2 v = H[s0 * 32 + lane];
        float2 a0 = __half22float2(*reinterpret_cast<__half2*>(&v.x));
        float2 a1 = __half22float2(*reinterpret_cast<__half2*>(&v.y));
        acc.x += a0.x; acc.y += a0.y; acc.z += a1.x; acc.w += a1.y;
    }

    float sc = g_inv_in[dst];
    float4 bb = ((const float4*)b)[lane];
    float x0 = acc.x * sc + bb.x;
    float x1 = acc.y * sc + bb.y;
    float x2 = acc.z * sc + bb.z;
    float x3 = acc.w * sc + bb.w;

    float s = x0 + x1 + x2 + x3;
    #pragma unroll
    for (int o = 16; o > 0; o >>= 1) s += __shfl_xor_sync(0xFFFFFFFFu, s, o);
    float mu = s * (1.0f / RK);

    float d0 = x0 - mu, d1 = x1 - mu, d2 = x2 - mu, d3 = x3 - mu;
    float v = d0*d0 + d1*d1 + d2*d2 + d3*d3;
    #pragma unroll
    for (int o = 16; o > 0; o >>= 1) v += __shfl_xor_sync(0xFFFFFFFFu, v, o);
    float rstd = rsqrtf(v * (1.0f / RK) + LN_EPS);

    float4 gg = ((const float4*)gamma)[lane];
    float4 be = ((const float4*)beta)[lane];
    float y0 = fmaxf(d0 * rstd * gg.x + be.x, 0.f);
    float y1 = fmaxf(d1 * rstd * gg.y + be.y, 0.f);
    float y2 = fmaxf(d2 * rstd * gg.z + be.z, 0.f);
    float y3 = fmaxf(d3 * rstd * gg.w + be.w, 0.f);

    out[w * 32 + lane] = make_float4(y0, y1, y2, y3);
}

// ---------------- launch ----------------
extern "C" void kernel_launch(void* const* d_in, const int* in_sizes, int n_in,
                              void* d_out, int out_size)
{
    const float* features = (const float*)d_in[0];
    const int*   src      = (const int*)d_in[1];
    const int*   dst      = (const int*)d_in[2];
    const int*   bnn      = (const int*)d_in[3];
    const float* Ws       = (const float*)d_in[4];
    const float* bs       = (const float*)d_in[5];
    const float* gammas   = (const float*)d_in[6];
    const float* betas    = (const float*)d_in[7];
    float* out = (float*)d_out;

    cudaFuncSetAttribute(gemm_tc_kernel,
                         cudaFuncAttributeMaxDynamicSharedMemorySize, SM_TOTAL);

    uint2* hbuf;
    float *bufA, *bufB;
    __half *bhi, *blo;
    int *map1_p, *map2_p, *cnt_p, *dout_p, *din_p, *list1_p, *list2_p;
    unsigned char *need_p, *flag3_p;
    cudaGetSymbolAddress((void**)&hbuf, g_h16);
    cudaGetSymbolAddress((void**)&bufA, g_bufA);
    cudaGetSymbolAddress((void**)&bufB, g_bufB);
    cudaGetSymbolAddress((void**)&bhi, g_Bhi);
    cudaGetSymbolAddress((void**)&blo, g_Blo);
    cudaGetSymbolAddress((void**)&map1_p, g_map1);
    cudaGetSymbolAddress((void**)&map2_p, g_map2);
    cudaGetSymbolAddress((void**)&cnt_p, g_cnt);
    cudaGetSymbolAddress((void**)&dout_p, g_deg_out);
    cudaGetSymbolAddress((void**)&din_p, g_deg_in);
    cudaGetSymbolAddress((void**)&list1_p, g_list1);
    cudaGetSymbolAddress((void**)&list2_p, g_list2);
    cudaGetSymbolAddress((void**)&need_p, g_need);
    cudaGetSymbolAddress((void**)&flag3_p, g_flag3);

    cudaMemsetAsync(dout_p, 0, NN * sizeof(int));
    cudaMemsetAsync(din_p, 0, (NN + SCAN_CH) * sizeof(int));
    cudaMemsetAsync(map1_p, 0xFF, NN * sizeof(int));   // -1
    cudaMemsetAsync(map2_p, 0xFF, NN * sizeof(int));   // -1
    cudaMemsetAsync(need_p, 0, NN);
    cudaMemsetAsync(flag3_p, 0, NN);
    cudaMemsetAsync(cnt_p, 0, 2 * sizeof(int));

    const int e4_grid = (NE / 4 + 255) / 256;   // 625

    setup_kernel<<<e4_grid, 256>>>(src, dst, Ws, bnn);
    pass_f2_kernel<<<e4_grid, 256>>>(src, dst);
    pass_f1_kernel<<<e4_grid, 256>>>(src, dst);
    block_reduce_kernel<<<SCAN_NB, 256>>>();
    block_scan_kernel<<<SCAN_NB, 256>>>();
    scatter_kernel<<<e4_grid, 256>>>(src, dst);

    const int spmm_grid_full = (NN * 32 + 255) / 256;   // 6250, early-exit
    const int spmm_grid_out  = (NG * 32 + 255) / 256;   // 7

    // layer 0: full GEMM over all nodes, SpMM over F1 -> compact X1 (bufA)
    gemm_tc_kernel<<<GRID_M, 128, SM_TOTAL>>>(features, bhi, blo, hbuf,
                                              nullptr, nullptr);
    spmm_ln_t<0><<<spmm_grid_full, 256>>>(hbuf, bs, gammas, betas,
                                          (float4*)bufA);
    // layer 1: compact GEMM over F1 rows, SpMM over F2 -> compact X2 (bufB)
    gemm_tc_kernel<<<GRID_M, 128, SM_TOTAL>>>(bufA, bhi + RK * RK,
                                              blo + RK * RK, hbuf,
                                              list1_p, cnt_p + 0);
    spmm_ln_t<1><<<spmm_grid_full, 256>>>(hbuf, bs + RK, gammas + RK,
                                          betas + RK, (float4*)bufB);
    // layer 2: compact GEMM over F2 rows, SpMM over the 50 finals -> d_out
    gemm_tc_kernel<<<GRID_M, 128, SM_TOTAL>>>(bufB, bhi + 2 * RK * RK,
                                              blo + 2 * RK * RK, hbuf,
                                              list2_p, cnt_p + 1);
    spmm_ln_t<2><<<spmm_grid_out, 256>>>(hbuf, bs + 2 * RK, gammas + 2 * RK,
                                         betas + 2 * RK, (float4*)out);
}

// round 14
// speedup vs baseline: 3.6708x; 1.0822x over previous
#include <cuda_runtime.h>
#include <cuda_bf16.h>
#include <cuda_fp16.h>
#include <cstdint>
#include <cstddef>

#define NN 50000
#define NE 640000
#define RK 128
#define NG 50
#define ORDER 3
#define LN_EPS 1e-5f

#define SCAN_CH 1024
#define SCAN_NB ((NN + SCAN_CH - 1) / SCAN_CH)   // 49

// tcgen05 is arch-accelerated: legal only in the compute_103a / sm_103a pass.
#if defined(__CUDA_ARCH__) && (defined(__CUDA_ARCH_FEAT_SM103_ALL) || \
    (defined(__CUDA_ARCH_SPECIFIC__) && (__CUDA_ARCH_SPECIFIC__ == 1030)))
#define HAS_TCGEN05 1
#else
#define HAS_TCGEN05 0
#endif

// ---------------- device scratch (no allocation allowed) ----------------
// zero-initialized block: ONE memset covers all of it
struct __align__(16) ZBlk {
    int deg_in[NN + SCAN_CH];   // padded so int4 loads never OOB
    int deg_out[NN];
    int cnt[2];                 // [0]=|F1|, [1]=|F2|
    unsigned char need[NN];     // dst needs its in-edges in CSR
    unsigned char flag3[NN];    // node is one of the 50 finals
};
__device__ ZBlk g_z;
// 0xFF-initialized block: ONE memset
struct __align__(16) MBlk {
    int map1[NN];               // node -> compact row in F1 (or -1)
    int map2[NN];               // node -> compact row in F2 (or -1)
};
__device__ MBlk g_m;

__device__ __align__(16) float g_h[NN * RK];     // H (fp32) for current layer
__device__ __align__(16) float g_bufA[NN * RK];  // X1 compact (F1 rows)
__device__ __align__(16) float g_bufB[NN * RK];  // X2 compact (F2 rows)
__device__ float g_inv_out[NN];
__device__ float g_inv_in[NN];
__device__ int   g_rowptr[NN + 1];
__device__ int   g_cursor[NN];
__device__ int   g_col[NE];
__device__ __align__(16) int g_part[52];
__device__ int   g_list1[NN];
__device__ int   g_list2[NN];
__device__ int   g_first[NG];
// pre-transposed / fp16 hi-lo split / pre-swizzled W (B[n][k] = W[k][n])
__device__ __align__(16) __half g_Bhi[ORDER][RK * RK];
__device__ __align__(16) __half g_Blo[ORDER][RK * RK];

// ---------------- portable helpers ----------------
__device__ __forceinline__ uint32_t smem_u32(const void* p) {
    uint32_t a;
    asm("{ .reg .u64 t; cvta.to.shared.u64 t, %1; cvt.u32.u64 %0, t; }" : "=r"(a) : "l"(p));
    return a;
}

// blocked SW128 atom layout for a [128 rows x 128 half cols] tile
__device__ __forceinline__ uint32_t tile_off_f16(int row, int col) {
    uint32_t boff = (uint32_t)((row >> 3) + (col >> 6) * 16) * 1024u
                  + (uint32_t)(row & 7) * 128u + (uint32_t)(col & 63) * 2u;
    return boff ^ ((boff >> 3) & 0x70);
}

// ---------------- sm_103a-only PTX wrappers ----------------
#if HAS_TCGEN05

#define TC_ALLOC(saddr, n) \
    asm volatile("tcgen05.alloc.cta_group::1.sync.aligned.shared::cta.b32 [%0], %1;" \
                 :: "r"((uint32_t)(saddr)), "r"((uint32_t)(n)) : "memory")
#define TC_DEALLOC(t, n) \
    asm volatile("tcgen05.dealloc.cta_group::1.sync.aligned.b32 %0, %1;" :: "r"(t), "r"((uint32_t)(n)))
#define TC_RELINQ() \
    asm volatile("tcgen05.relinquish_alloc_permit.cta_group::1.sync.aligned;")
#define TC_COMMIT(mbar) \
    asm volatile("tcgen05.commit.cta_group::1.mbarrier::arrive::one.shared::cluster.b64 [%0];" \
                 :: "r"((uint32_t)(mbar)) : "memory")
#define TC_FENCE_AFTER()  asm volatile("tcgen05.fence::after_thread_sync;" ::: "memory")
#define TC_FENCE_BEFORE() asm volatile("tcgen05.fence::before_thread_sync;" ::: "memory")
#define TC_WAIT_LD()      asm volatile("tcgen05.wait::ld.sync.aligned;" ::: "memory")

#define MBAR_INIT(mbar, cnt) \
    asm volatile("mbarrier.init.shared.b64 [%0], %1;" :: "r"((uint32_t)(mbar)), "r"((uint32_t)(cnt)) : "memory")
#define MBAR_WAIT(mbar, ph) do { \
    uint32_t _m = (uint32_t)(mbar); uint32_t _p = (uint32_t)(ph); uint32_t _d; \
    asm volatile("{\n\t.reg .pred p;\n\t" \
        "mbarrier.try_wait.parity.acquire.cta.shared::cta.b64 p, [%1], %2;\n\t" \
        "selp.b32 %0, 1, 0, p;\n\t}" : "=r"(_d) : "r"(_m), "r"(_p) : "memory"); \
    if (!_d) { \
        asm volatile("{\n\t.reg .pred P1;\n\t" \
            "WL_%=:\n\t" \
            "mbarrier.try_wait.parity.acquire.cta.shared::cta.b64 P1, [%0], %1, 0x989680;\n\t" \
            "@P1 bra.uni WD_%=;\n\t" \
            "bra.uni WL_%=;\n\t" \
            "WD_%=:\n\t}" :: "r"(_m), "r"(_p) : "memory"); \
    } \
} while (0)

#define LDTM_X32(r, t) \
    asm volatile("tcgen05.ld.sync.aligned.32x32b.x32.b32 " \
        "{%0, %1, %2, %3, %4, %5, %6, %7, %8, %9, %10, %11, %12, %13, %14, %15, " \
        " %16, %17, %18, %19, %20, %21, %22, %23, %24, %25, %26, %27, %28, %29, %30, %31}, [%32];" \
        : "=r"((r)[0]),  "=r"((r)[1]),  "=r"((r)[2]),  "=r"((r)[3]), \
          "=r"((r)[4]),  "=r"((r)[5]),  "=r"((r)[6]),  "=r"((r)[7]), \
          "=r"((r)[8]),  "=r"((r)[9]),  "=r"((r)[10]), "=r"((r)[11]), \
          "=r"((r)[12]), "=r"((r)[13]), "=r"((r)[14]), "=r"((r)[15]), \
          "=r"((r)[16]), "=r"((r)[17]), "=r"((r)[18]), "=r"((r)[19]), \
          "=r"((r)[20]), "=r"((r)[21]), "=r"((r)[22]), "=r"((r)[23]), \
          "=r"((r)[24]), "=r"((r)[25]), "=r"((r)[26]), "=r"((r)[27]), \
          "=r"((r)[28]), "=r"((r)[29]), "=r"((r)[30]), "=r"((r)[31]) \
        : "r"(t))

static constexpr uint64_t DESC_BASE_SW128 =
    (uint64_t(2) << 61) | (uint64_t(1) << 46) | (uint64_t(64) << 32) | (uint64_t(1) << 16);
__device__ __forceinline__ uint64_t make_desc(uint32_t addr) {
    return DESC_BASE_SW128 | ((uint64_t)(addr >> 4) & 0x3FFF);
}

// idesc kind::f16: dtype=F32(1<<4), atype=F16(0), btype=F16(0), N=128, M=128
static constexpr uint32_t IDESC_F16 =
    (1u << 4) | (16u << 17) | (8u << 24);

__device__ __forceinline__ void mma_f16_ss(uint32_t d, uint64_t a, uint64_t b,
                                           bool acc) {
    uint32_t en = acc ? 1u : 0u;
    asm volatile(
        "{\n\t.reg .pred p;\n\tsetp.ne.u32 p, %5, 0;\n\t"
        "tcgen05.mma.cta_group::1.kind::f16 [%0], %1, %2, %3, {%4, %4, %4, %4}, p;\n\t}"
        :: "r"(d), "l"(a), "l"(b), "r"(IDESC_F16), "r"(0u), "r"(en) : "memory");
}

#endif // HAS_TCGEN05

// ---------------- setup: degrees + W fp16-split prep + F3 marking ----------------
__global__ void __launch_bounds__(256) setup_kernel(
    const int* __restrict__ src, const int* __restrict__ dst,
    const float* __restrict__ Ws, const int* __restrict__ bnn)
{
    int i = blockIdx.x * 256 + threadIdx.x;
    if (i < NE / 4) {
        int4 s4 = ((const int4*)src)[i];
        int4 d4 = ((const int4*)dst)[i];
        atomicAdd(&g_z.deg_out[s4.x], 1);
        atomicAdd(&g_z.deg_out[s4.y], 1);
        atomicAdd(&g_z.deg_out[s4.z], 1);
        atomicAdd(&g_z.deg_out[s4.w], 1);
        atomicAdd(&g_z.deg_in[d4.x], 1);
        atomicAdd(&g_z.deg_in[d4.y], 1);
        atomicAdd(&g_z.deg_in[d4.z], 1);
        atomicAdd(&g_z.deg_in[d4.w], 1);
    }
    if (i < ORDER * RK * RK) {
        int layer = i >> 14;
        int rem = i & 16383;
        int k = rem >> 7;
        int n = rem & 127;
        float w = Ws[layer * RK * RK + k * RK + n];
        __half whi = __float2half_rn(w);
        __half wlo = __float2half_rn(w - __half2float(whi));
        uint32_t off2 = tile_off_f16(n, k) >> 1;
        g_Bhi[layer][off2] = whi;
        g_Blo[layer][off2] = wlo;
    }
    if (i < 3) g_part[49 + i] = 0;
    if (blockIdx.x == 0 && threadIdx.x == 0) {
        int run = 0;
        #pragma unroll 1
        for (int g = 0; g < NG; g++) {
            g_first[g] = run;
            g_z.flag3[run] = 1;
            g_z.need[run] = 1;
            run += bnn[g];
        }
    }
}

// frontier pass: F2 = unique srcs of edges into F3 (the 50 finals)
__global__ void __launch_bounds__(256) pass_f2_kernel(
    const int* __restrict__ src, const int* __restrict__ dst)
{
    int i = blockIdx.x * 256 + threadIdx.x;
    if (i >= NE / 4) return;
    int4 s4 = ((const int4*)src)[i];
    int4 d4 = ((const int4*)dst)[i];
    #pragma unroll
    for (int q = 0; q < 4; q++) {
        int d = (q == 0) ? d4.x : (q == 1) ? d4.y : (q == 2) ? d4.z : d4.w;
        int s = (q == 0) ? s4.x : (q == 1) ? s4.y : (q == 2) ? s4.z : s4.w;
        if (g_z.flag3[d]) {
            if (atomicCAS(&g_m.map2[s], -1, -2) == -1) {
                int idx = atomicAdd(&g_z.cnt[1], 1);
                g_list2[idx] = s;
                g_m.map2[s] = idx;
                g_z.need[s] = 1;
            }
        }
    }
}

// frontier pass: F1 = unique srcs of edges into F2; blocks < 49 also do
// the per-1024-chunk deg_in reduction (deg_in is complete after setup)
__global__ void __launch_bounds__(256) pass_f1_kernel(
    const int* __restrict__ src, const int* __restrict__ dst)
{
    const int b = blockIdx.x;
    const int tid = threadIdx.x;

    if (b < SCAN_NB) {
        const int4* di4 = (const int4*)g_z.deg_in;
        int4 v = di4[b * 256 + tid];
        int s = v.x + v.y + v.z + v.w;
        #pragma unroll
        for (int o = 16; o > 0; o >>= 1) s += __shfl_xor_sync(0xFFFFFFFFu, s, o);
        __shared__ int ws[8];
        if ((tid & 31) == 0) ws[tid >> 5] = s;
        __syncthreads();
        if (tid < 8) {
            int t = ws[tid];
            #pragma unroll
            for (int o = 4; o > 0; o >>= 1) t += __shfl_xor_sync(0xFFu, t, o);
            if (tid == 0) g_part[b] = t;
        }
    }

    int i = b * 256 + tid;
    if (i >= NE / 4) return;
    int4 s4 = ((const int4*)src)[i];
    int4 d4 = ((const int4*)dst)[i];
    #pragma unroll
    for (int q = 0; q < 4; q++) {
        int d = (q == 0) ? d4.x : (q == 1) ? d4.y : (q == 2) ? d4.z : d4.w;
        int s = (q == 0) ? s4.x : (q == 1) ? s4.y : (q == 2) ? s4.z : s4.w;
        if (g_m.map2[d] != -1) {
            if (atomicCAS(&g_m.map1[s], -1, -2) == -1) {
                int idx = atomicAdd(&g_z.cnt[0], 1);
                g_list1[idx] = s;
                g_m.map1[s] = idx;
                g_z.need[s] = 1;
            }
        }
    }
}

// fused partial-scan + per-chunk scan + rowptr/cursor/inv
__global__ void __launch_bounds__(256) block_scan_kernel() {
    const int b = blockIdx.x;
    const int tid = threadIdx.x;
    const int base = b * SCAN_CH + tid * 4;

    __shared__ int s_off;
    if (tid < 32) {
        int4 p = (tid < 13) ? ((const int4*)g_part)[tid] : make_int4(0, 0, 0, 0);
        int i0 = tid * 4;
        int off = ((i0 + 0) < b ? p.x : 0) + ((i0 + 1) < b ? p.y : 0)
                + ((i0 + 2) < b ? p.z : 0) + ((i0 + 3) < b ? p.w : 0);
        #pragma unroll
        for (int o = 16; o > 0; o >>= 1)
            off += __shfl_xor_sync(0xFFFFFFFFu, off, o);
        if (tid == 0) s_off = off;
    }

    const int4* di4 = (const int4*)g_z.deg_in;
    int4 v = di4[b * 256 + tid];
    int tsum = v.x + v.y + v.z + v.w;

    __shared__ int sc[256];
    sc[tid] = tsum;
    __syncthreads();
    #pragma unroll
    for (int o = 1; o < 256; o <<= 1) {
        int t = (tid >= o) ? sc[tid - o] : 0;
        __syncthreads();
        sc[tid] += t;
        __syncthreads();
    }
    int run = s_off + ((tid == 0) ? 0 : sc[tid - 1]);

    int r0 = run;
    int r1 = r0 + v.x;
    int r2 = r1 + v.y;
    int r3 = r2 + v.z;

    if (base + 0 < NN) { g_rowptr[base+0] = r0; g_cursor[base+0] = r0; }
    if (base + 1 < NN) { g_rowptr[base+1] = r1; g_cursor[base+1] = r1; }
    if (base + 2 < NN) { g_rowptr[base+2] = r2; g_cursor[base+2] = r2; }
    if (base + 3 < NN) { g_rowptr[base+3] = r3; g_cursor[base+3] = r3; }

    #pragma unroll
    for (int j = 0; j < 4; j++) {
        int idx = base + j;
        if (idx < NN) {
            int din = (j == 0) ? v.x : (j == 1) ? v.y : (j == 2) ? v.z : v.w;
            g_inv_in[idx]  = rsqrtf(fmaxf((float)din, 1.0f));
            g_inv_out[idx] = rsqrtf(fmaxf((float)g_z.deg_out[idx], 1.0f));
        }
    }
}

// filtered CSR scatter: only edges whose dst needs its in-edge list
__global__ void __launch_bounds__(256) scatter_kernel(
    const int* __restrict__ src, const int* __restrict__ dst)
{
    int i = blockIdx.x * 256 + threadIdx.x;
    if (i >= NE / 4) return;
    int4 s4 = ((const int4*)src)[i];
    int4 d4 = ((const int4*)dst)[i];
    #pragma unroll
    for (int q = 0; q < 4; q++) {
        int d = (q == 0) ? d4.x : (q == 1) ? d4.y : (q == 2) ? d4.z : d4.w;
        int s = (q == 0) ? s4.x : (q == 1) ? s4.y : (q == 2) ? s4.z : s4.w;
        if (g_z.need[d]) {
            int p = atomicAdd(&g_cursor[d], 1);
            g_col[p] = s;
        }
    }
}

// ---------------- tcgen05 GEMM (fp16 hi/lo 3-pass), fp32 H output ----------------
#define SM_META 0
#define SM_MBAR 8
#define SM_XHI  1024
#define SM_XLO  (SM_XHI + 32768)
#define SM_BHI  (SM_XLO + 32768)
#define SM_BLO  (SM_BHI + 32768)
#define SM_TOTAL (SM_BLO + 32768)   // 132 KB
#define TMEM_COLS 128
#define GRID_M ((NN + 127) / 128)

__global__ void __launch_bounds__(128, 1) gemm_tc_kernel(
    const float* __restrict__ X,
    const __half* __restrict__ Bhi, const __half* __restrict__ Blo,
    float4* __restrict__ H,
    const int* __restrict__ nodelist, const int* __restrict__ cntp)
{
#if HAS_TCGEN05
    const int n = cntp ? *cntp : NN;
    const int row0 = blockIdx.x * 128;
    if (row0 >= n) return;

    extern __shared__ char smem[];
    const uint32_t sbase = smem_u32(smem);
    const int tid = threadIdx.x;
    const int wid = tid >> 5;
    const int lane = tid & 31;

    if (wid == 0) TC_ALLOC(sbase + SM_META, TMEM_COLS);
    if (tid == 0) MBAR_INIT(sbase + SM_MBAR, 1);

    {
        const uint4* bh = (const uint4*)Bhi;
        const uint4* bl = (const uint4*)Blo;
        uint4* dh = (uint4*)(smem + SM_BHI);
        uint4* dl = (uint4*)(smem + SM_BLO);
        #pragma unroll
        for (int i = 0; i < 16; i++) {
            dh[tid + i * 128] = bh[tid + i * 128];
            dl[tid + i * 128] = bl[tid + i * 128];
        }
    }

    const float4* X4 = (const float4*)X;
    #pragma unroll
    for (int i = 0; i < 32; i++) {
        int idx = tid + i * 128;
        int r = idx >> 5, c4 = idx & 31;
        float4 v = make_float4(0.f, 0.f, 0.f, 0.f);
        if (row0 + r < n) v = X4[(row0 + r) * 32 + c4];
        __half2 h01 = __float22half2_rn(make_float2(v.x, v.y));
        __half2 h23 = __float22half2_rn(make_float2(v.z, v.w));
        float2 b01 = __half22float2(h01);
        float2 b23 = __half22float2(h23);
        __half2 l01 = __float22half2_rn(make_float2(v.x - b01.x, v.y - b01.y));
        __half2 l23 = __float22half2_rn(make_float2(v.z - b23.x, v.w - b23.y));
        uint2 uhi, ulo;
        uhi.x = *reinterpret_cast<uint32_t*>(&h01);
        uhi.y = *reinterpret_cast<uint32_t*>(&h23);
        ulo.x = *reinterpret_cast<uint32_t*>(&l01);
        ulo.y = *reinterpret_cast<uint32_t*>(&l23);
        uint32_t off = tile_off_f16(r, c4 * 4);
        *(uint2*)(smem + SM_XHI + off) = uhi;
        *(uint2*)(smem + SM_XLO + off) = ulo;
    }

    __syncthreads();
    uint32_t tmem;
    asm volatile("ld.shared.b32 %0, [%1];" : "=r"(tmem) : "r"(sbase + SM_META));

    if (tid == 0) {
        TC_FENCE_AFTER();
        const uint64_t a_hi = make_desc(sbase + SM_XHI);
        const uint64_t a_lo = make_desc(sbase + SM_XLO);
        const uint64_t b_hi = make_desc(sbase + SM_BHI);
        const uint64_t b_lo = make_desc(sbase + SM_BLO);
        #pragma unroll
        for (int p = 0; p < 3; p++) {
            uint64_t ab = (p == 1) ? a_lo : a_hi;
            uint64_t bb = (p == 2) ? b_lo : b_hi;
            #pragma unroll
            for (int s = 0; s < 8; s++) {
                uint64_t off = (uint64_t)((s >> 2) * 1024 + (s & 3) * 2);
                mma_f16_ss(tmem, ab + off, bb + off, !(p == 0 && s == 0));
            }
        }
        TC_COMMIT(sbase + SM_MBAR);
    }
    MBAR_WAIT(sbase + SM_MBAR, 0);
    TC_FENCE_AFTER();

    int row = row0 + wid * 32 + lane;
    float s = 0.f;
    if (row < n) {
        int node = nodelist ? nodelist[row] : row;
        s = g_inv_out[node];
    }
    #pragma unroll
    for (int base = 0; base < 128; base += 32) {
        uint32_t r[32];
        LDTM_X32(r, tmem + base);
        TC_WAIT_LD();
        if (row < n) {
            #pragma unroll
            for (int j = 0; j < 8; j++) {
                H[row * 32 + (base >> 2) + j] = make_float4(
                    __uint_as_float(r[j*4+0]) * s,
                    __uint_as_float(r[j*4+1]) * s,
                    __uint_as_float(r[j*4+2]) * s,
                    __uint_as_float(r[j*4+3]) * s);
            }
        }
    }

    TC_FENCE_BEFORE();
    __syncthreads();
    if (wid == 0) {
        TC_RELINQ();
        TC_DEALLOC(tmem, TMEM_COLS);
    }
#else
    (void)X; (void)Bhi; (void)Blo; (void)H; (void)nodelist; (void)cntp;
#endif
}

// ---------------- SpMM(fp32) + inv_in + bias + LN + ReLU (3 modes) ----------------
// MODE 0: dst=list1[w], w<cnt[0], H indexed by raw src, out row w
// MODE 1: dst=list2[w], w<cnt[1], H indexed by map1[src], out row w
// MODE 2: dst=first[w], w<NG,     H indexed by map2[src], out row w (d_out)
template<int MODE>
__global__ void __launch_bounds__(256) spmm_ln_t(
    const float4* __restrict__ H,
    const float* __restrict__ b, const float* __restrict__ gamma,
    const float* __restrict__ beta, float4* __restrict__ out)
{
    int w = (blockIdx.x * blockDim.x + threadIdx.x) >> 5;
    int lane = threadIdx.x & 31;

    int n_dst = (MODE == 0) ? g_z.cnt[0] : (MODE == 1) ? g_z.cnt[1] : NG;
    if (w >= n_dst) return;
    int dst = (MODE == 0) ? g_list1[w] : (MODE == 1) ? g_list2[w] : g_first[w];

    int beg = g_rowptr[dst];
    int end = g_rowptr[dst + 1];

    float4 acc = make_float4(0.f, 0.f, 0.f, 0.f);
    int e = beg;
    for (; e + 3 < end; e += 4) {
        int s0 = g_col[e], s1 = g_col[e+1], s2 = g_col[e+2], s3 = g_col[e+3];
        if (MODE == 1) { s0 = g_m.map1[s0]; s1 = g_m.map1[s1]; s2 = g_m.map1[s2]; s3 = g_m.map1[s3]; }
        if (MODE == 2) { s0 = g_m.map2[s0]; s1 = g_m.map2[s1]; s2 = g_m.map2[s2]; s3 = g_m.map2[s3]; }
        float4 v0 = H[s0 * 32 + lane];
        float4 v1 = H[s1 * 32 + lane];
        float4 v2 = H[s2 * 32 + lane];
        float4 v3 = H[s3 * 32 + lane];
        acc.x += v0.x + v1.x + v2.x + v3.x;
        acc.y += v0.y + v1.y + v2.y + v3.y;
        acc.z += v0.z + v1.z + v2.z + v3.z;
        acc.w += v0.w + v1.w + v2.w + v3.w;
    }
    for (; e < end; e++) {
        int s0 = g_col[e];
        if (MODE == 1) s0 = g_m.map1[s0];
        if (MODE == 2) s0 = g_m.map2[s0];
        float4 v = H[s0 * 32 + lane];
        acc.x += v.x; acc.y += v.y; acc.z += v.z; acc.w += v.w;
    }

    float sc = g_inv_in[dst];
    float4 bb = ((const float4*)b)[lane];
    float x0 = acc.x * sc + bb.x;
    float x1 = acc.y * sc + bb.y;
    float x2 = acc.z * sc + bb.z;
    float x3 = acc.w * sc + bb.w;

    float s = x0 + x1 + x2 + x3;
    #pragma unroll
    for (int o = 16; o > 0; o >>= 1) s += __shfl_xor_sync(0xFFFFFFFFu, s, o);
    float mu = s * (1.0f / RK);

    float d0 = x0 - mu, d1 = x1 - mu, d2 = x2 - mu, d3 = x3 - mu;
    float v = d0*d0 + d1*d1 + d2*d2 + d3*d3;
    #pragma unroll
    for (int o = 16; o > 0; o >>= 1) v += __shfl_xor_sync(0xFFFFFFFFu, v, o);
    float rstd = rsqrtf(v * (1.0f / RK) + LN_EPS);

    float4 gg = ((const float4*)gamma)[lane];
    float4 be = ((const float4*)beta)[lane];
    float y0 = fmaxf(d0 * rstd * gg.x + be.x, 0.f);
    float y1 = fmaxf(d1 * rstd * gg.y + be.y, 0.f);
    float y2 = fmaxf(d2 * rstd * gg.z + be.z, 0.f);
    float y3 = fmaxf(d3 * rstd * gg.w + be.w, 0.f);

    out[w * 32 + lane] = make_float4(y0, y1, y2, y3);
}

// ---------------- launch ----------------
extern "C" void kernel_launch(void* const* d_in, const int* in_sizes, int n_in,
                              void* d_out, int out_size)
{
    const float* features = (const float*)d_in[0];
    const int*   src      = (const int*)d_in[1];
    const int*   dst      = (const int*)d_in[2];
    const int*   bnn      = (const int*)d_in[3];
    const float* Ws       = (const float*)d_in[4];
    const float* bs       = (const float*)d_in[5];
    const float* gammas   = (const float*)d_in[6];
    const float* betas    = (const float*)d_in[7];
    float* out = (float*)d_out;

    cudaFuncSetAttribute(gemm_tc_kernel,
                         cudaFuncAttributeMaxDynamicSharedMemorySize, SM_TOTAL);

    float4* hbuf;
    float *bufA, *bufB;
    __half *bhi, *blo;
    char *zb, *mb;
    int *list1_p, *list2_p;
    cudaGetSymbolAddress((void**)&hbuf, g_h);
    cudaGetSymbolAddress((void**)&bufA, g_bufA);
    cudaGetSymbolAddress((void**)&bufB, g_bufB);
    cudaGetSymbolAddress((void**)&bhi, g_Bhi);
    cudaGetSymbolAddress((void**)&blo, g_Blo);
    cudaGetSymbolAddress((void**)&zb, g_z);
    cudaGetSymbolAddress((void**)&mb, g_m);
    cudaGetSymbolAddress((void**)&list1_p, g_list1);
    cudaGetSymbolAddress((void**)&list2_p, g_list2);
    int* cnt_p = (int*)(zb + offsetof(ZBlk, cnt));

    // TWO memsets cover all per-launch state
    cudaMemsetAsync(zb, 0, sizeof(ZBlk));
    cudaMemsetAsync(mb, 0xFF, sizeof(MBlk));

    const int e4_grid = (NE / 4 + 255) / 256;   // 625

    setup_kernel<<<e4_grid, 256>>>(src, dst, Ws, bnn);
    pass_f2_kernel<<<e4_grid, 256>>>(src, dst);
    pass_f1_kernel<<<e4_grid, 256>>>(src, dst);   // also does chunk reduce
    block_scan_kernel<<<SCAN_NB, 256>>>();
    scatter_kernel<<<e4_grid, 256>>>(src, dst);

    const int spmm_grid_full = (NN * 32 + 255) / 256;   // early-exit on cnt
    const int spmm_grid_out  = (NG * 32 + 255) / 256;

    // layer 0: full GEMM over all nodes, SpMM over F1 -> compact X1 (bufA)
    gemm_tc_kernel<<<GRID_M, 128, SM_TOTAL>>>(features, bhi, blo, hbuf,
                                              nullptr, nullptr);
    spmm_ln_t<0><<<spmm_grid_full, 256>>>(hbuf, bs, gammas, betas,
                                          (float4*)bufA);
    // layer 1: compact GEMM over F1 rows, SpMM over F2 -> compact X2 (bufB)
    gemm_tc_kernel<<<GRID_M, 128, SM_TOTAL>>>(bufA, bhi + RK * RK,
                                              blo + RK * RK, hbuf,
                                              list1_p, cnt_p + 0);
    spmm_ln_t<1><<<spmm_grid_full, 256>>>(hbuf, bs + RK, gammas + RK,
                                          betas + RK, (float4*)bufB);
    // layer 2: compact GEMM over F2 rows, SpMM over the 50 finals -> d_out
    gemm_tc_kernel<<<GRID_M, 128, SM_TOTAL>>>(bufB, bhi + 2 * RK * RK,
                                              blo + 2 * RK * RK, hbuf,
                                              list2_p, cnt_p + 1);
    spmm_ln_t<2><<<spmm_grid_out, 256>>>(hbuf, bs + 2 * RK, gammas + 2 * RK,
                                         betas + 2 * RK, (float4*)out);
}

// round 15
// speedup vs baseline: 3.8392x; 1.0459x over previous
#include <cuda_runtime.h>
#include <cuda_bf16.h>
#include <cuda_fp16.h>
#include <cstdint>
#include <cstddef>

#define NN 50000
#define NE 640000
#define RK 128
#define NG 50
#define ORDER 3
#define LN_EPS 1e-5f

#define SCAN_CH 1024
#define SCAN_NB ((NN + SCAN_CH - 1) / SCAN_CH)   // 49

// tcgen05 is arch-accelerated: legal only in the compute_103a / sm_103a pass.
#if defined(__CUDA_ARCH__) && (defined(__CUDA_ARCH_FEAT_SM103_ALL) || \
    (defined(__CUDA_ARCH_SPECIFIC__) && (__CUDA_ARCH_SPECIFIC__ == 1030)))
#define HAS_TCGEN05 1
#else
#define HAS_TCGEN05 0
#endif

// ---------------- device scratch (no allocation allowed) ----------------
// zero-initialized block: ONE memset covers all of it
struct __align__(16) ZBlk {
    int deg_in[NN + SCAN_CH];   // padded so int4 loads never OOB
    int deg_out[NN];
    int cnt[2];                 // [0]=|F1|, [1]=|F2|
    unsigned char need[NN];     // dst needs its in-edges in CSR
    unsigned char flag3[NN];    // node is one of the 50 finals
};
__device__ ZBlk g_z;
// 0xFF-initialized block: ONE memset
struct __align__(16) MBlk {
    int map1[NN];               // node -> compact row in F1 (or -1)
    int map2[NN];               // node -> compact row in F2 (or -1)
};
__device__ MBlk g_m;

__device__ __align__(16) uint2 g_h16[NN * 32];   // H (fp16): 32 uint2 per row
__device__ __align__(16) float g_bufA[NN * RK];  // X1 compact (F1 rows)
__device__ __align__(16) float g_bufB[NN * RK];  // X2 compact (F2 rows)
__device__ float g_inv_out[NN];
__device__ float g_inv_in[NN];
__device__ int   g_rowptr[NN + 1];
__device__ int   g_cursor[NN];
__device__ int   g_col[NE];
__device__ __align__(16) int g_part[52];
__device__ int   g_list1[NN];
__device__ int   g_list2[NN];
__device__ int   g_first[NG];
// pre-transposed / fp16 hi-lo split / pre-swizzled W (B[n][k] = W[k][n])
__device__ __align__(16) __half g_Bhi[ORDER][RK * RK];
__device__ __align__(16) __half g_Blo[ORDER][RK * RK];

// ---------------- portable helpers ----------------
__device__ __forceinline__ uint32_t smem_u32(const void* p) {
    uint32_t a;
    asm("{ .reg .u64 t; cvta.to.shared.u64 t, %1; cvt.u32.u64 %0, t; }" : "=r"(a) : "l"(p));
    return a;
}

// blocked SW128 atom layout for a [128 rows x 128 half cols] tile
__device__ __forceinline__ uint32_t tile_off_f16(int row, int col) {
    uint32_t boff = (uint32_t)((row >> 3) + (col >> 6) * 16) * 1024u
                  + (uint32_t)(row & 7) * 128u + (uint32_t)(col & 63) * 2u;
    return boff ^ ((boff >> 3) & 0x70);
}

// ---------------- sm_103a-only PTX wrappers ----------------
#if HAS_TCGEN05

#define TC_ALLOC(saddr, n) \
    asm volatile("tcgen05.alloc.cta_group::1.sync.aligned.shared::cta.b32 [%0], %1;" \
                 :: "r"((uint32_t)(saddr)), "r"((uint32_t)(n)) : "memory")
#define TC_DEALLOC(t, n) \
    asm volatile("tcgen05.dealloc.cta_group::1.sync.aligned.b32 %0, %1;" :: "r"(t), "r"((uint32_t)(n)))
#define TC_RELINQ() \
    asm volatile("tcgen05.relinquish_alloc_permit.cta_group::1.sync.aligned;")
#define TC_COMMIT(mbar) \
    asm volatile("tcgen05.commit.cta_group::1.mbarrier::arrive::one.shared::cluster.b64 [%0];" \
                 :: "r"((uint32_t)(mbar)) : "memory")
#define TC_FENCE_AFTER()  asm volatile("tcgen05.fence::after_thread_sync;" ::: "memory")
#define TC_FENCE_BEFORE() asm volatile("tcgen05.fence::before_thread_sync;" ::: "memory")
#define TC_WAIT_LD()      asm volatile("tcgen05.wait::ld.sync.aligned;" ::: "memory")

#define MBAR_INIT(mbar, cnt) \
    asm volatile("mbarrier.init.shared.b64 [%0], %1;" :: "r"((uint32_t)(mbar)), "r"((uint32_t)(cnt)) : "memory")
#define MBAR_WAIT(mbar, ph) do { \
    uint32_t _m = (uint32_t)(mbar); uint32_t _p = (uint32_t)(ph); uint32_t _d; \
    asm volatile("{\n\t.reg .pred p;\n\t" \
        "mbarrier.try_wait.parity.acquire.cta.shared::cta.b64 p, [%1], %2;\n\t" \
        "selp.b32 %0, 1, 0, p;\n\t}" : "=r"(_d) : "r"(_m), "r"(_p) : "memory"); \
    if (!_d) { \
        asm volatile("{\n\t.reg .pred P1;\n\t" \
            "WL_%=:\n\t" \
            "mbarrier.try_wait.parity.acquire.cta.shared::cta.b64 P1, [%0], %1, 0x989680;\n\t" \
            "@P1 bra.uni WD_%=;\n\t" \
            "bra.uni WL_%=;\n\t" \
            "WD_%=:\n\t}" :: "r"(_m), "r"(_p) : "memory"); \
    } \
} while (0)

#define LDTM_X32(r, t) \
    asm volatile("tcgen05.ld.sync.aligned.32x32b.x32.b32 " \
        "{%0, %1, %2, %3, %4, %5, %6, %7, %8, %9, %10, %11, %12, %13, %14, %15, " \
        " %16, %17, %18, %19, %20, %21, %22, %23, %24, %25, %26, %27, %28, %29, %30, %31}, [%32];" \
        : "=r"((r)[0]),  "=r"((r)[1]),  "=r"((r)[2]),  "=r"((r)[3]), \
          "=r"((r)[4]),  "=r"((r)[5]),  "=r"((r)[6]),  "=r"((r)[7]), \
          "=r"((r)[8]),  "=r"((r)[9]),  "=r"((r)[10]), "=r"((r)[11]), \
          "=r"((r)[12]), "=r"((r)[13]), "=r"((r)[14]), "=r"((r)[15]), \
          "=r"((r)[16]), "=r"((r)[17]), "=r"((r)[18]), "=r"((r)[19]), \
          "=r"((r)[20]), "=r"((r)[21]), "=r"((r)[22]), "=r"((r)[23]), \
          "=r"((r)[24]), "=r"((r)[25]), "=r"((r)[26]), "=r"((r)[27]), \
          "=r"((r)[28]), "=r"((r)[29]), "=r"((r)[30]), "=r"((r)[31]) \
        : "r"(t))

static constexpr uint64_t DESC_BASE_SW128 =
    (uint64_t(2) << 61) | (uint64_t(1) << 46) | (uint64_t(64) << 32) | (uint64_t(1) << 16);
__device__ __forceinline__ uint64_t make_desc(uint32_t addr) {
    return DESC_BASE_SW128 | ((uint64_t)(addr >> 4) & 0x3FFF);
}

// idesc kind::f16: dtype=F32(1<<4), atype=F16(0), btype=F16(0), N=128, M=128
static constexpr uint32_t IDESC_F16 =
    (1u << 4) | (16u << 17) | (8u << 24);

__device__ __forceinline__ void mma_f16_ss(uint32_t d, uint64_t a, uint64_t b,
                                           bool acc) {
    uint32_t en = acc ? 1u : 0u;
    asm volatile(
        "{\n\t.reg .pred p;\n\tsetp.ne.u32 p, %5, 0;\n\t"
        "tcgen05.mma.cta_group::1.kind::f16 [%0], %1, %2, %3, {%4, %4, %4, %4}, p;\n\t}"
        :: "r"(d), "l"(a), "l"(b), "r"(IDESC_F16), "r"(0u), "r"(en) : "memory");
}

#endif // HAS_TCGEN05

// ---------------- setup: degrees + W fp16-split prep + F3 marking ----------------
__global__ void __launch_bounds__(256) setup_kernel(
    const int* __restrict__ src, const int* __restrict__ dst,
    const float* __restrict__ Ws, const int* __restrict__ bnn)
{
    int i = blockIdx.x * 256 + threadIdx.x;
    if (i < NE / 4) {
        int4 s4 = ((const int4*)src)[i];
        int4 d4 = ((const int4*)dst)[i];
        atomicAdd(&g_z.deg_out[s4.x], 1);
        atomicAdd(&g_z.deg_out[s4.y], 1);
        atomicAdd(&g_z.deg_out[s4.z], 1);
        atomicAdd(&g_z.deg_out[s4.w], 1);
        atomicAdd(&g_z.deg_in[d4.x], 1);
        atomicAdd(&g_z.deg_in[d4.y], 1);
        atomicAdd(&g_z.deg_in[d4.z], 1);
        atomicAdd(&g_z.deg_in[d4.w], 1);
    }
    if (i < ORDER * RK * RK) {
        int layer = i >> 14;
        int rem = i & 16383;
        int k = rem >> 7;
        int n = rem & 127;
        float w = Ws[layer * RK * RK + k * RK + n];
        __half whi = __float2half_rn(w);
        __half wlo = __float2half_rn(w - __half2float(whi));
        uint32_t off2 = tile_off_f16(n, k) >> 1;
        g_Bhi[layer][off2] = whi;
        g_Blo[layer][off2] = wlo;
    }
    if (i < 3) g_part[49 + i] = 0;
    if (blockIdx.x == 0 && threadIdx.x == 0) {
        g_rowptr[NN] = NE;   // total in-degree == edge count (the round-11 bug fix)
        int run = 0;
        #pragma unroll 1
        for (int g = 0; g < NG; g++) {
            g_first[g] = run;
            g_z.flag3[run] = 1;
            g_z.need[run] = 1;
            run += bnn[g];
        }
    }
}

// frontier pass: F2 = unique srcs of edges into F3 (the 50 finals)
__global__ void __launch_bounds__(256) pass_f2_kernel(
    const int* __restrict__ src, const int* __restrict__ dst)
{
    int i = blockIdx.x * 256 + threadIdx.x;
    if (i >= NE / 4) return;
    int4 s4 = ((const int4*)src)[i];
    int4 d4 = ((const int4*)dst)[i];
    #pragma unroll
    for (int q = 0; q < 4; q++) {
        int d = (q == 0) ? d4.x : (q == 1) ? d4.y : (q == 2) ? d4.z : d4.w;
        int s = (q == 0) ? s4.x : (q == 1) ? s4.y : (q == 2) ? s4.z : s4.w;
        if (g_z.flag3[d]) {
            if (atomicCAS(&g_m.map2[s], -1, -2) == -1) {
                int idx = atomicAdd(&g_z.cnt[1], 1);
                g_list2[idx] = s;
                g_m.map2[s] = idx;
                g_z.need[s] = 1;
            }
        }
    }
}

// frontier pass: F1 = unique srcs of edges into F2; blocks < 49 also do
// the per-1024-chunk deg_in reduction (deg_in is complete after setup)
__global__ void __launch_bounds__(256) pass_f1_kernel(
    const int* __restrict__ src, const int* __restrict__ dst)
{
    const int b = blockIdx.x;
    const int tid = threadIdx.x;

    if (b < SCAN_NB) {
        const int4* di4 = (const int4*)g_z.deg_in;
        int4 v = di4[b * 256 + tid];
        int s = v.x + v.y + v.z + v.w;
        #pragma unroll
        for (int o = 16; o > 0; o >>= 1) s += __shfl_xor_sync(0xFFFFFFFFu, s, o);
        __shared__ int ws[8];
        if ((tid & 31) == 0) ws[tid >> 5] = s;
        __syncthreads();
        if (tid < 8) {
            int t = ws[tid];
            #pragma unroll
            for (int o = 4; o > 0; o >>= 1) t += __shfl_xor_sync(0xFFu, t, o);
            if (tid == 0) g_part[b] = t;
        }
    }

    int i = b * 256 + tid;
    if (i >= NE / 4) return;
    int4 s4 = ((const int4*)src)[i];
    int4 d4 = ((const int4*)dst)[i];
    #pragma unroll
    for (int q = 0; q < 4; q++) {
        int d = (q == 0) ? d4.x : (q == 1) ? d4.y : (q == 2) ? d4.z : d4.w;
        int s = (q == 0) ? s4.x : (q == 1) ? s4.y : (q == 2) ? s4.z : s4.w;
        if (g_m.map2[d] != -1) {
            if (atomicCAS(&g_m.map1[s], -1, -2) == -1) {
                int idx = atomicAdd(&g_z.cnt[0], 1);
                g_list1[idx] = s;
                g_m.map1[s] = idx;
                g_z.need[s] = 1;
            }
        }
    }
}

// fused partial-scan + per-chunk scan + rowptr/cursor/inv
__global__ void __launch_bounds__(256) block_scan_kernel() {
    const int b = blockIdx.x;
    const int tid = threadIdx.x;
    const int base = b * SCAN_CH + tid * 4;

    __shared__ int s_off;
    if (tid < 32) {
        int4 p = (tid < 13) ? ((const int4*)g_part)[tid] : make_int4(0, 0, 0, 0);
        int i0 = tid * 4;
        int off = ((i0 + 0) < b ? p.x : 0) + ((i0 + 1) < b ? p.y : 0)
                + ((i0 + 2) < b ? p.z : 0) + ((i0 + 3) < b ? p.w : 0);
        #pragma unroll
        for (int o = 16; o > 0; o >>= 1)
            off += __shfl_xor_sync(0xFFFFFFFFu, off, o);
        if (tid == 0) s_off = off;
    }

    const int4* di4 = (const int4*)g_z.deg_in;
    int4 v = di4[b * 256 + tid];
    int tsum = v.x + v.y + v.z + v.w;

    __shared__ int sc[256];
    sc[tid] = tsum;
    __syncthreads();
    #pragma unroll
    for (int o = 1; o < 256; o <<= 1) {
        int t = (tid >= o) ? sc[tid - o] : 0;
        __syncthreads();
        sc[tid] += t;
        __syncthreads();
    }
    int run = s_off + ((tid == 0) ? 0 : sc[tid - 1]);

    int r0 = run;
    int r1 = r0 + v.x;
    int r2 = r1 + v.y;
    int r3 = r2 + v.z;

    if (base + 0 < NN) { g_rowptr[base+0] = r0; g_cursor[base+0] = r0; }
    if (base + 1 < NN) { g_rowptr[base+1] = r1; g_cursor[base+1] = r1; }
    if (base + 2 < NN) { g_rowptr[base+2] = r2; g_cursor[base+2] = r2; }
    if (base + 3 < NN) { g_rowptr[base+3] = r3; g_cursor[base+3] = r3; }

    #pragma unroll
    for (int j = 0; j < 4; j++) {
        int idx = base + j;
        if (idx < NN) {
            int din = (j == 0) ? v.x : (j == 1) ? v.y : (j == 2) ? v.z : v.w;
            g_inv_in[idx]  = rsqrtf(fmaxf((float)din, 1.0f));
            g_inv_out[idx] = rsqrtf(fmaxf((float)g_z.deg_out[idx], 1.0f));
        }
    }
}

// filtered CSR scatter: only edges whose dst needs its in-edge list
__global__ void __launch_bounds__(256) scatter_kernel(
    const int* __restrict__ src, const int* __restrict__ dst)
{
    int i = blockIdx.x * 256 + threadIdx.x;
    if (i >= NE / 4) return;
    int4 s4 = ((const int4*)src)[i];
    int4 d4 = ((const int4*)dst)[i];
    #pragma unroll
    for (int q = 0; q < 4; q++) {
        int d = (q == 0) ? d4.x : (q == 1) ? d4.y : (q == 2) ? d4.z : d4.w;
        int s = (q == 0) ? s4.x : (q == 1) ? s4.y : (q == 2) ? s4.z : s4.w;
        if (g_z.need[d]) {
            int p = atomicAdd(&g_cursor[d], 1);
            g_col[p] = s;
        }
    }
}

// ---------------- tcgen05 GEMM (fp16 hi/lo 3-pass), fp16 H output ----------------
#define SM_META 0
#define SM_MBAR 8
#define SM_XHI  1024
#define SM_XLO  (SM_XHI + 32768)
#define SM_BHI  (SM_XLO + 32768)
#define SM_BLO  (SM_BHI + 32768)
#define SM_TOTAL (SM_BLO + 32768)   // 132 KB
#define TMEM_COLS 128
#define GRID_M ((NN + 127) / 128)

__global__ void __launch_bounds__(128, 1) gemm_tc_kernel(
    const float* __restrict__ X,
    const __half* __restrict__ Bhi, const __half* __restrict__ Blo,
    uint2* __restrict__ H,
    const int* __restrict__ nodelist, const int* __restrict__ cntp)
{
#if HAS_TCGEN05
    const int n = cntp ? *cntp : NN;
    const int row0 = blockIdx.x * 128;
    if (row0 >= n) return;

    extern __shared__ char smem[];
    const uint32_t sbase = smem_u32(smem);
    const int tid = threadIdx.x;
    const int wid = tid >> 5;
    const int lane = tid & 31;

    if (wid == 0) TC_ALLOC(sbase + SM_META, TMEM_COLS);
    if (tid == 0) MBAR_INIT(sbase + SM_MBAR, 1);

    {
        const uint4* bh = (const uint4*)Bhi;
        const uint4* bl = (const uint4*)Blo;
        uint4* dh = (uint4*)(smem + SM_BHI);
        uint4* dl = (uint4*)(smem + SM_BLO);
        #pragma unroll
        for (int i = 0; i < 16; i++) {
            dh[tid + i * 128] = bh[tid + i * 128];
            dl[tid + i * 128] = bl[tid + i * 128];
        }
    }

    const float4* X4 = (const float4*)X;
    #pragma unroll
    for (int i = 0; i < 32; i++) {
        int idx = tid + i * 128;
        int r = idx >> 5, c4 = idx & 31;
        float4 v = make_float4(0.f, 0.f, 0.f, 0.f);
        if (row0 + r < n) v = X4[(row0 + r) * 32 + c4];
        __half2 h01 = __float22half2_rn(make_float2(v.x, v.y));
        __half2 h23 = __float22half2_rn(make_float2(v.z, v.w));
        float2 b01 = __half22float2(h01);
        float2 b23 = __half22float2(h23);
        __half2 l01 = __float22half2_rn(make_float2(v.x - b01.x, v.y - b01.y));
        __half2 l23 = __float22half2_rn(make_float2(v.z - b23.x, v.w - b23.y));
        uint2 uhi, ulo;
        uhi.x = *reinterpret_cast<uint32_t*>(&h01);
        uhi.y = *reinterpret_cast<uint32_t*>(&h23);
        ulo.x = *reinterpret_cast<uint32_t*>(&l01);
        ulo.y = *reinterpret_cast<uint32_t*>(&l23);
        uint32_t off = tile_off_f16(r, c4 * 4);
        *(uint2*)(smem + SM_XHI + off) = uhi;
        *(uint2*)(smem + SM_XLO + off) = ulo;
    }

    __syncthreads();
    uint32_t tmem;
    asm volatile("ld.shared.b32 %0, [%1];" : "=r"(tmem) : "r"(sbase + SM_META));

    if (tid == 0) {
        TC_FENCE_AFTER();
        const uint64_t a_hi = make_desc(sbase + SM_XHI);
        const uint64_t a_lo = make_desc(sbase + SM_XLO);
        const uint64_t b_hi = make_desc(sbase + SM_BHI);
        const uint64_t b_lo = make_desc(sbase + SM_BLO);
        #pragma unroll
        for (int p = 0; p < 3; p++) {
            uint64_t ab = (p == 1) ? a_lo : a_hi;
            uint64_t bb = (p == 2) ? b_lo : b_hi;
            #pragma unroll
            for (int s = 0; s < 8; s++) {
                uint64_t off = (uint64_t)((s >> 2) * 1024 + (s & 3) * 2);
                mma_f16_ss(tmem, ab + off, bb + off, !(p == 0 && s == 0));
            }
        }
        TC_COMMIT(sbase + SM_MBAR);
    }
    MBAR_WAIT(sbase + SM_MBAR, 0);
    TC_FENCE_AFTER();

    int row = row0 + wid * 32 + lane;
    float s = 0.f;
    if (row < n) {
        int node = nodelist ? nodelist[row] : row;
        s = g_inv_out[node];
    }
    #pragma unroll
    for (int base = 0; base < 128; base += 32) {
        uint32_t r[32];
        LDTM_X32(r, tmem + base);
        TC_WAIT_LD();
        if (row < n) {
            #pragma unroll
            for (int j = 0; j < 8; j++) {
                float2 p0 = make_float2(__uint_as_float(r[j*4+0]) * s,
                                        __uint_as_float(r[j*4+1]) * s);
                float2 p1 = make_float2(__uint_as_float(r[j*4+2]) * s,
                                        __uint_as_float(r[j*4+3]) * s);
                __half2 h0 = __float22half2_rn(p0);
                __half2 h1 = __float22half2_rn(p1);
                uint2 u;
                u.x = *reinterpret_cast<uint32_t*>(&h0);
                u.y = *reinterpret_cast<uint32_t*>(&h1);
                H[row * 32 + (base >> 2) + j] = u;
            }
        }
    }

    TC_FENCE_BEFORE();
    __syncthreads();
    if (wid == 0) {
        TC_RELINQ();
        TC_DEALLOC(tmem, TMEM_COLS);
    }
#else
    (void)X; (void)Bhi; (void)Blo; (void)H; (void)nodelist; (void)cntp;
#endif
}

// ---------------- SpMM(fp16 in, fp32 accum) + inv_in + bias + LN + ReLU ----------------
// MODE 0: dst=list1[w], w<cnt[0], H indexed by raw src, out row w
// MODE 1: dst=list2[w], w<cnt[1], H indexed by map1[src], out row w
// MODE 2: dst=first[w], w<NG,     H indexed by map2[src], out row w (d_out)
template<int MODE>
__global__ void __launch_bounds__(256) spmm_ln_t(
    const uint2* __restrict__ H,
    const float* __restrict__ b, const float* __restrict__ gamma,
    const float* __restrict__ beta, float4* __restrict__ out)
{
    int w = (blockIdx.x * blockDim.x + threadIdx.x) >> 5;
    int lane = threadIdx.x & 31;

    int n_dst = (MODE == 0) ? g_z.cnt[0] : (MODE == 1) ? g_z.cnt[1] : NG;
    if (w >= n_dst) return;
    int dst = (MODE == 0) ? g_list1[w] : (MODE == 1) ? g_list2[w] : g_first[w];

    int beg = g_rowptr[dst];
    int end = g_rowptr[dst + 1];

    float4 acc = make_float4(0.f, 0.f, 0.f, 0.f);
    int e = beg;
    for (; e + 3 < end; e += 4) {
        int s0 = g_col[e], s1 = g_col[e+1], s2 = g_col[e+2], s3 = g_col[e+3];
        if (MODE == 1) { s0 = g_m.map1[s0]; s1 = g_m.map1[s1]; s2 = g_m.map1[s2]; s3 = g_m.map1[s3]; }
        if (MODE == 2) { s0 = g_m.map2[s0]; s1 = g_m.map2[s1]; s2 = g_m.map2[s2]; s3 = g_m.map2[s3]; }
        uint2 v0 = H[s0 * 32 + lane];
        uint2 v1 = H[s1 * 32 + lane];
        uint2 v2 = H[s2 * 32 + lane];
        uint2 v3 = H[s3 * 32 + lane];
        #pragma unroll
        for (int q = 0; q < 4; q++) {
            uint2 v = (q == 0) ? v0 : (q == 1) ? v1 : (q == 2) ? v2 : v3;
            float2 a0 = __half22float2(*reinterpret_cast<__half2*>(&v.x));
            float2 a1 = __half22float2(*reinterpret_cast<__half2*>(&v.y));
            acc.x += a0.x; acc.y += a0.y; acc.z += a1.x; acc.w += a1.y;
        }
    }
    for (; e < end; e++) {
        int s0 = g_col[e];
        if (MODE == 1) s0 = g_m.map1[s0];
        if (MODE == 2) s0 = g_m.map2[s0];
        uint2 v = H[s0 * 32 + lane];
        float2 a0 = __half22float2(*reinterpret_cast<__half2*>(&v.x));
        float2 a1 = __half22float2(*reinterpret_cast<__half2*>(&v.y));
        acc.x += a0.x; acc.y += a0.y; acc.z += a1.x; acc.w += a1.y;
    }

    float sc = g_inv_in[dst];
    float4 bb = ((const float4*)b)[lane];
    float x0 = acc.x * sc + bb.x;
    float x1 = acc.y * sc + bb.y;
    float x2 = acc.z * sc + bb.z;
    float x3 = acc.w * sc + bb.w;

    float s = x0 + x1 + x2 + x3;
    #pragma unroll
    for (int o = 16; o > 0; o >>= 1) s += __shfl_xor_sync(0xFFFFFFFFu, s, o);
    float mu = s * (1.0f / RK);

    float d0 = x0 - mu, d1 = x1 - mu, d2 = x2 - mu, d3 = x3 - mu;
    float v = d0*d0 + d1*d1 + d2*d2 + d3*d3;
    #pragma unroll
    for (int o = 16; o > 0; o >>= 1) v += __shfl_xor_sync(0xFFFFFFFFu, v, o);
    float rstd = rsqrtf(v * (1.0f / RK) + LN_EPS);

    float4 gg = ((const float4*)gamma)[lane];
    float4 be = ((const float4*)beta)[lane];
    float y0 = fmaxf(d0 * rstd * gg.x + be.x, 0.f);
    float y1 = fmaxf(d1 * rstd * gg.y + be.y, 0.f);
    float y2 = fmaxf(d2 * rstd * gg.z + be.z, 0.f);
    float y3 = fmaxf(d3 * rstd * gg.w + be.w, 0.f);

    out[w * 32 + lane] = make_float4(y0, y1, y2, y3);
}

// ---------------- launch ----------------
extern "C" void kernel_launch(void* const* d_in, const int* in_sizes, int n_in,
                              void* d_out, int out_size)
{
    const float* features = (const float*)d_in[0];
    const int*   src      = (const int*)d_in[1];
    const int*   dst      = (const int*)d_in[2];
    const int*   bnn      = (const int*)d_in[3];
    const float* Ws       = (const float*)d_in[4];
    const float* bs       = (const float*)d_in[5];
    const float* gammas   = (const float*)d_in[6];
    const float* betas    = (const float*)d_in[7];
    float* out = (float*)d_out;

    cudaFuncSetAttribute(gemm_tc_kernel,
                         cudaFuncAttributeMaxDynamicSharedMemorySize, SM_TOTAL);

    uint2* hbuf;
    float *bufA, *bufB;
    __half *bhi, *blo;
    char *zb, *mb;
    int *list1_p, *list2_p;
    cudaGetSymbolAddress((void**)&hbuf, g_h16);
    cudaGetSymbolAddress((void**)&bufA, g_bufA);
    cudaGetSymbolAddress((void**)&bufB, g_bufB);
    cudaGetSymbolAddress((void**)&bhi, g_Bhi);
    cudaGetSymbolAddress((void**)&blo, g_Blo);
    cudaGetSymbolAddress((void**)&zb, g_z);
    cudaGetSymbolAddress((void**)&mb, g_m);
    cudaGetSymbolAddress((void**)&list1_p, g_list1);
    cudaGetSymbolAddress((void**)&list2_p, g_list2);
    int* cnt_p = (int*)(zb + offsetof(ZBlk, cnt));

    // TWO memsets cover all per-launch state
    cudaMemsetAsync(zb, 0, sizeof(ZBlk));
    cudaMemsetAsync(mb, 0xFF, sizeof(MBlk));

    const int e4_grid = (NE / 4 + 255) / 256;   // 625

    setup_kernel<<<e4_grid, 256>>>(src, dst, Ws, bnn);
    pass_f2_kernel<<<e4_grid, 256>>>(src, dst);
    pass_f1_kernel<<<e4_grid, 256>>>(src, dst);   // also does chunk reduce
    block_scan_kernel<<<SCAN_NB, 256>>>();
    scatter_kernel<<<e4_grid, 256>>>(src, dst);

    const int spmm_grid_full = (NN * 32 + 255) / 256;   // early-exit on cnt
    const int spmm_grid_out  = (NG * 32 + 255) / 256;

    // layer 0: full GEMM over all nodes, SpMM over F1 -> compact X1 (bufA)
    gemm_tc_kernel<<<GRID_M, 128, SM_TOTAL>>>(features, bhi, blo, hbuf,
                                              nullptr, nullptr);
    spmm_ln_t<0><<<spmm_grid_full, 256>>>(hbuf, bs, gammas, betas,
                                          (float4*)bufA);
    // layer 1: compact GEMM over F1 rows, SpMM over F2 -> compact X2 (bufB)
    gemm_tc_kernel<<<GRID_M, 128, SM_TOTAL>>>(bufA, bhi + RK * RK,
                                              blo + RK * RK, hbuf,
                                              list1_p, cnt_p + 0);
    spmm_ln_t<1><<<spmm_grid_full, 256>>>(hbuf, bs + RK, gammas + RK,
                                          betas + RK, (float4*)bufB);
    // layer 2: compact GEMM over F2 rows, SpMM over the 50 finals -> d_out
    gemm_tc_kernel<<<GRID_M, 128, SM_TOTAL>>>(bufB, bhi + 2 * RK * RK,
                                              blo + 2 * RK * RK, hbuf,
                                              list2_p, cnt_p + 1);
    spmm_ln_t<2><<<spmm_grid_out, 256>>>(hbuf, bs + 2 * RK, gammas + 2 * RK,
                                         betas + 2 * RK, (float4*)out);
}

// round 16
// speedup vs baseline: 3.9301x; 1.0237x over previous
#include <cuda_runtime.h>
#include <cuda_bf16.h>
#include <cuda_fp16.h>
#include <cstdint>
#include <cstddef>

#define NN 50000
#define NE 640000
#define RK 128
#define NG 50
#define ORDER 3
#define LN_EPS 1e-5f

#define SCAN_CH 1024
#define SCAN_NB ((NN + SCAN_CH - 1) / SCAN_CH)   // 49

// tcgen05 is arch-accelerated: legal only in the compute_103a / sm_103a pass.
#if defined(__CUDA_ARCH__) && (defined(__CUDA_ARCH_FEAT_SM103_ALL) || \
    (defined(__CUDA_ARCH_SPECIFIC__) && (__CUDA_ARCH_SPECIFIC__ == 1030)))
#define HAS_TCGEN05 1
#else
#define HAS_TCGEN05 0
#endif

// ---------------- device scratch (no allocation allowed) ----------------
// zero-initialized block: ONE memset covers ALL per-launch state.
// map encoding: 0 = unvisited, -1 = claimed (transient), idx+1 = member.
struct __align__(16) ZBlk {
    int deg_in[NN + SCAN_CH];   // padded so int4 loads never OOB
    int deg_out[NN];
    int map1[NN];               // node -> compact row+1 in F1 (0 = none)
    int map2[NN];               // node -> compact row+1 in F2 (0 = none)
    int cnt[2];                 // [0]=|F1|, [1]=|F2|
    unsigned char need[NN];     // dst needs its in-edges in CSR
    unsigned char flag3[NN];    // node is one of the 50 finals
};
__device__ ZBlk g_z;

__device__ __align__(16) uint2 g_h16[NN * 32];   // H (fp16): 32 uint2 per row
__device__ __align__(16) float g_bufA[NN * RK];  // X1 compact (F1 rows)
__device__ __align__(16) float g_bufB[NN * RK];  // X2 compact (F2 rows)
__device__ float g_inv_out[NN];
__device__ float g_inv_in[NN];
__device__ int   g_rowptr[NN + 1];
__device__ int   g_cursor[NN];
__device__ int   g_col[NE];
__device__ __align__(16) int g_part[52];
__device__ int   g_list1[NN];
__device__ int   g_list2[NN];
__device__ int   g_first[NG];
// pre-transposed / fp16 hi-lo split / pre-swizzled W (B[n][k] = W[k][n])
__device__ __align__(16) __half g_Bhi[ORDER][RK * RK];
__device__ __align__(16) __half g_Blo[ORDER][RK * RK];

// ---------------- portable helpers ----------------
__device__ __forceinline__ uint32_t smem_u32(const void* p) {
    uint32_t a;
    asm("{ .reg .u64 t; cvta.to.shared.u64 t, %1; cvt.u32.u64 %0, t; }" : "=r"(a) : "l"(p));
    return a;
}

// blocked SW128 atom layout for a [128 rows x 128 half cols] tile
__device__ __forceinline__ uint32_t tile_off_f16(int row, int col) {
    uint32_t boff = (uint32_t)((row >> 3) + (col >> 6) * 16) * 1024u
                  + (uint32_t)(row & 7) * 128u + (uint32_t)(col & 63) * 2u;
    return boff ^ ((boff >> 3) & 0x70);
}

// ---------------- sm_103a-only PTX wrappers ----------------
#if HAS_TCGEN05

#define TC_ALLOC(saddr, n) \
    asm volatile("tcgen05.alloc.cta_group::1.sync.aligned.shared::cta.b32 [%0], %1;" \
                 :: "r"((uint32_t)(saddr)), "r"((uint32_t)(n)) : "memory")
#define TC_DEALLOC(t, n) \
    asm volatile("tcgen05.dealloc.cta_group::1.sync.aligned.b32 %0, %1;" :: "r"(t), "r"((uint32_t)(n)))
#define TC_RELINQ() \
    asm volatile("tcgen05.relinquish_alloc_permit.cta_group::1.sync.aligned;")
#define TC_COMMIT(mbar) \
    asm volatile("tcgen05.commit.cta_group::1.mbarrier::arrive::one.shared::cluster.b64 [%0];" \
                 :: "r"((uint32_t)(mbar)) : "memory")
#define TC_FENCE_AFTER()  asm volatile("tcgen05.fence::after_thread_sync;" ::: "memory")
#define TC_FENCE_BEFORE() asm volatile("tcgen05.fence::before_thread_sync;" ::: "memory")
#define TC_WAIT_LD()      asm volatile("tcgen05.wait::ld.sync.aligned;" ::: "memory")

#define MBAR_INIT(mbar, cnt) \
    asm volatile("mbarrier.init.shared.b64 [%0], %1;" :: "r"((uint32_t)(mbar)), "r"((uint32_t)(cnt)) : "memory")
#define MBAR_WAIT(mbar, ph) do { \
    uint32_t _m = (uint32_t)(mbar); uint32_t _p = (uint32_t)(ph); uint32_t _d; \
    asm volatile("{\n\t.reg .pred p;\n\t" \
        "mbarrier.try_wait.parity.acquire.cta.shared::cta.b64 p, [%1], %2;\n\t" \
        "selp.b32 %0, 1, 0, p;\n\t}" : "=r"(_d) : "r"(_m), "r"(_p) : "memory"); \
    if (!_d) { \
        asm volatile("{\n\t.reg .pred P1;\n\t" \
            "WL_%=:\n\t" \
            "mbarrier.try_wait.parity.acquire.cta.shared::cta.b64 P1, [%0], %1, 0x989680;\n\t" \
            "@P1 bra.uni WD_%=;\n\t" \
            "bra.uni WL_%=;\n\t" \
            "WD_%=:\n\t}" :: "r"(_m), "r"(_p) : "memory"); \
    } \
} while (0)

#define LDTM_X32(r, t) \
    asm volatile("tcgen05.ld.sync.aligned.32x32b.x32.b32 " \
        "{%0, %1, %2, %3, %4, %5, %6, %7, %8, %9, %10, %11, %12, %13, %14, %15, " \
        " %16, %17, %18, %19, %20, %21, %22, %23, %24, %25, %26, %27, %28, %29, %30, %31}, [%32];" \
        : "=r"((r)[0]),  "=r"((r)[1]),  "=r"((r)[2]),  "=r"((r)[3]), \
          "=r"((r)[4]),  "=r"((r)[5]),  "=r"((r)[6]),  "=r"((r)[7]), \
          "=r"((r)[8]),  "=r"((r)[9]),  "=r"((r)[10]), "=r"((r)[11]), \
          "=r"((r)[12]), "=r"((r)[13]), "=r"((r)[14]), "=r"((r)[15]), \
          "=r"((r)[16]), "=r"((r)[17]), "=r"((r)[18]), "=r"((r)[19]), \
          "=r"((r)[20]), "=r"((r)[21]), "=r"((r)[22]), "=r"((r)[23]), \
          "=r"((r)[24]), "=r"((r)[25]), "=r"((r)[26]), "=r"((r)[27]), \
          "=r"((r)[28]), "=r"((r)[29]), "=r"((r)[30]), "=r"((r)[31]) \
        : "r"(t))

static constexpr uint64_t DESC_BASE_SW128 =
    (uint64_t(2) << 61) | (uint64_t(1) << 46) | (uint64_t(64) << 32) | (uint64_t(1) << 16);
__device__ __forceinline__ uint64_t make_desc(uint32_t addr) {
    return DESC_BASE_SW128 | ((uint64_t)(addr >> 4) & 0x3FFF);
}

// idesc kind::f16: dtype=F32(1<<4), atype=F16(0), btype=F16(0), N=128, M=128
static constexpr uint32_t IDESC_F16 =
    (1u << 4) | (16u << 17) | (8u << 24);

__device__ __forceinline__ void mma_f16_ss(uint32_t d, uint64_t a, uint64_t b,
                                           bool acc) {
    uint32_t en = acc ? 1u : 0u;
    asm volatile(
        "{\n\t.reg .pred p;\n\tsetp.ne.u32 p, %5, 0;\n\t"
        "tcgen05.mma.cta_group::1.kind::f16 [%0], %1, %2, %3, {%4, %4, %4, %4}, p;\n\t}"
        :: "r"(d), "l"(a), "l"(b), "r"(IDESC_F16), "r"(0u), "r"(en) : "memory");
}

#endif // HAS_TCGEN05

// ---------------- init: finals marking + constants (1 tiny block) ----------------
__global__ void init_kernel(const int* __restrict__ bnn) {
    if (threadIdx.x == 0) {
        g_rowptr[NN] = NE;          // total in-degree == edge count
        g_part[49] = 0; g_part[50] = 0; g_part[51] = 0;
        int run = 0;
        #pragma unroll 1
        for (int g = 0; g < NG; g++) {
            g_first[g] = run;
            g_z.flag3[run] = 1;
            g_z.need[run] = 1;
            run += bnn[g];
        }
    }
}

// ---------------- setup: degrees + W fp16-split prep + F2 marking ----------------
__global__ void __launch_bounds__(256) setup_kernel(
    const int* __restrict__ src, const int* __restrict__ dst,
    const float* __restrict__ Ws)
{
    int i = blockIdx.x * 256 + threadIdx.x;
    if (i < NE / 4) {
        int4 s4 = ((const int4*)src)[i];
        int4 d4 = ((const int4*)dst)[i];
        atomicAdd(&g_z.deg_out[s4.x], 1);
        atomicAdd(&g_z.deg_out[s4.y], 1);
        atomicAdd(&g_z.deg_out[s4.z], 1);
        atomicAdd(&g_z.deg_out[s4.w], 1);
        atomicAdd(&g_z.deg_in[d4.x], 1);
        atomicAdd(&g_z.deg_in[d4.y], 1);
        atomicAdd(&g_z.deg_in[d4.z], 1);
        atomicAdd(&g_z.deg_in[d4.w], 1);
        // F2 marking fused into the same edge pass (flag3 from init_kernel)
        #pragma unroll
        for (int q = 0; q < 4; q++) {
            int d = (q == 0) ? d4.x : (q == 1) ? d4.y : (q == 2) ? d4.z : d4.w;
            int s = (q == 0) ? s4.x : (q == 1) ? s4.y : (q == 2) ? s4.z : s4.w;
            if (g_z.flag3[d]) {
                if (atomicCAS(&g_z.map2[s], 0, -1) == 0) {
                    int idx = atomicAdd(&g_z.cnt[1], 1);
                    g_list2[idx] = s;
                    g_z.map2[s] = idx + 1;
                    g_z.need[s] = 1;
                }
            }
        }
    }
    if (i < ORDER * RK * RK) {
        int layer = i >> 14;
        int rem = i & 16383;
        int k = rem >> 7;
        int n = rem & 127;
        float w = Ws[layer * RK * RK + k * RK + n];
        __half whi = __float2half_rn(w);
        __half wlo = __float2half_rn(w - __half2float(whi));
        uint32_t off2 = tile_off_f16(n, k) >> 1;
        g_Bhi[layer][off2] = whi;
        g_Blo[layer][off2] = wlo;
    }
}

// F1 = unique srcs of edges into F2; blocks < 49 also do the per-1024-chunk
// deg_in reduction (deg_in is complete after setup)
__global__ void __launch_bounds__(256) pass_f1_kernel(
    const int* __restrict__ src, const int* __restrict__ dst)
{
    const int b = blockIdx.x;
    const int tid = threadIdx.x;

    if (b < SCAN_NB) {
        const int4* di4 = (const int4*)g_z.deg_in;
        int4 v = di4[b * 256 + tid];
        int s = v.x + v.y + v.z + v.w;
        #pragma unroll
        for (int o = 16; o > 0; o >>= 1) s += __shfl_xor_sync(0xFFFFFFFFu, s, o);
        __shared__ int ws[8];
        if ((tid & 31) == 0) ws[tid >> 5] = s;
        __syncthreads();
        if (tid < 8) {
            int t = ws[tid];
            #pragma unroll
            for (int o = 4; o > 0; o >>= 1) t += __shfl_xor_sync(0xFFu, t, o);
            if (tid == 0) g_part[b] = t;
        }
    }

    int i = b * 256 + tid;
    if (i >= NE / 4) return;
    int4 s4 = ((const int4*)src)[i];
    int4 d4 = ((const int4*)dst)[i];
    #pragma unroll
    for (int q = 0; q < 4; q++) {
        int d = (q == 0) ? d4.x : (q == 1) ? d4.y : (q == 2) ? d4.z : d4.w;
        int s = (q == 0) ? s4.x : (q == 1) ? s4.y : (q == 2) ? s4.z : s4.w;
        if (g_z.map2[d] != 0) {
            if (atomicCAS(&g_z.map1[s], 0, -1) == 0) {
                int idx = atomicAdd(&g_z.cnt[0], 1);
                g_list1[idx] = s;
                g_z.map1[s] = idx + 1;
                g_z.need[s] = 1;
            }
        }
    }
}

// fused partial-scan + per-chunk scan (warp-shuffle) + rowptr/cursor/inv
__global__ void __launch_bounds__(256) block_scan_kernel() {
    const int b = blockIdx.x;
    const int tid = threadIdx.x;
    const int lane = tid & 31;
    const int wrp = tid >> 5;
    const int base = b * SCAN_CH + tid * 4;

    __shared__ int s_off;
    __shared__ int wsum[8];

    if (tid < 32) {
        int4 p = (tid < 13) ? ((const int4*)g_part)[tid] : make_int4(0, 0, 0, 0);
        int i0 = tid * 4;
        int off = ((i0 + 0) < b ? p.x : 0) + ((i0 + 1) < b ? p.y : 0)
                + ((i0 + 2) < b ? p.z : 0) + ((i0 + 3) < b ? p.w : 0);
        #pragma unroll
        for (int o = 16; o > 0; o >>= 1)
            off += __shfl_xor_sync(0xFFFFFFFFu, off, o);
        if (tid == 0) s_off = off;
    }

    const int4* di4 = (const int4*)g_z.deg_in;
    int4 v = di4[b * 256 + tid];
    int tsum = v.x + v.y + v.z + v.w;

    // per-warp inclusive scan via shfl_up
    int incl = tsum;
    #pragma unroll
    for (int o = 1; o < 32; o <<= 1) {
        int t = __shfl_up_sync(0xFFFFFFFFu, incl, o);
        if (lane >= o) incl += t;
    }
    if (lane == 31) wsum[wrp] = incl;
    __syncthreads();
    int woff = 0;
    #pragma unroll
    for (int j = 0; j < 8; j++) woff += (j < wrp) ? wsum[j] : 0;
    int run = s_off + woff + incl - tsum;   // exclusive prefix for this thread

    int r0 = run;
    int r1 = r0 + v.x;
    int r2 = r1 + v.y;
    int r3 = r2 + v.z;

    if (base + 0 < NN) { g_rowptr[base+0] = r0; g_cursor[base+0] = r0; }
    if (base + 1 < NN) { g_rowptr[base+1] = r1; g_cursor[base+1] = r1; }
    if (base + 2 < NN) { g_rowptr[base+2] = r2; g_cursor[base+2] = r2; }
    if (base + 3 < NN) { g_rowptr[base+3] = r3; g_cursor[base+3] = r3; }

    #pragma unroll
    for (int j = 0; j < 4; j++) {
        int idx = base + j;
        if (idx < NN) {
            int din = (j == 0) ? v.x : (j == 1) ? v.y : (j == 2) ? v.z : v.w;
            g_inv_in[idx]  = rsqrtf(fmaxf((float)din, 1.0f));
            g_inv_out[idx] = rsqrtf(fmaxf((float)g_z.deg_out[idx], 1.0f));
        }
    }
}

// filtered CSR scatter: only edges whose dst needs its in-edge list
__global__ void __launch_bounds__(256) scatter_kernel(
    const int* __restrict__ src, const int* __restrict__ dst)
{
    int i = blockIdx.x * 256 + threadIdx.x;
    if (i >= NE / 4) return;
    int4 s4 = ((const int4*)src)[i];
    int4 d4 = ((const int4*)dst)[i];
    #pragma unroll
    for (int q = 0; q < 4; q++) {
        int d = (q == 0) ? d4.x : (q == 1) ? d4.y : (q == 2) ? d4.z : d4.w;
        int s = (q == 0) ? s4.x : (q == 1) ? s4.y : (q == 2) ? s4.z : s4.w;
        if (g_z.need[d]) {
            int p = atomicAdd(&g_cursor[d], 1);
            g_col[p] = s;
        }
    }
}

// ---------------- tcgen05 GEMM (fp16 hi/lo 3-pass), fp16 H output ----------------
#define SM_META 0
#define SM_MBAR 8
#define SM_XHI  1024
#define SM_XLO  (SM_XHI + 32768)
#define SM_BHI  (SM_XLO + 32768)
#define SM_BLO  (SM_BHI + 32768)
#define SM_TOTAL (SM_BLO + 32768)   // 132 KB
#define TMEM_COLS 128
#define GRID_M ((NN + 127) / 128)

__global__ void __launch_bounds__(128, 1) gemm_tc_kernel(
    const float* __restrict__ X,
    const __half* __restrict__ Bhi, const __half* __restrict__ Blo,
    uint2* __restrict__ H,
    const int* __restrict__ nodelist, const int* __restrict__ cntp)
{
#if HAS_TCGEN05
    const int n = cntp ? *cntp : NN;
    const int row0 = blockIdx.x * 128;
    if (row0 >= n) return;

    extern __shared__ char smem[];
    const uint32_t sbase = smem_u32(smem);
    const int tid = threadIdx.x;
    const int wid = tid >> 5;
    const int lane = tid & 31;

    if (wid == 0) TC_ALLOC(sbase + SM_META, TMEM_COLS);
    if (tid == 0) MBAR_INIT(sbase + SM_MBAR, 1);

    {
        const uint4* bh = (const uint4*)Bhi;
        const uint4* bl = (const uint4*)Blo;
        uint4* dh = (uint4*)(smem + SM_BHI);
        uint4* dl = (uint4*)(smem + SM_BLO);
        #pragma unroll
        for (int i = 0; i < 16; i++) {
            dh[tid + i * 128] = bh[tid + i * 128];
            dl[tid + i * 128] = bl[tid + i * 128];
        }
    }

    const float4* X4 = (const float4*)X;
    #pragma unroll
    for (int i = 0; i < 32; i++) {
        int idx = tid + i * 128;
        int r = idx >> 5, c4 = idx & 31;
        float4 v = make_float4(0.f, 0.f, 0.f, 0.f);
        if (row0 + r < n) v = X4[(row0 + r) * 32 + c4];
        __half2 h01 = __float22half2_rn(make_float2(v.x, v.y));
        __half2 h23 = __float22half2_rn(make_float2(v.z, v.w));
        float2 b01 = __half22float2(h01);
        float2 b23 = __half22float2(h23);
        __half2 l01 = __float22half2_rn(make_float2(v.x - b01.x, v.y - b01.y));
        __half2 l23 = __float22half2_rn(make_float2(v.z - b23.x, v.w - b23.y));
        uint2 uhi, ulo;
        uhi.x = *reinterpret_cast<uint32_t*>(&h01);
        uhi.y = *reinterpret_cast<uint32_t*>(&h23);
        ulo.x = *reinterpret_cast<uint32_t*>(&l01);
        ulo.y = *reinterpret_cast<uint32_t*>(&l23);
        uint32_t off = tile_off_f16(r, c4 * 4);
        *(uint2*)(smem + SM_XHI + off) = uhi;
        *(uint2*)(smem + SM_XLO + off) = ulo;
    }

    __syncthreads();
    uint32_t tmem;
    asm volatile("ld.shared.b32 %0, [%1];" : "=r"(tmem) : "r"(sbase + SM_META));

    if (tid == 0) {
        TC_FENCE_AFTER();
        const uint64_t a_hi = make_desc(sbase + SM_XHI);
        const uint64_t a_lo = make_desc(sbase + SM_XLO);
        const uint64_t b_hi = make_desc(sbase + SM_BHI);
        const uint64_t b_lo = make_desc(sbase + SM_BLO);
        #pragma unroll
        for (int p = 0; p < 3; p++) {
            uint64_t ab = (p == 1) ? a_lo : a_hi;
            uint64_t bb = (p == 2) ? b_lo : b_hi;
            #pragma unroll
            for (int s = 0; s < 8; s++) {
                uint64_t off = (uint64_t)((s >> 2) * 1024 + (s & 3) * 2);
                mma_f16_ss(tmem, ab + off, bb + off, !(p == 0 && s == 0));
            }
        }
        TC_COMMIT(sbase + SM_MBAR);
    }
    MBAR_WAIT(sbase + SM_MBAR, 0);
    TC_FENCE_AFTER();

    int row = row0 + wid * 32 + lane;
    float s = 0.f;
    if (row < n) {
        int node = nodelist ? nodelist[row] : row;
        s = g_inv_out[node];
    }
    #pragma unroll
    for (int base = 0; base < 128; base += 32) {
        uint32_t r[32];
        LDTM_X32(r, tmem + base);
        TC_WAIT_LD();
        if (row < n) {
            #pragma unroll
            for (int j = 0; j < 8; j++) {
                float2 p0 = make_float2(__uint_as_float(r[j*4+0]) * s,
                                        __uint_as_float(r[j*4+1]) * s);
                float2 p1 = make_float2(__uint_as_float(r[j*4+2]) * s,
                                        __uint_as_float(r[j*4+3]) * s);
                __half2 h0 = __float22half2_rn(p0);
                __half2 h1 = __float22half2_rn(p1);
                uint2 u;
                u.x = *reinterpret_cast<uint32_t*>(&h0);
                u.y = *reinterpret_cast<uint32_t*>(&h1);
                H[row * 32 + (base >> 2) + j] = u;
            }
        }
    }

    TC_FENCE_BEFORE();
    __syncthreads();
    if (wid == 0) {
        TC_RELINQ();
        TC_DEALLOC(tmem, TMEM_COLS);
    }
#else
    (void)X; (void)Bhi; (void)Blo; (void)H; (void)nodelist; (void)cntp;
#endif
}

// ---------------- SpMM(fp16 in, fp32 accum) + inv_in + bias + LN + ReLU ----------------
// MODE 0: dst=list1[w], w<cnt[0], H indexed by raw src, out row w
// MODE 1: dst=list2[w], w<cnt[1], H indexed by map1[src]-1, out row w
// MODE 2: dst=first[w], w<NG,     H indexed by map2[src]-1, out row w (d_out)
template<int MODE>
__global__ void __launch_bounds__(256) spmm_ln_t(
    const uint2* __restrict__ H,
    const float* __restrict__ b, const float* __restrict__ gamma,
    const float* __restrict__ beta, float4* __restrict__ out)
{
    int w = (blockIdx.x * blockDim.x + threadIdx.x) >> 5;
    int lane = threadIdx.x & 31;

    int n_dst = (MODE == 0) ? g_z.cnt[0] : (MODE == 1) ? g_z.cnt[1] : NG;
    if (w >= n_dst) return;
    int dst = (MODE == 0) ? g_list1[w] : (MODE == 1) ? g_list2[w] : g_first[w];

    int beg = g_rowptr[dst];
    int end = g_rowptr[dst + 1];

    float4 acc = make_float4(0.f, 0.f, 0.f, 0.f);
    int e = beg;
    for (; e + 3 < end; e += 4) {
        int s0 = g_col[e], s1 = g_col[e+1], s2 = g_col[e+2], s3 = g_col[e+3];
        if (MODE == 1) { s0 = g_z.map1[s0]-1; s1 = g_z.map1[s1]-1; s2 = g_z.map1[s2]-1; s3 = g_z.map1[s3]-1; }
        if (MODE == 2) { s0 = g_z.map2[s0]-1; s1 = g_z.map2[s1]-1; s2 = g_z.map2[s2]-1; s3 = g_z.map2[s3]-1; }
        uint2 v0 = H[s0 * 32 + lane];
        uint2 v1 = H[s1 * 32 + lane];
        uint2 v2 = H[s2 * 32 + lane];
        uint2 v3 = H[s3 * 32 + lane];
        #pragma unroll
        for (int q = 0; q < 4; q++) {
            uint2 v = (q == 0) ? v0 : (q == 1) ? v1 : (q == 2) ? v2 : v3;
            float2 a0 = __half22float2(*reinterpret_cast<__half2*>(&v.x));
            float2 a1 = __half22float2(*reinterpret_cast<__half2*>(&v.y));
            acc.x += a0.x; acc.y += a0.y; acc.z += a1.x; acc.w += a1.y;
        }
    }
    for (; e < end; e++) {
        int s0 = g_col[e];
        if (MODE == 1) s0 = g_z.map1[s0] - 1;
        if (MODE == 2) s0 = g_z.map2[s0] - 1;
        uint2 v = H[s0 * 32 + lane];
        float2 a0 = __half22float2(*reinterpret_cast<__half2*>(&v.x));
        float2 a1 = __half22float2(*reinterpret_cast<__half2*>(&v.y));
        acc.x += a0.x; acc.y += a0.y; acc.z += a1.x; acc.w += a1.y;
    }

    float sc = g_inv_in[dst];
    float4 bb = ((const float4*)b)[lane];
    float x0 = acc.x * sc + bb.x;
    float x1 = acc.y * sc + bb.y;
    float x2 = acc.z * sc + bb.z;
    float x3 = acc.w * sc + bb.w;

    float s = x0 + x1 + x2 + x3;
    #pragma unroll
    for (int o = 16; o > 0; o >>= 1) s += __shfl_xor_sync(0xFFFFFFFFu, s, o);
    float mu = s * (1.0f / RK);

    float d0 = x0 - mu, d1 = x1 - mu, d2 = x2 - mu, d3 = x3 - mu;
    float v = d0*d0 + d1*d1 + d2*d2 + d3*d3;
    #pragma unroll
    for (int o = 16; o > 0; o >>= 1) v += __shfl_xor_sync(0xFFFFFFFFu, v, o);
    float rstd = rsqrtf(v * (1.0f / RK) + LN_EPS);

    float4 gg = ((const float4*)gamma)[lane];
    float4 be = ((const float4*)beta)[lane];
    float y0 = fmaxf(d0 * rstd * gg.x + be.x, 0.f);
    float y1 = fmaxf(d1 * rstd * gg.y + be.y, 0.f);
    float y2 = fmaxf(d2 * rstd * gg.z + be.z, 0.f);
    float y3 = fmaxf(d3 * rstd * gg.w + be.w, 0.f);

    out[w * 32 + lane] = make_float4(y0, y1, y2, y3);
}

// ---------------- launch ----------------
extern "C" void kernel_launch(void* const* d_in, const int* in_sizes, int n_in,
                              void* d_out, int out_size)
{
    const float* features = (const float*)d_in[0];
    const int*   src      = (const int*)d_in[1];
    const int*   dst      = (const int*)d_in[2];
    const int*   bnn      = (const int*)d_in[3];
    const float* Ws       = (const float*)d_in[4];
    const float* bs       = (const float*)d_in[5];
    const float* gammas   = (const float*)d_in[6];
    const float* betas    = (const float*)d_in[7];
    float* out = (float*)d_out;

    cudaFuncSetAttribute(gemm_tc_kernel,
                         cudaFuncAttributeMaxDynamicSharedMemorySize, SM_TOTAL);

    uint2* hbuf;
    float *bufA, *bufB;
    __half *bhi, *blo;
    char *zb;
    int *list1_p, *list2_p;
    cudaGetSymbolAddress((void**)&hbuf, g_h16);
    cudaGetSymbolAddress((void**)&bufA, g_bufA);
    cudaGetSymbolAddress((void**)&bufB, g_bufB);
    cudaGetSymbolAddress((void**)&bhi, g_Bhi);
    cudaGetSymbolAddress((void**)&blo, g_Blo);
    cudaGetSymbolAddress((void**)&zb, g_z);
    cudaGetSymbolAddress((void**)&list1_p, g_list1);
    cudaGetSymbolAddress((void**)&list2_p, g_list2);
    int* cnt_p = (int*)(zb + offsetof(ZBlk, cnt));

    // ONE memset covers all per-launch state
    cudaMemsetAsync(zb, 0, sizeof(ZBlk));

    const int e4_grid = (NE / 4 + 255) / 256;   // 625

    init_kernel<<<1, 64>>>(bnn);
    setup_kernel<<<e4_grid, 256>>>(src, dst, Ws);   // deg + W prep + F2 mark
    pass_f1_kernel<<<e4_grid, 256>>>(src, dst);     // F1 mark + chunk reduce
    block_scan_kernel<<<SCAN_NB, 256>>>();
    scatter_kernel<<<e4_grid, 256>>>(src, dst);

    const int spmm_grid_full = (NN * 32 + 255) / 256;   // early-exit on cnt
    const int spmm_grid_out  = (NG * 32 + 255) / 256;

    // layer 0: full GEMM over all nodes, SpMM over F1 -> compact X1 (bufA)
    gemm_tc_kernel<<<GRID_M, 128, SM_TOTAL>>>(features, bhi, blo, hbuf,
                                              nullptr, nullptr);
    spmm_ln_t<0><<<spmm_grid_full, 256>>>(hbuf, bs, gammas, betas,
                                          (float4*)bufA);
    // layer 1: compact GEMM over F1 rows, SpMM over F2 -> compact X2 (bufB)
    gemm_tc_kernel<<<GRID_M, 128, SM_TOTAL>>>(bufA, bhi + RK * RK,
                                              blo + RK * RK, hbuf,
                                              list1_p, cnt_p + 0);
    spmm_ln_t<1><<<spmm_grid_full, 256>>>(hbuf, bs + RK, gammas + RK,
                                          betas + RK, (float4*)bufB);
    // layer 2: compact GEMM over F2 rows, SpMM over the 50 finals -> d_out
    gemm_tc_kernel<<<GRID_M, 128, SM_TOTAL>>>(bufB, bhi + 2 * RK * RK,
                                              blo + 2 * RK * RK, hbuf,
                                              list2_p, cnt_p + 1);
    spmm_ln_t<2><<<spmm_grid_out, 256>>>(hbuf, bs + 2 * RK, gammas + 2 * RK,
                                         betas + 2 * RK, (float4*)out);
}